// round 1
// baseline (speedup 1.0000x reference)
#include <cuda_runtime.h>
#include <cstdint>

// ---------------------------------------------------------------------------
// WaveConv2d: 4-level db4 DWT (symmetric pad) -> per-pixel channel mixing of
// level-4 subbands -> 4-level inverse DWT (levels 1..3 highs pass through).
//
// Shapes:
//   x  : (16, 64, 256, 256) fp32
//   w1..w4 : (64, 64, 22, 22) fp32   (i, o, x, y)
//   out: (16, 64, 256, 256) fp32
//
// Level sizes (out = (N+7)//2): 256->131->69->38->22
// Symmetric pad left = 6 at every level (p = 12,13,13,12).
// Inverse sizes (2n-6, cropped): 22->38, 38->70(->69), 69->132(->131), 131->256
// ---------------------------------------------------------------------------

#define Bv 16
#define Cv 64
#define BCv (Bv*Cv)   // 1024

// decomposition filters (db4). Analysis uses reversed filters under
// cross-correlation: lo[o] = sum_t xp[2o+t]*DLO[7-t].
__constant__ float DLO[8] = {
  -0.010597401784997278f,  0.032883011666982945f,  0.030841381835986965f,
  -0.18703481171888114f,  -0.02798376941698385f,   0.6308807679295904f,
   0.7148465705525415f,    0.23037781330885523f };
__constant__ float DHI[8] = {
  -0.23037781330885523f,   0.7148465705525415f,   -0.6308807679295904f,
  -0.02798376941698385f,   0.18703481171888114f,   0.030841381835986965f,
  -0.032883011666982945f, -0.010597401784997278f };

// ---- scratch (device globals; no allocations allowed) ----
__device__ float g_l1[(size_t)BCv*4*131*131];  // 281 MB
__device__ float g_l2[(size_t)BCv*4*69*69];
__device__ float g_l3[(size_t)BCv*4*38*38];
__device__ float g_l4[(size_t)BCv*4*22*22];
__device__ float g_mod[(size_t)BCv*4*22*22];
__device__ float g_r4[(size_t)BCv*38*38];
__device__ float g_r3[(size_t)BCv*69*69];
__device__ float g_r2[(size_t)BCv*131*131];

__device__ __forceinline__ int refl(int j, int N) {
  if (j < 0)  j = -1 - j;
  if (j >= N) j = 2*N - 1 - j;
  if (j < 0)  j = 0;
  if (j >= N) j = N - 1;
  return j;
}

// ---------------------------------------------------------------------------
// Fused 2-D analysis: one level of DWT. in: (BC, H, W) with plane stride inPS.
// out: (BC, 4, OH, OW). Subband order: 0=LL, 1=(Wlo,Hhi), 2=(Whi,Hlo), 3=HH.
// ---------------------------------------------------------------------------
template<int TOY, int TOX>
__global__ void afb2d_kernel(const float* __restrict__ in, size_t inPS,
                             float* __restrict__ out,
                             int H, int W, int OH, int OW, int plH, int plW) {
  constexpr int RI = 2*TOY + 6;
  constexpr int CI = 2*TOX + 6;
  __shared__ float s_in[RI][CI];
  __shared__ float s_lo[RI][TOX];
  __shared__ float s_hi[RI][TOX];

  const int bc  = blockIdx.z;
  const int ty0 = blockIdx.y * TOY;
  const int tx0 = blockIdx.x * TOX;
  const float* src = in + (size_t)bc * inPS;

  // stage 0: load padded input tile (symmetric boundary)
  for (int idx = threadIdx.x; idx < RI*CI; idx += blockDim.x) {
    int r = idx / CI, c = idx - r*CI;
    int sr = refl(2*ty0 + r - plH, H);
    int sc = refl(2*tx0 + c - plW, W);
    s_in[r][c] = src[(size_t)sr * W + sc];
  }
  __syncthreads();

  // stage 1: row pass (filter along W)
  for (int idx = threadIdx.x; idx < RI*TOX; idx += blockDim.x) {
    int r = idx / TOX, ox = idx - r*TOX;
    float lo = 0.f, hi = 0.f;
#pragma unroll
    for (int t = 0; t < 8; t++) {
      float v = s_in[r][2*ox + t];
      lo += v * DLO[7 - t];
      hi += v * DHI[7 - t];
    }
    s_lo[r][ox] = lo;
    s_hi[r][ox] = hi;
  }
  __syncthreads();

  // stage 2: column pass (filter along H), emit 4 subbands
  const size_t plane = (size_t)OH * OW;
  const size_t obase = (size_t)bc * 4 * plane;
  for (int idx = threadIdx.x; idx < TOY*TOX; idx += blockDim.x) {
    int oyl = idx / TOX, ox = idx - oyl*TOX;
    int oy = ty0 + oyl, gx = tx0 + ox;
    if (oy >= OH || gx >= OW) continue;
    float ll=0.f, lh=0.f, hl=0.f, hh=0.f;
#pragma unroll
    for (int t = 0; t < 8; t++) {
      float a = s_lo[2*oyl + t][ox];
      float b = s_hi[2*oyl + t][ox];
      float kl = DLO[7 - t], kh = DHI[7 - t];
      ll += a*kl;  lh += a*kh;  hl += b*kl;  hh += b*kh;
    }
    size_t o = (size_t)oy * OW + gx;
    out[obase             + o] = ll;  // LL
    out[obase +   plane   + o] = lh;  // Wlo,Hhi
    out[obase + 2*plane   + o] = hl;  // Whi,Hlo
    out[obase + 3*plane   + o] = hh;  // HH
  }
}

// ---------------------------------------------------------------------------
// Fused 2-D synthesis: one inverse level.
// ll: (BC, >=h, >=w) with plane stride llPS and row stride llRS (crop folded in)
// hb: (BC, 4, h, w) -> uses subbands 1,2,3
// out: (BC, TH, TW) with plane stride oPS; TH <= 2h-6, TW <= 2w-6.
// Synthesis identity: y[j] = sum_{t: (j+t) odd} k[t] * x[(j+t-1)/2]
// ---------------------------------------------------------------------------
template<int TOY, int TOX>
__global__ void sfb2d_kernel(const float* __restrict__ ll, size_t llPS, int llRS,
                             const float* __restrict__ hb, size_t hPS,
                             int h, int w,
                             float* __restrict__ out, size_t oPS,
                             int TH, int TW) {
  constexpr int NI = TOX/2 + 3;
  __shared__ float s_lo[TOY][NI + 1];
  __shared__ float s_hi[TOY][NI + 1];

  const int bc  = blockIdx.z;
  const int jy0 = blockIdx.y * TOY;
  const int jx0 = blockIdx.x * TOX;   // even (TOX even)
  const int i0  = jx0 >> 1;

  const size_t sp = (size_t)h * w;
  const float* pll = ll + (size_t)bc * llPS;
  const float* ph0 = hb + (size_t)bc * hPS +     sp;
  const float* ph1 = hb + (size_t)bc * hPS + 2 * sp;
  const float* ph2 = hb + (size_t)bc * hPS + 3 * sp;

  // stage 1: column synthesis -> lo_row / hi_row
  for (int idx = threadIdx.x; idx < TOY*NI; idx += blockDim.x) {
    int jyl = idx / NI, il = idx - jyl*NI;
    int jy = jy0 + jyl, i = i0 + il;
    float lo = 0.f, hi = 0.f;
    if (jy < TH && i < w) {
      int base = jy >> 1;
      int u0 = (jy & 1) ? 0 : 1;
#pragma unroll
      for (int m = 0; m < 4; m++) {
        int u = u0 + 2*m;
        int ky = base + m;
        float fl = DLO[u], fh = DHI[u];
        lo += fl * pll[(size_t)ky * llRS + i] + fh * ph0[(size_t)ky * w + i];
        hi += fl * ph1[(size_t)ky * w + i]   + fh * ph2[(size_t)ky * w + i];
      }
    }
    s_lo[jyl][il] = lo;
    s_hi[jyl][il] = hi;
  }
  __syncthreads();

  // stage 2: row synthesis -> output
  float* po = out + (size_t)bc * oPS;
  for (int idx = threadIdx.x; idx < TOY*TOX; idx += blockDim.x) {
    int jyl = idx / TOX, jxl = idx - jyl*TOX;
    int jy = jy0 + jyl, jx = jx0 + jxl;
    if (jy >= TH || jx >= TW) continue;
    int t0 = (jx & 1) ? 0 : 1;
    int ib = (jx >> 1) - i0;
    float acc = 0.f;
#pragma unroll
    for (int m = 0; m < 4; m++) {
      int t = t0 + 2*m;
      acc += DLO[t] * s_lo[jyl][ib + m] + DHI[t] * s_hi[jyl][ib + m];
    }
    po[(size_t)jy * TW + jx] = acc;
  }
}

// ---------------------------------------------------------------------------
// Per-pixel channel mixing at level 4:
// out[b,o,s,xy] = sum_i in[b,i,s,xy] * W_s[i,o,xy]   (s=0..3 -> w1..w4)
// ---------------------------------------------------------------------------
__global__ void mul2d_kernel(const float* __restrict__ in,
                             const float* __restrict__ w1,
                             const float* __restrict__ w2,
                             const float* __restrict__ w3,
                             const float* __restrict__ w4,
                             float* __restrict__ outb) {
  const int s  = blockIdx.y;      // 0..3
  const int xy = blockIdx.x;      // 0..483
  const float* W = (s == 0) ? w1 : (s == 1) ? w2 : (s == 2) ? w3 : w4;

  __shared__ float sa[Bv][Cv];
  const int t = threadIdx.x;      // 256
  for (int idx = t; idx < Bv*Cv; idx += 256) {
    int b = idx >> 6, i = idx & 63;
    sa[b][i] = in[(((size_t)b * Cv + i) * 4 + s) * 484 + xy];
  }
  __syncthreads();

  const int o  = t & 63;
  const int bq = t >> 6;          // 0..3
  float a0=0.f, a1=0.f, a2=0.f, a3=0.f;
  for (int i = 0; i < Cv; i++) {
    float wv = W[((size_t)i * Cv + o) * 484 + xy];
    a0 += sa[bq     ][i] * wv;
    a1 += sa[bq +  4][i] * wv;
    a2 += sa[bq +  8][i] * wv;
    a3 += sa[bq + 12][i] * wv;
  }
  outb[(((size_t)(bq     ) * Cv + o) * 4 + s) * 484 + xy] = a0;
  outb[(((size_t)(bq +  4) * Cv + o) * 4 + s) * 484 + xy] = a1;
  outb[(((size_t)(bq +  8) * Cv + o) * 4 + s) * 484 + xy] = a2;
  outb[(((size_t)(bq + 12) * Cv + o) * 4 + s) * 484 + xy] = a3;
}

// ---------------------------------------------------------------------------
extern "C" void kernel_launch(void* const* d_in, const int* in_sizes, int n_in,
                              void* d_out, int out_size) {
  const float* x  = (const float*)d_in[0];
  const float* w1 = (const float*)d_in[1];
  const float* w2 = (const float*)d_in[2];
  const float* w3 = (const float*)d_in[3];
  const float* w4 = (const float*)d_in[4];
  float* out = (float*)d_out;

  float *l1, *l2, *l3, *l4, *md, *r4, *r3, *r2;
  cudaGetSymbolAddress((void**)&l1, g_l1);
  cudaGetSymbolAddress((void**)&l2, g_l2);
  cudaGetSymbolAddress((void**)&l3, g_l3);
  cudaGetSymbolAddress((void**)&l4, g_l4);
  cudaGetSymbolAddress((void**)&md, g_mod);
  cudaGetSymbolAddress((void**)&r4, g_r4);
  cudaGetSymbolAddress((void**)&r3, g_r3);
  cudaGetSymbolAddress((void**)&r2, g_r2);

  constexpr int TOY = 16, TOX = 32;   // analysis tile
  constexpr int SOY = 16, SOX = 64;   // synthesis tile

  auto agrid = [](int OH, int OW) {
    return dim3((OW + TOX - 1) / TOX, (OH + TOY - 1) / TOY, BCv);
  };
  auto sgrid = [](int TH, int TW) {
    return dim3((TW + SOX - 1) / SOX, (TH + SOY - 1) / SOY, BCv);
  };

  // ---- forward DWT ----
  afb2d_kernel<TOY,TOX><<<agrid(131,131), 256>>>(x,  (size_t)256*256,   l1, 256, 256, 131, 131, 6, 6);
  afb2d_kernel<TOY,TOX><<<agrid( 69, 69), 256>>>(l1, (size_t)4*131*131, l2, 131, 131,  69,  69, 6, 6);
  afb2d_kernel<TOY,TOX><<<agrid( 38, 38), 256>>>(l2, (size_t)4*69*69,   l3,  69,  69,  38,  38, 6, 6);
  afb2d_kernel<TOY,TOX><<<agrid( 22, 22), 256>>>(l3, (size_t)4*38*38,   l4,  38,  38,  22,  22, 6, 6);

  // ---- level-4 channel mixing ----
  mul2d_kernel<<<dim3(484, 4), 256>>>(l4, w1, w2, w3, w4, md);

  // ---- inverse DWT ----
  sfb2d_kernel<SOY,SOX><<<sgrid( 38,  38), 256>>>(md, (size_t)4*22*22,  22, md, (size_t)4*22*22,   22,  22, r4,  (size_t)38*38,    38,  38);
  sfb2d_kernel<SOY,SOX><<<sgrid( 69,  69), 256>>>(r4, (size_t)38*38,    38, l3, (size_t)4*38*38,   38,  38, r3,  (size_t)69*69,    69,  69);
  sfb2d_kernel<SOY,SOX><<<sgrid(131, 131), 256>>>(r3, (size_t)69*69,    69, l2, (size_t)4*69*69,   69,  69, r2,  (size_t)131*131, 131, 131);
  sfb2d_kernel<SOY,SOX><<<sgrid(256, 256), 256>>>(r2, (size_t)131*131, 131, l1, (size_t)4*131*131, 131, 131, out, (size_t)256*256, 256, 256);
}

// round 2
// speedup vs baseline: 1.5065x; 1.5065x over previous
#include <cuda_runtime.h>
#include <cstdint>

// ---------------------------------------------------------------------------
// WaveConv2d via perfect-reconstruction shortcut:
//   out = x + IDWT(delta), delta nonzero only at level 4:
//   delta_s = mul2d(orig_l4, w_s) - orig_l4   (s = LL,LH,HL,HH -> w1..w4)
// Forward: LL-chain only (256->131->69->38), then full afb to level-4 (22).
// Inverse: full sfb at level 4 (22->38), then lo-only sfb (38->69->131->256),
// final level fused with +x.
// ---------------------------------------------------------------------------

#define Bv 16
#define Cv 64
#define BCv (Bv*Cv)   // 1024

__constant__ float DLO[8] = {
  -0.010597401784997278f,  0.032883011666982945f,  0.030841381835986965f,
  -0.18703481171888114f,  -0.02798376941698385f,   0.6308807679295904f,
   0.7148465705525415f,    0.23037781330885523f };
__constant__ float DHI[8] = {
  -0.23037781330885523f,   0.7148465705525415f,   -0.6308807679295904f,
  -0.02798376941698385f,   0.18703481171888114f,   0.030841381835986965f,
  -0.032883011666982945f, -0.010597401784997278f };

// ---- scratch (device globals) ----
__device__ float g_ll1[(size_t)BCv*131*131];   // 70 MB
__device__ float g_ll2[(size_t)BCv*69*69];
__device__ float g_ll3[(size_t)BCv*38*38];
__device__ float g_l4 [(size_t)BCv*4*22*22];
__device__ float g_d4 [(size_t)BCv*4*22*22];
__device__ float g_r4 [(size_t)BCv*38*38];
__device__ float g_r3 [(size_t)BCv*69*69];
__device__ float g_r2 [(size_t)BCv*131*131];

__device__ __forceinline__ int refl(int j, int N) {
  if (j < 0)  j = -1 - j;
  if (j >= N) j = 2*N - 1 - j;
  if (j < 0)  j = 0;
  if (j >= N) j = N - 1;
  return j;
}

// ---------------------------------------------------------------------------
// LL-only analysis level. in: (BC,H,W) stride inPS -> out: (BC,OH,OW).
// Block (32,8).
// ---------------------------------------------------------------------------
template<int TOY, int TOX>
__global__ void afb2d_ll_kernel(const float* __restrict__ in, size_t inPS,
                                float* __restrict__ out,
                                int H, int W, int OH, int OW) {
  constexpr int RI = 2*TOY + 6;
  constexpr int CI = 2*TOX + 6;
  __shared__ float s_in[RI][CI];
  __shared__ float s_lo[RI][TOX];

  const int bc  = blockIdx.z;
  const int ty0 = blockIdx.y * TOY;
  const int tx0 = blockIdx.x * TOX;
  const int tx = threadIdx.x, ty = threadIdx.y;
  const float* src = in + (size_t)bc * inPS;

  for (int r = ty; r < RI; r += 8) {
    int sr = refl(2*ty0 + r - 6, H);
    const float* row = src + (size_t)sr * W;
    for (int c = tx; c < CI; c += 32)
      s_in[r][c] = row[refl(2*tx0 + c - 6, W)];
  }
  __syncthreads();

  for (int r = ty; r < RI; r += 8) {
    for (int ox = tx; ox < TOX; ox += 32) {
      float lo = 0.f;
#pragma unroll
      for (int t = 0; t < 8; t++) lo += s_in[r][2*ox + t] * DLO[7 - t];
      s_lo[r][ox] = lo;
    }
  }
  __syncthreads();

  float* dst = out + (size_t)bc * OH * OW;
  for (int oyl = ty; oyl < TOY; oyl += 8) {
    int oy = ty0 + oyl;
    if (oy >= OH) continue;
    for (int ox = tx; ox < TOX; ox += 32) {
      int gx = tx0 + ox;
      if (gx >= OW) continue;
      float ll = 0.f;
#pragma unroll
      for (int t = 0; t < 8; t++) ll += s_lo[2*oyl + t][ox] * DLO[7 - t];
      dst[(size_t)oy * OW + gx] = ll;
    }
  }
}

// ---------------------------------------------------------------------------
// Full 4-subband analysis (level 4 only). out: (BC,4,OH,OW), 0=LL,1=LH,2=HL,3=HH.
// ---------------------------------------------------------------------------
template<int TOY, int TOX>
__global__ void afb2d_full_kernel(const float* __restrict__ in, size_t inPS,
                                  float* __restrict__ out,
                                  int H, int W, int OH, int OW) {
  constexpr int RI = 2*TOY + 6;
  constexpr int CI = 2*TOX + 6;
  __shared__ float s_in[RI][CI];
  __shared__ float s_lo[RI][TOX];
  __shared__ float s_hi[RI][TOX];

  const int bc  = blockIdx.z;
  const int ty0 = blockIdx.y * TOY;
  const int tx0 = blockIdx.x * TOX;
  const int tx = threadIdx.x, ty = threadIdx.y;
  const float* src = in + (size_t)bc * inPS;

  for (int r = ty; r < RI; r += 8) {
    int sr = refl(2*ty0 + r - 6, H);
    const float* row = src + (size_t)sr * W;
    for (int c = tx; c < CI; c += 32)
      s_in[r][c] = row[refl(2*tx0 + c - 6, W)];
  }
  __syncthreads();

  for (int r = ty; r < RI; r += 8) {
    for (int ox = tx; ox < TOX; ox += 32) {
      float lo = 0.f, hi = 0.f;
#pragma unroll
      for (int t = 0; t < 8; t++) {
        float v = s_in[r][2*ox + t];
        lo += v * DLO[7 - t];
        hi += v * DHI[7 - t];
      }
      s_lo[r][ox] = lo;
      s_hi[r][ox] = hi;
    }
  }
  __syncthreads();

  const size_t plane = (size_t)OH * OW;
  float* dst = out + (size_t)bc * 4 * plane;
  for (int oyl = ty; oyl < TOY; oyl += 8) {
    int oy = ty0 + oyl;
    if (oy >= OH) continue;
    for (int ox = tx; ox < TOX; ox += 32) {
      int gx = tx0 + ox;
      if (gx >= OW) continue;
      float ll=0.f, lh=0.f, hl=0.f, hh=0.f;
#pragma unroll
      for (int t = 0; t < 8; t++) {
        float a = s_lo[2*oyl + t][ox];
        float b = s_hi[2*oyl + t][ox];
        float kl = DLO[7 - t], kh = DHI[7 - t];
        ll += a*kl;  lh += a*kh;  hl += b*kl;  hh += b*kh;
      }
      size_t o = (size_t)oy * OW + gx;
      dst[            o] = ll;
      dst[  plane   + o] = lh;
      dst[2*plane   + o] = hl;
      dst[3*plane   + o] = hh;
    }
  }
}

// ---------------------------------------------------------------------------
// Full synthesis (level 4 inverse of delta). cf: (BC,4,h,w). out: (BC,TH,TW).
// y[j] = sum_{m} k[u0+2m] * x[(j>>1)+m],  u0 = (j&1)?0:1
// ---------------------------------------------------------------------------
template<int TOY, int TOX>
__global__ void sfb2d_full_kernel(const float* __restrict__ cf,
                                  int h, int w,
                                  float* __restrict__ out, size_t oPS,
                                  int TH, int TW) {
  constexpr int NI = TOX/2 + 3;
  __shared__ float s_lo[TOY][NI + 1];
  __shared__ float s_hi[TOY][NI + 1];

  const int bc  = blockIdx.z;
  const int jy0 = blockIdx.y * TOY;
  const int jx0 = blockIdx.x * TOX;
  const int i0  = jx0 >> 1;
  const int tx = threadIdx.x, ty = threadIdx.y;

  const size_t sp = (size_t)h * w;
  const float* pll = cf + (size_t)bc * 4 * sp;
  const float* ph0 = pll +     sp;
  const float* ph1 = pll + 2 * sp;
  const float* ph2 = pll + 3 * sp;

  for (int jyl = ty; jyl < TOY; jyl += 8) {
    int jy = jy0 + jyl;
    int base = jy >> 1;
    int u0 = (jy & 1) ? 0 : 1;
    bool okY = jy < TH;
    for (int il = tx; il < NI; il += 32) {
      int i = i0 + il;
      float lo = 0.f, hi = 0.f;
      if (okY && i < w) {
#pragma unroll
        for (int m = 0; m < 4; m++) {
          int u = u0 + 2*m;
          size_t off = (size_t)(base + m) * w + i;
          float fl = DLO[u], fh = DHI[u];
          lo += fl * pll[off] + fh * ph0[off];
          hi += fl * ph1[off] + fh * ph2[off];
        }
      }
      s_lo[jyl][il] = lo;
      s_hi[jyl][il] = hi;
    }
  }
  __syncthreads();

  float* po = out + (size_t)bc * oPS;
  for (int jyl = ty; jyl < TOY; jyl += 8) {
    int jy = jy0 + jyl;
    if (jy >= TH) continue;
    for (int jxl = tx; jxl < TOX; jxl += 32) {
      int jx = jx0 + jxl;
      if (jx >= TW) continue;
      int t0 = (jx & 1) ? 0 : 1;
      int ib = (jx >> 1) - i0;
      float acc = 0.f;
#pragma unroll
      for (int m = 0; m < 4; m++) {
        int t = t0 + 2*m;
        acc += DLO[t] * s_lo[jyl][ib + m] + DHI[t] * s_hi[jyl][ib + m];
      }
      po[(size_t)jy * TW + jx] = acc;
    }
  }
}

// ---------------------------------------------------------------------------
// Lo-only synthesis (highs are zero). ll: (BC, rows, llRS) stride llPS.
// out: (BC,TH,TW) stride oPS. ADDX fuses out = x + y.
// ---------------------------------------------------------------------------
template<int TOY, int TOX, bool ADDX>
__global__ void sfb2d_lo_kernel(const float* __restrict__ ll, size_t llPS, int llRS,
                                int w,
                                const float* __restrict__ xin,
                                float* __restrict__ out, size_t oPS,
                                int TH, int TW) {
  constexpr int NI = TOX/2 + 3;
  __shared__ float s_lo[TOY][NI + 1];

  const int bc  = blockIdx.z;
  const int jy0 = blockIdx.y * TOY;
  const int jx0 = blockIdx.x * TOX;
  const int i0  = jx0 >> 1;
  const int tx = threadIdx.x, ty = threadIdx.y;
  const float* pll = ll + (size_t)bc * llPS;

  for (int jyl = ty; jyl < TOY; jyl += 8) {
    int jy = jy0 + jyl;
    int base = jy >> 1;
    int u0 = (jy & 1) ? 0 : 1;
    float f0 = DLO[u0], f1 = DLO[u0+2], f2 = DLO[u0+4], f3 = DLO[u0+6];
    bool okY = jy < TH;
    for (int il = tx; il < NI; il += 32) {
      int i = i0 + il;
      float lo = 0.f;
      if (okY && i < w) {
        const float* p = pll + (size_t)base * llRS + i;
        lo = f0*p[0] + f1*p[llRS] + f2*p[2*(size_t)llRS] + f3*p[3*(size_t)llRS];
      }
      s_lo[jyl][il] = lo;
    }
  }
  __syncthreads();

  float* po = out + (size_t)bc * oPS;
  const float* px = xin + (size_t)bc * oPS;
  for (int jyl = ty; jyl < TOY; jyl += 8) {
    int jy = jy0 + jyl;
    if (jy >= TH) continue;
    for (int jxl = tx; jxl < TOX; jxl += 32) {
      int jx = jx0 + jxl;
      if (jx >= TW) continue;
      int t0 = (jx & 1) ? 0 : 1;
      int ib = (jx >> 1) - i0;
      float acc = DLO[t0  ] * s_lo[jyl][ib    ]
                + DLO[t0+2] * s_lo[jyl][ib + 1]
                + DLO[t0+4] * s_lo[jyl][ib + 2]
                + DLO[t0+6] * s_lo[jyl][ib + 3];
      size_t o = (size_t)jy * TW + jx;
      po[o] = ADDX ? (acc + px[o]) : acc;
    }
  }
}

// ---------------------------------------------------------------------------
// Level-4 channel mixing, emitting delta = mixed - original:
// d[b,o,s,xy] = sum_i a[b,i,s,xy]*W_s[i,o,xy] - a[b,o,s,xy]
// ---------------------------------------------------------------------------
__global__ void mul2d_delta_kernel(const float* __restrict__ in,
                                   const float* __restrict__ w1,
                                   const float* __restrict__ w2,
                                   const float* __restrict__ w3,
                                   const float* __restrict__ w4,
                                   float* __restrict__ outb) {
  const int s  = blockIdx.y;      // 0..3
  const int xy = blockIdx.x;      // 0..483
  const float* W = (s == 0) ? w1 : (s == 1) ? w2 : (s == 2) ? w3 : w4;

  __shared__ float sa[Bv][Cv];
  const int t = threadIdx.x;      // 256
  for (int idx = t; idx < Bv*Cv; idx += 256) {
    int b = idx >> 6, i = idx & 63;
    sa[b][i] = in[(((size_t)b * Cv + i) * 4 + s) * 484 + xy];
  }
  __syncthreads();

  const int o  = t & 63;
  const int bq = t >> 6;          // 0..3
  float a0=0.f, a1=0.f, a2=0.f, a3=0.f;
  for (int i = 0; i < Cv; i++) {
    float wv = W[((size_t)i * Cv + o) * 484 + xy];
    a0 += sa[bq     ][i] * wv;
    a1 += sa[bq +  4][i] * wv;
    a2 += sa[bq +  8][i] * wv;
    a3 += sa[bq + 12][i] * wv;
  }
  a0 -= sa[bq     ][o];
  a1 -= sa[bq +  4][o];
  a2 -= sa[bq +  8][o];
  a3 -= sa[bq + 12][o];
  outb[(((size_t)(bq     ) * Cv + o) * 4 + s) * 484 + xy] = a0;
  outb[(((size_t)(bq +  4) * Cv + o) * 4 + s) * 484 + xy] = a1;
  outb[(((size_t)(bq +  8) * Cv + o) * 4 + s) * 484 + xy] = a2;
  outb[(((size_t)(bq + 12) * Cv + o) * 4 + s) * 484 + xy] = a3;
}

// ---------------------------------------------------------------------------
extern "C" void kernel_launch(void* const* d_in, const int* in_sizes, int n_in,
                              void* d_out, int out_size) {
  const float* x  = (const float*)d_in[0];
  const float* w1 = (const float*)d_in[1];
  const float* w2 = (const float*)d_in[2];
  const float* w3 = (const float*)d_in[3];
  const float* w4 = (const float*)d_in[4];
  float* out = (float*)d_out;

  float *ll1, *ll2, *ll3, *l4, *d4, *r4, *r3, *r2;
  cudaGetSymbolAddress((void**)&ll1, g_ll1);
  cudaGetSymbolAddress((void**)&ll2, g_ll2);
  cudaGetSymbolAddress((void**)&ll3, g_ll3);
  cudaGetSymbolAddress((void**)&l4,  g_l4);
  cudaGetSymbolAddress((void**)&d4,  g_d4);
  cudaGetSymbolAddress((void**)&r4,  g_r4);
  cudaGetSymbolAddress((void**)&r3,  g_r3);
  cudaGetSymbolAddress((void**)&r2,  g_r2);

  const dim3 blk(32, 8);
  constexpr int TOY = 16, TOX = 32;   // analysis tile
  constexpr int SOY = 16, SOX = 64;   // synthesis tile

  auto agrid = [](int OH, int OW) {
    return dim3((OW + TOX - 1) / TOX, (OH + TOY - 1) / TOY, BCv);
  };
  auto sgrid = [](int TH, int TW) {
    return dim3((TW + SOX - 1) / SOX, (TH + SOY - 1) / SOY, BCv);
  };

  // ---- forward: LL chain, then full level-4 ----
  afb2d_ll_kernel<TOY,TOX><<<agrid(131,131), blk>>>(x,   (size_t)256*256, ll1, 256, 256, 131, 131);
  afb2d_ll_kernel<TOY,TOX><<<agrid( 69, 69), blk>>>(ll1, (size_t)131*131, ll2, 131, 131,  69,  69);
  afb2d_ll_kernel<TOY,TOX><<<agrid( 38, 38), blk>>>(ll2, (size_t)69*69,   ll3,  69,  69,  38,  38);
  afb2d_full_kernel<TOY,TOX><<<agrid(22,22), blk>>>(ll3, (size_t)38*38,   l4,   38,  38,  22,  22);

  // ---- level-4 mixing -> delta ----
  mul2d_delta_kernel<<<dim3(484, 4), 256>>>(l4, w1, w2, w3, w4, d4);

  // ---- inverse of delta ----
  sfb2d_full_kernel<SOY,SOX><<<sgrid(38,38), blk>>>(d4, 22, 22, r4, (size_t)38*38, 38, 38);
  sfb2d_lo_kernel<SOY,SOX,false><<<sgrid( 69, 69), blk>>>(r4, (size_t)38*38,   38,  38, nullptr, r3,  (size_t)69*69,    69,  69);
  sfb2d_lo_kernel<SOY,SOX,false><<<sgrid(131,131), blk>>>(r3, (size_t)69*69,   69,  69, nullptr, r2,  (size_t)131*131, 131, 131);
  sfb2d_lo_kernel<SOY,SOX,true ><<<sgrid(256,256), blk>>>(r2, (size_t)131*131, 131, 131, x,      out, (size_t)256*256, 256, 256);
}

// round 3
// speedup vs baseline: 2.1210x; 1.4079x over previous
#include <cuda_runtime.h>

// ---------------------------------------------------------------------------
// WaveConv2d via perfect-reconstruction shortcut:
//   out = x + IDWT(delta), delta nonzero only at level 4.
// R3: int32 indexing, interior fast paths, float2 vectorization, smem-staged
// synthesis, coalesced mul2d.
// ---------------------------------------------------------------------------

#define BCv 1024   // B*C

__constant__ float DLO[8] = {
  -0.010597401784997278f,  0.032883011666982945f,  0.030841381835986965f,
  -0.18703481171888114f,  -0.02798376941698385f,   0.6308807679295904f,
   0.7148465705525415f,    0.23037781330885523f };
__constant__ float DHI[8] = {
  -0.23037781330885523f,   0.7148465705525415f,   -0.6308807679295904f,
  -0.02798376941698385f,   0.18703481171888114f,   0.030841381835986965f,
  -0.032883011666982945f, -0.010597401784997278f };

// ---- scratch ----
__device__ float g_ll1[(size_t)BCv*131*131];
__device__ float g_ll2[(size_t)BCv*69*69];
__device__ float g_ll3[(size_t)BCv*38*38];
__device__ float g_l4 [(size_t)BCv*4*22*22];
__device__ float g_d4 [(size_t)BCv*4*22*22];
__device__ float g_r4 [(size_t)BCv*38*38];
__device__ float g_r3 [(size_t)BCv*69*69];
__device__ float g_r2 [(size_t)BCv*131*131];

__device__ __forceinline__ int refl(int j, int N) {
  if (j < 0)  j = -1 - j;
  if (j >= N) j = 2*N - 1 - j;
  return j;
}

// ---------------------------------------------------------------------------
// LL-only analysis level. in: (BC,H,W) -> out: (BC,OH,OW). Block (32,8).
// ---------------------------------------------------------------------------
template<int TOY, int TOX, bool VEC>
__global__ __launch_bounds__(256)
void afb_ll_kernel(const float* __restrict__ in, int inPS,
                   float* __restrict__ out,
                   int H, int W, int OH, int OW) {
  constexpr int RI = 2*TOY + 6;
  constexpr int CI = 2*TOX + 6;
  static_assert(TOX == 32, "TOX must equal blockDim.x");
  __shared__ float s_in[RI][CI];
  __shared__ float s_lo[RI][TOX];

  const int bc  = blockIdx.z;
  const int ty0 = blockIdx.y * TOY;
  const int tx0 = blockIdx.x * TOX;
  const int tx = threadIdx.x, ty = threadIdx.y;
  const float* src = in + bc * inPS;

  const bool interior = (ty0 >= 3) && (2*ty0 + 2*TOY <= H) &&
                        (tx0 >= 3) && (2*tx0 + 2*TOX <= W);
  if (interior) {
    const float* base = src + (2*ty0 - 6) * W + (2*tx0 - 6);
    if (VEC) {
#pragma unroll
      for (int r = ty; r < RI; r += 8) {
        const float2* p = reinterpret_cast<const float2*>(base + r * W);
        float2* srow = reinterpret_cast<float2*>(&s_in[r][0]);
#pragma unroll
        for (int c = tx; c < CI/2; c += 32) srow[c] = p[c];
      }
    } else {
#pragma unroll
      for (int r = ty; r < RI; r += 8) {
        const float* p = base + r * W;
#pragma unroll
        for (int c = tx; c < CI; c += 32) s_in[r][c] = p[c];
      }
    }
  } else {
    for (int r = ty; r < RI; r += 8) {
      int sr = refl(2*ty0 + r - 6, H);
      const float* row = src + sr * W;
      for (int c = tx; c < CI; c += 32)
        s_in[r][c] = row[refl(2*tx0 + c - 6, W)];
    }
  }
  __syncthreads();

#pragma unroll
  for (int r = ty; r < RI; r += 8) {
    const float2* p2 = reinterpret_cast<const float2*>(&s_in[r][0]) + tx;
    float2 v0 = p2[0], v1 = p2[1], v2 = p2[2], v3 = p2[3];
    s_lo[r][tx] = v0.x*DLO[7] + v0.y*DLO[6] + v1.x*DLO[5] + v1.y*DLO[4]
                + v2.x*DLO[3] + v2.y*DLO[2] + v3.x*DLO[1] + v3.y*DLO[0];
  }
  __syncthreads();

  float* dst = out + bc * OH * OW;
  const int gx = tx0 + tx;
#pragma unroll
  for (int oyl = ty; oyl < TOY; oyl += 8) {
    int oy = ty0 + oyl;
    if (oy < OH && gx < OW) {
      float acc = 0.f;
#pragma unroll
      for (int t = 0; t < 8; t++) acc += s_lo[2*oyl + t][tx] * DLO[7 - t];
      dst[oy * OW + gx] = acc;
    }
  }
}

// ---------------------------------------------------------------------------
// Level-4 full analysis: whole 38x38 -> 4 x 22x22, one block per plane.
// ---------------------------------------------------------------------------
__global__ __launch_bounds__(256)
void afb_full22_kernel(const float* __restrict__ in, float* __restrict__ out) {
  __shared__ float s_in[50][50];
  __shared__ float s_lo[50][22];
  __shared__ float s_hi[50][22];
  const int bc = blockIdx.x;
  const int tx = threadIdx.x, ty = threadIdx.y;
  const float* src = in + bc * 1444;

  for (int r = ty; r < 50; r += 8) {
    int sr = refl(r - 6, 38);
    const float* row = src + sr * 38;
    for (int c = tx; c < 50; c += 32) s_in[r][c] = row[refl(c - 6, 38)];
  }
  __syncthreads();

  if (tx < 22) {
#pragma unroll
    for (int r = ty; r < 50; r += 8) {
      float lo = 0.f, hi = 0.f;
#pragma unroll
      for (int t = 0; t < 8; t++) {
        float v = s_in[r][2*tx + t];
        lo += v * DLO[7 - t];
        hi += v * DHI[7 - t];
      }
      s_lo[r][tx] = lo;
      s_hi[r][tx] = hi;
    }
  }
  __syncthreads();

  float* dst = out + bc * 4 * 484;
  if (tx < 22) {
#pragma unroll
    for (int oy = ty; oy < 22; oy += 8) {
      float ll=0.f, lh=0.f, hl=0.f, hh=0.f;
#pragma unroll
      for (int t = 0; t < 8; t++) {
        float a = s_lo[2*oy + t][tx];
        float b = s_hi[2*oy + t][tx];
        float kl = DLO[7 - t], kh = DHI[7 - t];
        ll += a*kl;  lh += a*kh;  hl += b*kl;  hh += b*kh;
      }
      int o = oy * 22 + tx;
      dst[o] = ll;  dst[484 + o] = lh;  dst[968 + o] = hl;  dst[1452 + o] = hh;
    }
  }
}

// ---------------------------------------------------------------------------
// Level-4 full synthesis of delta: (BC,4,22,22) -> (BC,38,38), block per plane.
// ---------------------------------------------------------------------------
__global__ __launch_bounds__(256)
void sfb_full22_kernel(const float* __restrict__ cf, float* __restrict__ out) {
  __shared__ float s_lo[38][23];
  __shared__ float s_hi[38][23];
  const int bc = blockIdx.x;
  const int tx = threadIdx.x, ty = threadIdx.y;
  const float* pll = cf + bc * 1936;
  const float* ph0 = pll + 484;
  const float* ph1 = pll + 968;
  const float* ph2 = pll + 1452;

  if (tx < 22) {
#pragma unroll
    for (int jy = ty; jy < 38; jy += 8) {
      int base = jy >> 1;
      int u0 = 1 - (jy & 1);
      float lo = 0.f, hi = 0.f;
#pragma unroll
      for (int m = 0; m < 4; m++) {
        int u = u0 + 2*m;
        int off = (base + m) * 22 + tx;
        float fl = DLO[u], fh = DHI[u];
        lo += fl * pll[off] + fh * ph0[off];
        hi += fl * ph1[off] + fh * ph2[off];
      }
      s_lo[jy][tx] = lo;
      s_hi[jy][tx] = hi;
    }
  }
  __syncthreads();

  float* po = out + bc * 1444;
#pragma unroll
  for (int jy = ty; jy < 38; jy += 8) {
#pragma unroll
    for (int jx = tx; jx < 38; jx += 32) {
      int t0 = 1 - (jx & 1);
      int ib = jx >> 1;
      float acc = DLO[t0  ] * s_lo[jy][ib  ] + DHI[t0  ] * s_hi[jy][ib  ]
                + DLO[t0+2] * s_lo[jy][ib+1] + DHI[t0+2] * s_hi[jy][ib+1]
                + DLO[t0+4] * s_lo[jy][ib+2] + DHI[t0+4] * s_hi[jy][ib+2]
                + DLO[t0+6] * s_lo[jy][ib+3] + DHI[t0+6] * s_hi[jy][ib+3];
      po[jy * 38 + jx] = acc;
    }
  }
}

// ---------------------------------------------------------------------------
// Lo-only synthesis (highs zero). ll: (BC,h,llRS). out: (BC,TH,TW).
// EXACT: no bounds checks (sizes divide tiles), float2 stores. ADDX: out += x.
// ---------------------------------------------------------------------------
template<int SOY, int SOX, bool ADDX, bool EXACT>
__global__ __launch_bounds__(256)
void sfb_lo_kernel(const float* __restrict__ ll, int llPS, int llRS,
                   int h, int w,
                   const float* __restrict__ xin,
                   float* __restrict__ out, int oPS,
                   int TH, int TW) {
  constexpr int NI = SOX/2 + 3;
  constexpr int RL = SOY/2 + 4;
  __shared__ float s_ll[RL][NI];
  __shared__ float s_lo[SOY][NI + 1];

  const int bc  = blockIdx.z;
  const int jy0 = blockIdx.y * SOY;
  const int jx0 = blockIdx.x * SOX;
  const int i0  = jx0 >> 1;
  const int bl0 = jy0 >> 1;
  const int tx = threadIdx.x, ty = threadIdx.y;
  const float* pll = ll + bc * llPS + bl0 * llRS + i0;

  // stage 0: ll tile -> smem
  if (EXACT) {
#pragma unroll
    for (int r = ty; r < RL; r += 8)
#pragma unroll
      for (int c = tx; c < NI; c += 32)
        s_ll[r][c] = pll[r * llRS + c];
  } else {
    for (int r = ty; r < RL; r += 8)
      for (int c = tx; c < NI; c += 32)
        s_ll[r][c] = (bl0 + r < h && i0 + c < w) ? pll[r * llRS + c] : 0.f;
  }
  __syncthreads();

  // stage 1: vertical synthesis
#pragma unroll
  for (int jyl = ty; jyl < SOY; jyl += 8) {
    int jy = jy0 + jyl;
    int rb = (jy >> 1) - bl0;
    int u0 = 1 - (jy & 1);
    float f0 = DLO[u0], f1 = DLO[u0+2], f2 = DLO[u0+4], f3 = DLO[u0+6];
#pragma unroll
    for (int il = tx; il < NI; il += 32)
      s_lo[jyl][il] = f0*s_ll[rb][il] + f1*s_ll[rb+1][il]
                    + f2*s_ll[rb+2][il] + f3*s_ll[rb+3][il];
  }
  __syncthreads();

  // stage 2: horizontal synthesis
  float* po = out + bc * oPS;
  if (EXACT) {
    const float* px = xin + bc * oPS;
#pragma unroll
    for (int jyl = ty; jyl < SOY; jyl += 8) {
      int jy = jy0 + jyl;
#pragma unroll
      for (int pr = tx; pr < SOX/2; pr += 32) {
        float s0 = s_lo[jyl][pr  ], s1 = s_lo[jyl][pr+1];
        float s2 = s_lo[jyl][pr+2], s3 = s_lo[jyl][pr+3];
        float2 v;
        v.x = DLO[1]*s0 + DLO[3]*s1 + DLO[5]*s2 + DLO[7]*s3;  // even jx
        v.y = DLO[0]*s0 + DLO[2]*s1 + DLO[4]*s2 + DLO[6]*s3;  // odd jx
        int o = jy * TW + jx0 + 2*pr;
        if (ADDX) {
          float2 xv = *reinterpret_cast<const float2*>(px + o);
          v.x += xv.x; v.y += xv.y;
        }
        *reinterpret_cast<float2*>(po + o) = v;
      }
    }
  } else {
    for (int jyl = ty; jyl < SOY; jyl += 8) {
      int jy = jy0 + jyl;
      if (jy >= TH) continue;
#pragma unroll
      for (int jxl = tx; jxl < SOX; jxl += 32) {
        int jx = jx0 + jxl;
        if (jx >= TW) continue;
        int t0 = 1 - (jx & 1);
        int ib = (jx >> 1) - i0;
        float acc = DLO[t0  ] * s_lo[jyl][ib  ]
                  + DLO[t0+2] * s_lo[jyl][ib+1]
                  + DLO[t0+4] * s_lo[jyl][ib+2]
                  + DLO[t0+6] * s_lo[jyl][ib+3];
        po[jy * TW + jx] = acc;
      }
    }
  }
}

// ---------------------------------------------------------------------------
// Level-4 channel mixing -> delta. Threads along xy (coalesced W/a/out).
// block 256 = 16 xy-lanes x 16 o-groups (4 o each). grid (31, 4).
// ---------------------------------------------------------------------------
__global__ __launch_bounds__(256)
void mul2d_delta_kernel(const float* __restrict__ in,
                        const float* __restrict__ w1,
                        const float* __restrict__ w2,
                        const float* __restrict__ w3,
                        const float* __restrict__ w4,
                        float* __restrict__ outb) {
  const int s   = blockIdx.y;
  const int xy0 = blockIdx.x * 16;
  const float* W = (s == 0) ? w1 : (s == 1) ? w2 : (s == 2) ? w3 : w4;
  const int t = threadIdx.x;
  const int lane = t & 15, g = t >> 4;
  const int xy = xy0 + lane;

  __shared__ float Ws[8][64][16];
  __shared__ float As[8][16][16];
  float acc[16][4];
#pragma unroll
  for (int b = 0; b < 16; b++)
#pragma unroll
    for (int oo = 0; oo < 4; oo++) acc[b][oo] = 0.f;

  for (int i0 = 0; i0 < 64; i0 += 8) {
    __syncthreads();
#pragma unroll
    for (int k = 0; k < 32; k++) {           // stage W chunk: 8*64*16
      int f = t + 256*k;
      int ii = f >> 10, o = (f & 1023) >> 4, lx = f & 15;
      int xyl = xy0 + lx; xyl = xyl < 484 ? xyl : 483;
      Ws[ii][o][lx] = W[((i0 + ii)*64 + o)*484 + xyl];
    }
#pragma unroll
    for (int k = 0; k < 8; k++) {            // stage a chunk: 8*16*16
      int f = t + 256*k;
      int ii = f >> 8, b = (f >> 4) & 15, lx = f & 15;
      int xyl = xy0 + lx; xyl = xyl < 484 ? xyl : 483;
      As[ii][b][lx] = in[((b*64 + (i0 + ii))*4 + s)*484 + xyl];
    }
    __syncthreads();
#pragma unroll
    for (int ii = 0; ii < 8; ii++) {
      float wv0 = Ws[ii][g*4 + 0][lane];
      float wv1 = Ws[ii][g*4 + 1][lane];
      float wv2 = Ws[ii][g*4 + 2][lane];
      float wv3 = Ws[ii][g*4 + 3][lane];
#pragma unroll
      for (int b = 0; b < 16; b++) {
        float av = As[ii][b][lane];
        acc[b][0] += av*wv0;  acc[b][1] += av*wv1;
        acc[b][2] += av*wv2;  acc[b][3] += av*wv3;
      }
    }
  }

  if (xy < 484) {
#pragma unroll
    for (int b = 0; b < 16; b++)
#pragma unroll
      for (int oo = 0; oo < 4; oo++) {
        int o = g*4 + oo;
        int idx = ((b*64 + o)*4 + s)*484 + xy;
        outb[idx] = acc[b][oo] - in[idx];     // delta = mixed - original
      }
  }
}

// ---------------------------------------------------------------------------
extern "C" void kernel_launch(void* const* d_in, const int* in_sizes, int n_in,
                              void* d_out, int out_size) {
  const float* x  = (const float*)d_in[0];
  const float* w1 = (const float*)d_in[1];
  const float* w2 = (const float*)d_in[2];
  const float* w3 = (const float*)d_in[3];
  const float* w4 = (const float*)d_in[4];
  float* out = (float*)d_out;

  float *ll1, *ll2, *ll3, *l4, *d4, *r4, *r3, *r2;
  cudaGetSymbolAddress((void**)&ll1, g_ll1);
  cudaGetSymbolAddress((void**)&ll2, g_ll2);
  cudaGetSymbolAddress((void**)&ll3, g_ll3);
  cudaGetSymbolAddress((void**)&l4,  g_l4);
  cudaGetSymbolAddress((void**)&d4,  g_d4);
  cudaGetSymbolAddress((void**)&r4,  g_r4);
  cudaGetSymbolAddress((void**)&r3,  g_r3);
  cudaGetSymbolAddress((void**)&r2,  g_r2);

  const dim3 blk(32, 8);
  constexpr int TOY = 16, TOX = 32;
  constexpr int SOY = 16, SOX = 64;
  auto agrid = [](int OH, int OW) {
    return dim3((OW + TOX - 1)/TOX, (OH + TOY - 1)/TOY, BCv);
  };
  auto sgrid = [](int TH, int TW) {
    return dim3((TW + SOX - 1)/SOX, (TH + SOY - 1)/SOY, BCv);
  };

  // forward: LL chain, then full level 4
  afb_ll_kernel<TOY,TOX,true ><<<agrid(131,131), blk>>>(x,   256*256, ll1, 256, 256, 131, 131);
  afb_ll_kernel<TOY,TOX,false><<<agrid( 69, 69), blk>>>(ll1, 131*131, ll2, 131, 131,  69,  69);
  afb_ll_kernel<TOY,TOX,false><<<agrid( 38, 38), blk>>>(ll2,   69*69, ll3,  69,  69,  38,  38);
  afb_full22_kernel<<<BCv, blk>>>(ll3, l4);

  // level-4 mixing -> delta
  mul2d_delta_kernel<<<dim3(31, 4), 256>>>(l4, w1, w2, w3, w4, d4);

  // inverse of delta
  sfb_full22_kernel<<<BCv, blk>>>(d4, r4);
  sfb_lo_kernel<SOY,SOX,false,false><<<sgrid( 69, 69), blk>>>(r4, 38*38,   38, 38, 38,  nullptr, r3,  69*69,    69,  69);
  sfb_lo_kernel<SOY,SOX,false,false><<<sgrid(131,131), blk>>>(r3, 69*69,   69, 69, 69,  nullptr, r2,  131*131, 131, 131);
  sfb_lo_kernel<SOY,SOX,true ,true ><<<sgrid(256,256), blk>>>(r2, 131*131, 131,131,131, x,       out, 256*256, 256, 256);
}

// round 4
// speedup vs baseline: 2.3223x; 1.0949x over previous
#include <cuda_runtime.h>

// ---------------------------------------------------------------------------
// WaveConv2d via perfect-reconstruction shortcut:
//   out = x + IDWT(delta), delta nonzero only at level 4.
// R4: direct-load interior level-1 afb, float4 final sfb, fused mid levels.
// ---------------------------------------------------------------------------

#define BCv 1024   // B*C

__constant__ float DLO[8] = {
  -0.010597401784997278f,  0.032883011666982945f,  0.030841381835986965f,
  -0.18703481171888114f,  -0.02798376941698385f,   0.6308807679295904f,
   0.7148465705525415f,    0.23037781330885523f };
__constant__ float DHI[8] = {
  -0.23037781330885523f,   0.7148465705525415f,   -0.6308807679295904f,
  -0.02798376941698385f,   0.18703481171888114f,   0.030841381835986965f,
  -0.032883011666982945f, -0.010597401784997278f };

// ---- scratch ----
__device__ float g_ll1[(size_t)BCv*131*131];
__device__ float g_ll2[(size_t)BCv*69*69];
__device__ float g_l4 [(size_t)BCv*4*22*22];
__device__ float g_d4 [(size_t)BCv*4*22*22];
__device__ float g_r3 [(size_t)BCv*69*69];
__device__ float g_r2 [(size_t)BCv*131*131];

__device__ __forceinline__ int refl(int j, int N) {
  if (j < 0)  j = -1 - j;
  if (j >= N) j = 2*N - 1 - j;
  return j;
}

// ---------------------------------------------------------------------------
// Level-1 analysis (256x256 -> 131x131, LL only). Interior: direct global
// float2 reads in the row pass (no s_in staging). Block (32,8).
// ---------------------------------------------------------------------------
__global__ __launch_bounds__(256)
void afb_ll1_kernel(const float* __restrict__ in, float* __restrict__ out) {
  constexpr int TOY = 16, TOX = 32;
  constexpr int RI = 2*TOY + 6;           // 38
  __shared__ float s_lo[RI][TOX];
  __shared__ float s_in[RI][2*TOX + 6];   // boundary path only

  const int bc  = blockIdx.z;
  const int ty0 = blockIdx.y * TOY;
  const int tx0 = blockIdx.x * TOX;
  const int tx = threadIdx.x, ty = threadIdx.y;
  const float* src = in + bc * 65536;

  const bool interior = (ty0 >= 3) && (2*ty0 + 2*TOY <= 256) &&
                        (tx0 >= 3) && (2*tx0 + 2*TOX <= 256);
  if (interior) {
    const float2* base = reinterpret_cast<const float2*>(src + (2*ty0 - 6)*256 + (2*tx0 - 6));
#pragma unroll
    for (int r = ty; r < RI; r += 8) {
      const float2* p = base + r*128 + tx;
      float2 v0 = p[0], v1 = p[1], v2 = p[2], v3 = p[3];
      s_lo[r][tx] = v0.x*DLO[7] + v0.y*DLO[6] + v1.x*DLO[5] + v1.y*DLO[4]
                  + v2.x*DLO[3] + v2.y*DLO[2] + v3.x*DLO[1] + v3.y*DLO[0];
    }
  } else {
    for (int r = ty; r < RI; r += 8) {
      int sr = refl(2*ty0 + r - 6, 256);
      const float* row = src + sr * 256;
      for (int c = tx; c < 2*TOX + 6; c += 32)
        s_in[r][c] = row[refl(2*tx0 + c - 6, 256)];
    }
    __syncthreads();
#pragma unroll
    for (int r = ty; r < RI; r += 8) {
      float acc = 0.f;
#pragma unroll
      for (int t = 0; t < 8; t++) acc += s_in[r][2*tx + t] * DLO[7 - t];
      s_lo[r][tx] = acc;
    }
  }
  __syncthreads();

  float* dst = out + bc * 17161;
  const int gx = tx0 + tx;
#pragma unroll
  for (int oyl = ty; oyl < TOY; oyl += 8) {
    int oy = ty0 + oyl;
    if (oy < 131 && gx < 131) {
      float acc = 0.f;
#pragma unroll
      for (int t = 0; t < 8; t++) acc += s_lo[2*oyl + t][tx] * DLO[7 - t];
      dst[oy * 131 + gx] = acc;
    }
  }
}

// ---------------------------------------------------------------------------
// Generic LL-only analysis (used for level 2: 131 -> 69). Block (32,8).
// ---------------------------------------------------------------------------
template<int TOY, int TOX>
__global__ __launch_bounds__(256)
void afb_ll_kernel(const float* __restrict__ in, int inPS,
                   float* __restrict__ out,
                   int H, int W, int OH, int OW) {
  constexpr int RI = 2*TOY + 6;
  constexpr int CI = 2*TOX + 6;
  __shared__ float s_in[RI][CI];
  __shared__ float s_lo[RI][TOX];

  const int bc  = blockIdx.z;
  const int ty0 = blockIdx.y * TOY;
  const int tx0 = blockIdx.x * TOX;
  const int tx = threadIdx.x, ty = threadIdx.y;
  const float* src = in + bc * inPS;

  for (int r = ty; r < RI; r += 8) {
    int sr = refl(2*ty0 + r - 6, H);
    const float* row = src + sr * W;
    for (int c = tx; c < CI; c += 32)
      s_in[r][c] = row[refl(2*tx0 + c - 6, W)];
  }
  __syncthreads();

#pragma unroll
  for (int r = ty; r < RI; r += 8) {
    float acc = 0.f;
#pragma unroll
    for (int t = 0; t < 8; t++) acc += s_in[r][2*tx + t] * DLO[7 - t];
    s_lo[r][tx] = acc;
  }
  __syncthreads();

  float* dst = out + bc * OH * OW;
  const int gx = tx0 + tx;
#pragma unroll
  for (int oyl = ty; oyl < TOY; oyl += 8) {
    int oy = ty0 + oyl;
    if (oy < OH && gx < OW) {
      float acc = 0.f;
#pragma unroll
      for (int t = 0; t < 8; t++) acc += s_lo[2*oyl + t][tx] * DLO[7 - t];
      dst[oy * OW + gx] = acc;
    }
  }
}

// ---------------------------------------------------------------------------
// Fused forward levels 3+4: ll2 (BC,69,69) -> l4 (BC,4,22,22). Block/plane.
// Buffer A: s_in2[69][82] then s_ll3[38][50]; Buffer B: s_lo3[82][39] then
// lo4/hi4 [50][23].
// ---------------------------------------------------------------------------
__global__ __launch_bounds__(256)
void afb_fused34_kernel(const float* __restrict__ in, float* __restrict__ out) {
  __shared__ float A[69*82];
  __shared__ float Bf[82*39];
  const int bc = blockIdx.x;
  const int tx = threadIdx.x, ty = threadIdx.y;
  const float* src = in + bc * 4761;

  // P0: load ll2 with column halo (pl=6, pr=7 -> width 82)
  for (int r = ty; r < 69; r += 8)
    for (int c = tx; c < 82; c += 32)
      A[r*82 + c] = src[r*69 + refl(c - 6, 69)];
  __syncthreads();

  // P1: L3 row pass -> Bf[82][39]
  for (int pr = ty; pr < 82; pr += 8) {
    int sr = refl(pr - 6, 69);
    const float* arow = &A[sr*82];
    for (int ox = tx; ox < 38; ox += 32) {
      float acc = 0.f;
#pragma unroll
      for (int t = 0; t < 8; t++) acc += arow[2*ox + t] * DLO[7 - t];
      Bf[pr*39 + ox] = acc;
    }
  }
  __syncthreads();

  // P2: L3 col pass -> s_ll3 in A (stride 50, data at col offset 6)
  for (int oy = ty; oy < 38; oy += 8)
    for (int ox = tx; ox < 38; ox += 32) {
      float acc = 0.f;
#pragma unroll
      for (int t = 0; t < 8; t++) acc += Bf[(2*oy + t)*39 + ox] * DLO[7 - t];
      A[oy*50 + 6 + ox] = acc;
    }
  __syncthreads();

  // P3: fill column halo of s_ll3 (cols 0..5, 44..49)
  {
    int idx = ty*32 + tx;
    for (int f = idx; f < 38*12; f += 256) {
      int oy = f / 12, k = f - oy*12;
      int c = (k < 6) ? k : (k + 38);
      A[oy*50 + c] = A[oy*50 + 6 + refl(c - 6, 38)];
    }
  }
  __syncthreads();

  // P4: L4 row pass -> lo/hi in Bf ([50][23] each)
  for (int pr = ty; pr < 50; pr += 8) {
    int sr = refl(pr - 6, 38);
    const float* arow = &A[sr*50];
    if (tx < 22) {
      float lo = 0.f, hi = 0.f;
#pragma unroll
      for (int t = 0; t < 8; t++) {
        float v = arow[2*tx + t];
        lo += v * DLO[7 - t];
        hi += v * DHI[7 - t];
      }
      Bf[pr*23 + tx] = lo;
      Bf[1150 + pr*23 + tx] = hi;
    }
  }
  __syncthreads();

  // P5: L4 col pass -> 4 subbands to global
  float* dst = out + bc * 1936;
  if (tx < 22) {
#pragma unroll
    for (int oy = ty; oy < 22; oy += 8) {
      float ll=0.f, lh=0.f, hl=0.f, hh=0.f;
#pragma unroll
      for (int t = 0; t < 8; t++) {
        float a = Bf[(2*oy + t)*23 + tx];
        float b = Bf[1150 + (2*oy + t)*23 + tx];
        float kl = DLO[7 - t], kh = DHI[7 - t];
        ll += a*kl;  lh += a*kh;  hl += b*kl;  hh += b*kh;
      }
      int o = oy*22 + tx;
      dst[o] = ll;  dst[484 + o] = lh;  dst[968 + o] = hl;  dst[1452 + o] = hh;
    }
  }
}

// ---------------------------------------------------------------------------
// Fused inverse levels 4+3: d4 (BC,4,22,22) -> r3 (BC,69,69). Block/plane.
// ---------------------------------------------------------------------------
__global__ __launch_bounds__(256)
void sfb_fused43_kernel(const float* __restrict__ d4, float* __restrict__ r3) {
  __shared__ float sd[4*484];
  __shared__ float slo[38*23];
  __shared__ float shi[38*23];
  __shared__ float sr4[38*39];
  __shared__ float slo2[69*39];
  const int bc = blockIdx.x;
  const int tx = threadIdx.x, ty = threadIdx.y;
  const int t = ty*32 + tx;
  const float* src = d4 + bc * 1936;

  for (int f = t; f < 1936; f += 256) sd[f] = src[f];
  __syncthreads();

  // vertical L4
  if (tx < 22) {
#pragma unroll
    for (int jy = ty; jy < 38; jy += 8) {
      int base = jy >> 1, u0 = 1 - (jy & 1);
      float lo = 0.f, hi = 0.f;
#pragma unroll
      for (int m = 0; m < 4; m++) {
        int off = (base + m)*22 + tx;
        float fl = DLO[u0 + 2*m], fh = DHI[u0 + 2*m];
        lo += fl*sd[off]       + fh*sd[484 + off];
        hi += fl*sd[968 + off] + fh*sd[1452 + off];
      }
      slo[jy*23 + tx] = lo;
      shi[jy*23 + tx] = hi;
    }
  }
  __syncthreads();

  // horizontal L4 -> r4 (38x38)
#pragma unroll
  for (int jy = ty; jy < 38; jy += 8)
    for (int jx = tx; jx < 38; jx += 32) {
      int t0 = 1 - (jx & 1), ib = jx >> 1;
      float acc = 0.f;
#pragma unroll
      for (int m = 0; m < 4; m++)
        acc += DLO[t0 + 2*m]*slo[jy*23 + ib + m] + DHI[t0 + 2*m]*shi[jy*23 + ib + m];
      sr4[jy*39 + jx] = acc;
    }
  __syncthreads();

  // vertical L3 (lo-only)
  for (int jy2 = ty; jy2 < 69; jy2 += 8) {
    int base = jy2 >> 1, u0 = 1 - (jy2 & 1);
    float f0 = DLO[u0], f1 = DLO[u0+2], f2 = DLO[u0+4], f3 = DLO[u0+6];
    for (int i = tx; i < 38; i += 32)
      slo2[jy2*39 + i] = f0*sr4[base*39 + i]     + f1*sr4[(base+1)*39 + i]
                       + f2*sr4[(base+2)*39 + i] + f3*sr4[(base+3)*39 + i];
  }
  __syncthreads();

  // horizontal L3 -> global
  float* dst = r3 + bc * 4761;
  for (int jy2 = ty; jy2 < 69; jy2 += 8)
    for (int jx = tx; jx < 69; jx += 32) {
      int t0 = 1 - (jx & 1), ib = jx >> 1;
      float acc = DLO[t0  ]*slo2[jy2*39 + ib    ]
                + DLO[t0+2]*slo2[jy2*39 + ib + 1]
                + DLO[t0+4]*slo2[jy2*39 + ib + 2]
                + DLO[t0+6]*slo2[jy2*39 + ib + 3];
      dst[jy2*69 + jx] = acc;
    }
}

// ---------------------------------------------------------------------------
// Lo-only synthesis, generic (used 69 -> 131). Block (32,8).
// ---------------------------------------------------------------------------
template<int SOY, int SOX>
__global__ __launch_bounds__(256)
void sfb_lo_kernel(const float* __restrict__ ll, int llPS, int llRS,
                   int h, int w,
                   float* __restrict__ out, int oPS,
                   int TH, int TW) {
  constexpr int NI = SOX/2 + 3;
  constexpr int RL = SOY/2 + 4;
  __shared__ float s_ll[RL][NI];
  __shared__ float s_lo[SOY][NI + 1];

  const int bc  = blockIdx.z;
  const int jy0 = blockIdx.y * SOY;
  const int jx0 = blockIdx.x * SOX;
  const int i0  = jx0 >> 1;
  const int bl0 = jy0 >> 1;
  const int tx = threadIdx.x, ty = threadIdx.y;
  const float* pll = ll + bc * llPS + bl0 * llRS + i0;

  for (int r = ty; r < RL; r += 8)
    for (int c = tx; c < NI; c += 32)
      s_ll[r][c] = (bl0 + r < h && i0 + c < w) ? pll[r * llRS + c] : 0.f;
  __syncthreads();

#pragma unroll
  for (int jyl = ty; jyl < SOY; jyl += 8) {
    int rb = jyl >> 1;
    int u0 = 1 - (jyl & 1);
    float f0 = DLO[u0], f1 = DLO[u0+2], f2 = DLO[u0+4], f3 = DLO[u0+6];
#pragma unroll
    for (int il = tx; il < NI; il += 32)
      s_lo[jyl][il] = f0*s_ll[rb][il] + f1*s_ll[rb+1][il]
                    + f2*s_ll[rb+2][il] + f3*s_ll[rb+3][il];
  }
  __syncthreads();

  float* po = out + bc * oPS;
  for (int jyl = ty; jyl < SOY; jyl += 8) {
    int jy = jy0 + jyl;
    if (jy >= TH) continue;
#pragma unroll
    for (int jxl = tx; jxl < SOX; jxl += 32) {
      int jx = jx0 + jxl;
      if (jx >= TW) continue;
      int t0 = 1 - (jx & 1);
      int ib = (jx >> 1) - i0;
      float acc = DLO[t0  ]*s_lo[jyl][ib  ]
                + DLO[t0+2]*s_lo[jyl][ib+1]
                + DLO[t0+4]*s_lo[jyl][ib+2]
                + DLO[t0+6]*s_lo[jyl][ib+3];
      po[jy * TW + jx] = acc;
    }
  }
}

// ---------------------------------------------------------------------------
// Final synthesis 131 -> 256 fused with +x. float4 stores. Block (32,8),
// grid (2,16,1024). SOX=128, SOY=16. Exact (no bounds checks).
// ---------------------------------------------------------------------------
__global__ __launch_bounds__(256)
void sfb_final_kernel(const float* __restrict__ r2,
                      const float* __restrict__ x,
                      float* __restrict__ out) {
  constexpr int NI = 67, RL = 12;
  __shared__ __align__(16) float s_ll[RL][68];
  __shared__ __align__(16) float s_lo[16][68];

  const int bc  = blockIdx.z;
  const int jy0 = blockIdx.y * 16;
  const int jx0 = blockIdx.x * 128;
  const int i0  = jx0 >> 1;
  const int bl0 = jy0 >> 1;
  const int tx = threadIdx.x, ty = threadIdx.y;
  const float* pr2 = r2 + bc * 17161;

  // stage 0: ll tile (rows clamped at bottom edge; cols always in range)
  for (int r = ty; r < RL; r += 8) {
    int rr = bl0 + r; rr = rr < 131 ? rr : 130;
    const float* row = pr2 + rr * 131 + i0;
    for (int c = tx; c < NI; c += 32)
      s_ll[r][c] = row[c];
  }
  __syncthreads();

  // stage 1: vertical synthesis
#pragma unroll
  for (int jyl = ty; jyl < 16; jyl += 8) {
    int rb = jyl >> 1;
    int u0 = 1 - (jyl & 1);
    float f0 = DLO[u0], f1 = DLO[u0+2], f2 = DLO[u0+4], f3 = DLO[u0+6];
#pragma unroll
    for (int c = tx; c < NI; c += 32)
      s_lo[jyl][c] = f0*s_ll[rb][c] + f1*s_ll[rb+1][c]
                   + f2*s_ll[rb+2][c] + f3*s_ll[rb+3][c];
  }
  __syncthreads();

  // stage 2: horizontal synthesis, 1 float4 per thread per row
  float* po = out + bc * 65536;
  const float* px = x + bc * 65536;
  const float k0 = DLO[0], k1 = DLO[1], k2 = DLO[2], k3 = DLO[3];
  const float k4 = DLO[4], k5 = DLO[5], k6 = DLO[6], k7 = DLO[7];
#pragma unroll
  for (int jyl = ty; jyl < 16; jyl += 8) {
    int jy = jy0 + jyl;
    const float2* sp = reinterpret_cast<const float2*>(&s_lo[jyl][0]);
    float2 a = sp[tx], b = sp[tx + 1], c2 = sp[tx + 2];
    float4 v;
    v.x = k1*a.x + k3*a.y + k5*b.x + k7*b.y;
    v.y = k0*a.x + k2*a.y + k4*b.x + k6*b.y;
    v.z = k1*a.y + k3*b.x + k5*b.y + k7*c2.x;
    v.w = k0*a.y + k2*b.x + k4*b.y + k6*c2.x;
    int o = jy * 256 + jx0 + 4*tx;
    float4 xv = *reinterpret_cast<const float4*>(px + o);
    v.x += xv.x; v.y += xv.y; v.z += xv.z; v.w += xv.w;
    *reinterpret_cast<float4*>(po + o) = v;
  }
}

// ---------------------------------------------------------------------------
// Level-4 channel mixing -> delta (unchanged from R3).
// ---------------------------------------------------------------------------
__global__ __launch_bounds__(256)
void mul2d_delta_kernel(const float* __restrict__ in,
                        const float* __restrict__ w1,
                        const float* __restrict__ w2,
                        const float* __restrict__ w3,
                        const float* __restrict__ w4,
                        float* __restrict__ outb) {
  const int s   = blockIdx.y;
  const int xy0 = blockIdx.x * 16;
  const float* W = (s == 0) ? w1 : (s == 1) ? w2 : (s == 2) ? w3 : w4;
  const int t = threadIdx.x;
  const int lane = t & 15, g = t >> 4;
  const int xy = xy0 + lane;

  __shared__ float Ws[8][64][16];
  __shared__ float As[8][16][16];
  float acc[16][4];
#pragma unroll
  for (int b = 0; b < 16; b++)
#pragma unroll
    for (int oo = 0; oo < 4; oo++) acc[b][oo] = 0.f;

  for (int i0 = 0; i0 < 64; i0 += 8) {
    __syncthreads();
#pragma unroll
    for (int k = 0; k < 32; k++) {
      int f = t + 256*k;
      int ii = f >> 10, o = (f & 1023) >> 4, lx = f & 15;
      int xyl = xy0 + lx; xyl = xyl < 484 ? xyl : 483;
      Ws[ii][o][lx] = W[((i0 + ii)*64 + o)*484 + xyl];
    }
#pragma unroll
    for (int k = 0; k < 8; k++) {
      int f = t + 256*k;
      int ii = f >> 8, b = (f >> 4) & 15, lx = f & 15;
      int xyl = xy0 + lx; xyl = xyl < 484 ? xyl : 483;
      As[ii][b][lx] = in[((b*64 + (i0 + ii))*4 + s)*484 + xyl];
    }
    __syncthreads();
#pragma unroll
    for (int ii = 0; ii < 8; ii++) {
      float wv0 = Ws[ii][g*4 + 0][lane];
      float wv1 = Ws[ii][g*4 + 1][lane];
      float wv2 = Ws[ii][g*4 + 2][lane];
      float wv3 = Ws[ii][g*4 + 3][lane];
#pragma unroll
      for (int b = 0; b < 16; b++) {
        float av = As[ii][b][lane];
        acc[b][0] += av*wv0;  acc[b][1] += av*wv1;
        acc[b][2] += av*wv2;  acc[b][3] += av*wv3;
      }
    }
  }

  if (xy < 484) {
#pragma unroll
    for (int b = 0; b < 16; b++)
#pragma unroll
      for (int oo = 0; oo < 4; oo++) {
        int o = g*4 + oo;
        int idx = ((b*64 + o)*4 + s)*484 + xy;
        outb[idx] = acc[b][oo] - in[idx];
      }
  }
}

// ---------------------------------------------------------------------------
extern "C" void kernel_launch(void* const* d_in, const int* in_sizes, int n_in,
                              void* d_out, int out_size) {
  const float* x  = (const float*)d_in[0];
  const float* w1 = (const float*)d_in[1];
  const float* w2 = (const float*)d_in[2];
  const float* w3 = (const float*)d_in[3];
  const float* w4 = (const float*)d_in[4];
  float* out = (float*)d_out;

  float *ll1, *ll2, *l4, *d4, *r3, *r2;
  cudaGetSymbolAddress((void**)&ll1, g_ll1);
  cudaGetSymbolAddress((void**)&ll2, g_ll2);
  cudaGetSymbolAddress((void**)&l4,  g_l4);
  cudaGetSymbolAddress((void**)&d4,  g_d4);
  cudaGetSymbolAddress((void**)&r3,  g_r3);
  cudaGetSymbolAddress((void**)&r2,  g_r2);

  const dim3 blk(32, 8);

  // forward
  afb_ll1_kernel<<<dim3(5, 9, BCv), blk>>>(x, ll1);
  afb_ll_kernel<16,32><<<dim3(3, 5, BCv), blk>>>(ll1, 131*131, ll2, 131, 131, 69, 69);
  afb_fused34_kernel<<<BCv, blk>>>(ll2, l4);

  // level-4 mixing -> delta
  mul2d_delta_kernel<<<dim3(31, 4), 256>>>(l4, w1, w2, w3, w4, d4);

  // inverse
  sfb_fused43_kernel<<<BCv, blk>>>(d4, r3);
  sfb_lo_kernel<16,64><<<dim3(3, 9, BCv), blk>>>(r3, 69*69, 69, 69, 69, r2, 131*131, 131, 131);
  sfb_final_kernel<<<dim3(2, 16, BCv), blk>>>(r2, x, out);
}

// round 5
// speedup vs baseline: 2.7718x; 1.1936x over previous
#include <cuda_runtime.h>

// ---------------------------------------------------------------------------
// WaveConv2d via perfect-reconstruction shortcut:
//   out = x + IDWT(delta), delta nonzero only at level 4.
// R5: o-split mul2d (occupancy), fused inverse levels 2+1 (no r2 roundtrip).
// ---------------------------------------------------------------------------

#define BCv 1024   // B*C

__constant__ float DLO[8] = {
  -0.010597401784997278f,  0.032883011666982945f,  0.030841381835986965f,
  -0.18703481171888114f,  -0.02798376941698385f,   0.6308807679295904f,
   0.7148465705525415f,    0.23037781330885523f };
__constant__ float DHI[8] = {
  -0.23037781330885523f,   0.7148465705525415f,   -0.6308807679295904f,
  -0.02798376941698385f,   0.18703481171888114f,   0.030841381835986965f,
  -0.032883011666982945f, -0.010597401784997278f };

// ---- scratch ----
__device__ float g_ll1[(size_t)BCv*131*131];
__device__ float g_ll2[(size_t)BCv*69*69];
__device__ float g_l4 [(size_t)BCv*4*22*22];
__device__ float g_d4 [(size_t)BCv*4*22*22];
__device__ float g_r3 [(size_t)BCv*69*69];

__device__ __forceinline__ int refl(int j, int N) {
  if (j < 0)  j = -1 - j;
  if (j >= N) j = 2*N - 1 - j;
  return j;
}

// ---------------------------------------------------------------------------
// Level-1 analysis (256x256 -> 131x131, LL only). Block (32,8).
// ---------------------------------------------------------------------------
__global__ __launch_bounds__(256)
void afb_ll1_kernel(const float* __restrict__ in, float* __restrict__ out) {
  constexpr int TOY = 16, TOX = 32;
  constexpr int RI = 2*TOY + 6;           // 38
  __shared__ float s_lo[RI][TOX];
  __shared__ float s_in[RI][2*TOX + 6];   // boundary path only

  const int bc  = blockIdx.z;
  const int ty0 = blockIdx.y * TOY;
  const int tx0 = blockIdx.x * TOX;
  const int tx = threadIdx.x, ty = threadIdx.y;
  const float* src = in + bc * 65536;

  const bool interior = (ty0 >= 3) && (2*ty0 + 2*TOY <= 256) &&
                        (tx0 >= 3) && (2*tx0 + 2*TOX <= 256);
  if (interior) {
    const float2* base = reinterpret_cast<const float2*>(src + (2*ty0 - 6)*256 + (2*tx0 - 6));
#pragma unroll
    for (int r = ty; r < RI; r += 8) {
      const float2* p = base + r*128 + tx;
      float2 v0 = p[0], v1 = p[1], v2 = p[2], v3 = p[3];
      s_lo[r][tx] = v0.x*DLO[7] + v0.y*DLO[6] + v1.x*DLO[5] + v1.y*DLO[4]
                  + v2.x*DLO[3] + v2.y*DLO[2] + v3.x*DLO[1] + v3.y*DLO[0];
    }
  } else {
    for (int r = ty; r < RI; r += 8) {
      int sr = refl(2*ty0 + r - 6, 256);
      const float* row = src + sr * 256;
      for (int c = tx; c < 2*TOX + 6; c += 32)
        s_in[r][c] = row[refl(2*tx0 + c - 6, 256)];
    }
    __syncthreads();
#pragma unroll
    for (int r = ty; r < RI; r += 8) {
      float acc = 0.f;
#pragma unroll
      for (int t = 0; t < 8; t++) acc += s_in[r][2*tx + t] * DLO[7 - t];
      s_lo[r][tx] = acc;
    }
  }
  __syncthreads();

  float* dst = out + bc * 17161;
  const int gx = tx0 + tx;
#pragma unroll
  for (int oyl = ty; oyl < TOY; oyl += 8) {
    int oy = ty0 + oyl;
    if (oy < 131 && gx < 131) {
      float acc = 0.f;
#pragma unroll
      for (int t = 0; t < 8; t++) acc += s_lo[2*oyl + t][tx] * DLO[7 - t];
      dst[oy * 131 + gx] = acc;
    }
  }
}

// ---------------------------------------------------------------------------
// Generic LL-only analysis (level 2: 131 -> 69). Block (32,8).
// ---------------------------------------------------------------------------
template<int TOY, int TOX>
__global__ __launch_bounds__(256)
void afb_ll_kernel(const float* __restrict__ in, int inPS,
                   float* __restrict__ out,
                   int H, int W, int OH, int OW) {
  constexpr int RI = 2*TOY + 6;
  constexpr int CI = 2*TOX + 6;
  __shared__ float s_in[RI][CI];
  __shared__ float s_lo[RI][TOX];

  const int bc  = blockIdx.z;
  const int ty0 = blockIdx.y * TOY;
  const int tx0 = blockIdx.x * TOX;
  const int tx = threadIdx.x, ty = threadIdx.y;
  const float* src = in + bc * inPS;

  for (int r = ty; r < RI; r += 8) {
    int sr = refl(2*ty0 + r - 6, H);
    const float* row = src + sr * W;
    for (int c = tx; c < CI; c += 32)
      s_in[r][c] = row[refl(2*tx0 + c - 6, W)];
  }
  __syncthreads();

#pragma unroll
  for (int r = ty; r < RI; r += 8) {
    float acc = 0.f;
#pragma unroll
    for (int t = 0; t < 8; t++) acc += s_in[r][2*tx + t] * DLO[7 - t];
    s_lo[r][tx] = acc;
  }
  __syncthreads();

  float* dst = out + bc * OH * OW;
  const int gx = tx0 + tx;
#pragma unroll
  for (int oyl = ty; oyl < TOY; oyl += 8) {
    int oy = ty0 + oyl;
    if (oy < OH && gx < OW) {
      float acc = 0.f;
#pragma unroll
      for (int t = 0; t < 8; t++) acc += s_lo[2*oyl + t][tx] * DLO[7 - t];
      dst[oy * OW + gx] = acc;
    }
  }
}

// ---------------------------------------------------------------------------
// Fused forward levels 3+4: ll2 (BC,69,69) -> l4 (BC,4,22,22). Block/plane.
// ---------------------------------------------------------------------------
__global__ __launch_bounds__(256)
void afb_fused34_kernel(const float* __restrict__ in, float* __restrict__ out) {
  __shared__ float A[69*82];
  __shared__ float Bf[82*39];
  const int bc = blockIdx.x;
  const int tx = threadIdx.x, ty = threadIdx.y;
  const float* src = in + bc * 4761;

  for (int r = ty; r < 69; r += 8)
    for (int c = tx; c < 82; c += 32)
      A[r*82 + c] = src[r*69 + refl(c - 6, 69)];
  __syncthreads();

  for (int pr = ty; pr < 82; pr += 8) {
    int sr = refl(pr - 6, 69);
    const float* arow = &A[sr*82];
    for (int ox = tx; ox < 38; ox += 32) {
      float acc = 0.f;
#pragma unroll
      for (int t = 0; t < 8; t++) acc += arow[2*ox + t] * DLO[7 - t];
      Bf[pr*39 + ox] = acc;
    }
  }
  __syncthreads();

  for (int oy = ty; oy < 38; oy += 8)
    for (int ox = tx; ox < 38; ox += 32) {
      float acc = 0.f;
#pragma unroll
      for (int t = 0; t < 8; t++) acc += Bf[(2*oy + t)*39 + ox] * DLO[7 - t];
      A[oy*50 + 6 + ox] = acc;
    }
  __syncthreads();

  {
    int idx = ty*32 + tx;
    for (int f = idx; f < 38*12; f += 256) {
      int oy = f / 12, k = f - oy*12;
      int c = (k < 6) ? k : (k + 38);
      A[oy*50 + c] = A[oy*50 + 6 + refl(c - 6, 38)];
    }
  }
  __syncthreads();

  for (int pr = ty; pr < 50; pr += 8) {
    int sr = refl(pr - 6, 38);
    const float* arow = &A[sr*50];
    if (tx < 22) {
      float lo = 0.f, hi = 0.f;
#pragma unroll
      for (int t = 0; t < 8; t++) {
        float v = arow[2*tx + t];
        lo += v * DLO[7 - t];
        hi += v * DHI[7 - t];
      }
      Bf[pr*23 + tx] = lo;
      Bf[1150 + pr*23 + tx] = hi;
    }
  }
  __syncthreads();

  float* dst = out + bc * 1936;
  if (tx < 22) {
#pragma unroll
    for (int oy = ty; oy < 22; oy += 8) {
      float ll=0.f, lh=0.f, hl=0.f, hh=0.f;
#pragma unroll
      for (int t = 0; t < 8; t++) {
        float a = Bf[(2*oy + t)*23 + tx];
        float b = Bf[1150 + (2*oy + t)*23 + tx];
        float kl = DLO[7 - t], kh = DHI[7 - t];
        ll += a*kl;  lh += a*kh;  hl += b*kl;  hh += b*kh;
      }
      int o = oy*22 + tx;
      dst[o] = ll;  dst[484 + o] = lh;  dst[968 + o] = hl;  dst[1452 + o] = hh;
    }
  }
}

// ---------------------------------------------------------------------------
// Fused inverse levels 4+3: d4 (BC,4,22,22) -> r3 (BC,69,69). Block/plane.
// ---------------------------------------------------------------------------
__global__ __launch_bounds__(256)
void sfb_fused43_kernel(const float* __restrict__ d4, float* __restrict__ r3) {
  __shared__ float sd[4*484];
  __shared__ float slo[38*23];
  __shared__ float shi[38*23];
  __shared__ float sr4[38*39];
  __shared__ float slo2[69*39];
  const int bc = blockIdx.x;
  const int tx = threadIdx.x, ty = threadIdx.y;
  const int t = ty*32 + tx;
  const float* src = d4 + bc * 1936;

  for (int f = t; f < 1936; f += 256) sd[f] = src[f];
  __syncthreads();

  if (tx < 22) {
#pragma unroll
    for (int jy = ty; jy < 38; jy += 8) {
      int base = jy >> 1, u0 = 1 - (jy & 1);
      float lo = 0.f, hi = 0.f;
#pragma unroll
      for (int m = 0; m < 4; m++) {
        int off = (base + m)*22 + tx;
        float fl = DLO[u0 + 2*m], fh = DHI[u0 + 2*m];
        lo += fl*sd[off]       + fh*sd[484 + off];
        hi += fl*sd[968 + off] + fh*sd[1452 + off];
      }
      slo[jy*23 + tx] = lo;
      shi[jy*23 + tx] = hi;
    }
  }
  __syncthreads();

#pragma unroll
  for (int jy = ty; jy < 38; jy += 8)
    for (int jx = tx; jx < 38; jx += 32) {
      int t0 = 1 - (jx & 1), ib = jx >> 1;
      float acc = 0.f;
#pragma unroll
      for (int m = 0; m < 4; m++)
        acc += DLO[t0 + 2*m]*slo[jy*23 + ib + m] + DHI[t0 + 2*m]*shi[jy*23 + ib + m];
      sr4[jy*39 + jx] = acc;
    }
  __syncthreads();

  for (int jy2 = ty; jy2 < 69; jy2 += 8) {
    int base = jy2 >> 1, u0 = 1 - (jy2 & 1);
    float f0 = DLO[u0], f1 = DLO[u0+2], f2 = DLO[u0+4], f3 = DLO[u0+6];
    for (int i = tx; i < 38; i += 32)
      slo2[jy2*39 + i] = f0*sr4[base*39 + i]     + f1*sr4[(base+1)*39 + i]
                       + f2*sr4[(base+2)*39 + i] + f3*sr4[(base+3)*39 + i];
  }
  __syncthreads();

  float* dst = r3 + bc * 4761;
  for (int jy2 = ty; jy2 < 69; jy2 += 8)
    for (int jx = tx; jx < 69; jx += 32) {
      int t0 = 1 - (jx & 1), ib = jx >> 1;
      float acc = DLO[t0  ]*slo2[jy2*39 + ib    ]
                + DLO[t0+2]*slo2[jy2*39 + ib + 1]
                + DLO[t0+4]*slo2[jy2*39 + ib + 2]
                + DLO[t0+6]*slo2[jy2*39 + ib + 3];
      dst[jy2*69 + jx] = acc;
    }
}

// ---------------------------------------------------------------------------
// Fused inverse levels 2+1: r3 (BC,69,69) -> out = x + synth (BC,256,256).
// Grid (2,16,BCv), block (32,8). All indices statically in range.
// ---------------------------------------------------------------------------
__global__ __launch_bounds__(256)
void sfb_final2_kernel(const float* __restrict__ r3,
                       const float* __restrict__ x,
                       float* __restrict__ out) {
  __shared__ float s_r3[9][37];
  __shared__ float s_t [11][37];
  __shared__ __align__(16) float s_ll[11][68];
  __shared__ __align__(16) float s_lo[16][68];

  const int bc  = blockIdx.z;
  const int jy0 = blockIdx.y * 16;     // 0..240
  const int jx0 = blockIdx.x * 128;    // 0 or 128
  const int i0  = jx0 >> 1;            // r2 col origin: 0 or 64
  const int bl0 = jy0 >> 1;            // r2 row origin: 0..120 (even)
  const int q0  = bl0 >> 1;            // r3 row origin: 0..60
  const int j0  = i0 >> 1;             // r3 col origin: 0 or 32
  const int tx = threadIdx.x, ty = threadIdx.y;
  const int t = ty*32 + tx;

  // stage A: r3 tile [9][37]
  const float* pr3 = r3 + bc * 4761 + q0 * 69 + j0;
  for (int f = t; f < 9*37; f += 256) {
    int r = f / 37, c = f - r*37;
    s_r3[r][c] = pr3[r*69 + c];
  }
  __syncthreads();

  // stage B: vertical L2-synthesis -> s_t[11][37] (r2 rows bl0..bl0+10)
  for (int f = t; f < 11*37; f += 256) {
    int rr = f / 37, c = f - rr*37;
    int rb = rr >> 1, u0 = 1 - (rr & 1);
    s_t[rr][c] = DLO[u0  ]*s_r3[rb  ][c] + DLO[u0+2]*s_r3[rb+1][c]
               + DLO[u0+4]*s_r3[rb+2][c] + DLO[u0+6]*s_r3[rb+3][c];
  }
  __syncthreads();

  // stage C: horizontal L2-synthesis -> s_ll[11][67] (r2 cols i0..i0+66)
  for (int f = t; f < 11*67; f += 256) {
    int rr = f / 67, cc = f - rr*67;
    int ib = cc >> 1, t0 = 1 - (cc & 1);
    s_ll[rr][cc] = DLO[t0  ]*s_t[rr][ib  ] + DLO[t0+2]*s_t[rr][ib+1]
                 + DLO[t0+4]*s_t[rr][ib+2] + DLO[t0+6]*s_t[rr][ib+3];
  }
  __syncthreads();

  // stage 1: vertical L1-synthesis
#pragma unroll
  for (int jyl = ty; jyl < 16; jyl += 8) {
    int rb = jyl >> 1;
    int u0 = 1 - (jyl & 1);
    float f0 = DLO[u0], f1 = DLO[u0+2], f2 = DLO[u0+4], f3 = DLO[u0+6];
#pragma unroll
    for (int c = tx; c < 67; c += 32)
      s_lo[jyl][c] = f0*s_ll[rb][c] + f1*s_ll[rb+1][c]
                   + f2*s_ll[rb+2][c] + f3*s_ll[rb+3][c];
  }
  __syncthreads();

  // stage 2: horizontal L1-synthesis, float4 out with +x
  float* po = out + bc * 65536;
  const float* px = x + bc * 65536;
  const float k0 = DLO[0], k1 = DLO[1], k2 = DLO[2], k3 = DLO[3];
  const float k4 = DLO[4], k5 = DLO[5], k6 = DLO[6], k7 = DLO[7];
#pragma unroll
  for (int jyl = ty; jyl < 16; jyl += 8) {
    int jy = jy0 + jyl;
    const float2* sp = reinterpret_cast<const float2*>(&s_lo[jyl][0]);
    float2 a = sp[tx], b = sp[tx + 1], c2 = sp[tx + 2];
    float4 v;
    v.x = k1*a.x + k3*a.y + k5*b.x + k7*b.y;
    v.y = k0*a.x + k2*a.y + k4*b.x + k6*b.y;
    v.z = k1*a.y + k3*b.x + k5*b.y + k7*c2.x;
    v.w = k0*a.y + k2*b.x + k4*b.y + k6*c2.x;
    int o = jy * 256 + jx0 + 4*tx;
    float4 xv = *reinterpret_cast<const float4*>(px + o);
    v.x += xv.x; v.y += xv.y; v.z += xv.z; v.w += xv.w;
    *reinterpret_cast<float4*>(po + o) = v;
  }
}

// ---------------------------------------------------------------------------
// Level-4 channel mixing -> delta. o split across blocks for occupancy.
// grid (31, 4, 4): bx=xy tile(16), by=s, bz=o tile(16). block 256.
// ---------------------------------------------------------------------------
__global__ __launch_bounds__(256)
void mul2d_delta_kernel(const float* __restrict__ in,
                        const float* __restrict__ w1,
                        const float* __restrict__ w2,
                        const float* __restrict__ w3,
                        const float* __restrict__ w4,
                        float* __restrict__ outb) {
  const int s   = blockIdx.y;
  const int xy0 = blockIdx.x * 16;
  const int o0  = blockIdx.z * 16;
  const float* W = (s == 0) ? w1 : (s == 1) ? w2 : (s == 2) ? w3 : w4;
  const int t = threadIdx.x;
  const int lane = t & 15, g = t >> 4;   // lane=xy, g=o within tile
  const int xy = xy0 + lane;

  __shared__ float Ws[8][16][16];
  __shared__ float As[8][16][16];
  float acc[16];
#pragma unroll
  for (int b = 0; b < 16; b++) acc[b] = 0.f;

  for (int i0 = 0; i0 < 64; i0 += 8) {
    __syncthreads();
#pragma unroll
    for (int k = 0; k < 8; k++) {        // W chunk: 8i x 16o x 16xy
      int f = t + 256*k;
      int ii = f >> 8, o = (f >> 4) & 15, lx = f & 15;
      int xyl = xy0 + lx; xyl = xyl < 484 ? xyl : 483;
      Ws[ii][o][lx] = W[((i0 + ii)*64 + o0 + o)*484 + xyl];
    }
#pragma unroll
    for (int k = 0; k < 8; k++) {        // a chunk: 8i x 16b x 16xy
      int f = t + 256*k;
      int ii = f >> 8, b = (f >> 4) & 15, lx = f & 15;
      int xyl = xy0 + lx; xyl = xyl < 484 ? xyl : 483;
      As[ii][b][lx] = in[((b*64 + (i0 + ii))*4 + s)*484 + xyl];
    }
    __syncthreads();
#pragma unroll
    for (int ii = 0; ii < 8; ii++) {
      float wv = Ws[ii][g][lane];
#pragma unroll
      for (int b = 0; b < 16; b++)
        acc[b] += As[ii][b][lane] * wv;
    }
  }

  if (xy < 484) {
    int o = o0 + g;
#pragma unroll
    for (int b = 0; b < 16; b++) {
      int idx = ((b*64 + o)*4 + s)*484 + xy;
      outb[idx] = acc[b] - in[idx];      // delta = mixed - original
    }
  }
}

// ---------------------------------------------------------------------------
extern "C" void kernel_launch(void* const* d_in, const int* in_sizes, int n_in,
                              void* d_out, int out_size) {
  const float* x  = (const float*)d_in[0];
  const float* w1 = (const float*)d_in[1];
  const float* w2 = (const float*)d_in[2];
  const float* w3 = (const float*)d_in[3];
  const float* w4 = (const float*)d_in[4];
  float* out = (float*)d_out;

  float *ll1, *ll2, *l4, *d4, *r3;
  cudaGetSymbolAddress((void**)&ll1, g_ll1);
  cudaGetSymbolAddress((void**)&ll2, g_ll2);
  cudaGetSymbolAddress((void**)&l4,  g_l4);
  cudaGetSymbolAddress((void**)&d4,  g_d4);
  cudaGetSymbolAddress((void**)&r3,  g_r3);

  const dim3 blk(32, 8);

  // forward
  afb_ll1_kernel<<<dim3(5, 9, BCv), blk>>>(x, ll1);
  afb_ll_kernel<16,32><<<dim3(3, 5, BCv), blk>>>(ll1, 131*131, ll2, 131, 131, 69, 69);
  afb_fused34_kernel<<<BCv, blk>>>(ll2, l4);

  // level-4 mixing -> delta
  mul2d_delta_kernel<<<dim3(31, 4, 4), 256>>>(l4, w1, w2, w3, w4, d4);

  // inverse
  sfb_fused43_kernel<<<BCv, blk>>>(d4, r3);
  sfb_final2_kernel<<<dim3(2, 16, BCv), blk>>>(r3, x, out);
}

// round 6
// speedup vs baseline: 3.0033x; 1.0835x over previous
#include <cuda_runtime.h>

// ---------------------------------------------------------------------------
// WaveConv2d via perfect-reconstruction shortcut:
//   out = x + IDWT(delta), delta nonzero only at level 4.
// R6: register-tiled mul2d, full-width final sfb, 32x32 level-1 afb tiles.
// ---------------------------------------------------------------------------

#define BCv 1024   // B*C

__constant__ float DLO[8] = {
  -0.010597401784997278f,  0.032883011666982945f,  0.030841381835986965f,
  -0.18703481171888114f,  -0.02798376941698385f,   0.6308807679295904f,
   0.7148465705525415f,    0.23037781330885523f };
__constant__ float DHI[8] = {
  -0.23037781330885523f,   0.7148465705525415f,   -0.6308807679295904f,
  -0.02798376941698385f,   0.18703481171888114f,   0.030841381835986965f,
  -0.032883011666982945f, -0.010597401784997278f };

// ---- scratch ----
__device__ float g_ll1[(size_t)BCv*131*131];
__device__ float g_ll2[(size_t)BCv*69*69];
__device__ float g_l4 [(size_t)BCv*4*22*22];
__device__ float g_d4 [(size_t)BCv*4*22*22];
__device__ float g_r3 [(size_t)BCv*69*69];

__device__ __forceinline__ int refl(int j, int N) {
  if (j < 0)  j = -1 - j;
  if (j >= N) j = 2*N - 1 - j;
  return j;
}

// ---------------------------------------------------------------------------
// Level-1 analysis (256x256 -> 131x131, LL only). 32x32 output tile.
// Block (32,8), grid (5,5,BCv).
// ---------------------------------------------------------------------------
__global__ __launch_bounds__(256)
void afb_ll1_kernel(const float* __restrict__ in, float* __restrict__ out) {
  constexpr int TOY = 32, TOX = 32;
  constexpr int RI = 2*TOY + 6;           // 70
  __shared__ float s_lo[RI][TOX];
  __shared__ float s_in[RI][2*TOX + 6];   // boundary path only

  const int bc  = blockIdx.z;
  const int ty0 = blockIdx.y * TOY;
  const int tx0 = blockIdx.x * TOX;
  const int tx = threadIdx.x, ty = threadIdx.y;
  const float* src = in + bc * 65536;

  const bool interior = (ty0 >= 3) && (2*ty0 + 2*TOY <= 256) &&
                        (tx0 >= 3) && (2*tx0 + 2*TOX <= 256);
  // rows/cols actually needed (tight for edge blocks)
  const int oh = min(TOY, 131 - ty0);
  const int rows = 2*oh + 6;

  if (interior) {
    const float2* base = reinterpret_cast<const float2*>(src + (2*ty0 - 6)*256 + (2*tx0 - 6));
    for (int r = ty; r < RI; r += 8) {
      const float2* p = base + r*128 + tx;
      float2 v0 = p[0], v1 = p[1], v2 = p[2], v3 = p[3];
      s_lo[r][tx] = v0.x*DLO[7] + v0.y*DLO[6] + v1.x*DLO[5] + v1.y*DLO[4]
                  + v2.x*DLO[3] + v2.y*DLO[2] + v3.x*DLO[1] + v3.y*DLO[0];
    }
  } else {
    const int ow = min(TOX, 131 - tx0);
    const int cols = 2*ow + 6;
    for (int r = ty; r < rows; r += 8) {
      int sr = refl(2*ty0 + r - 6, 256);
      const float* row = src + sr * 256;
      for (int c = tx; c < cols; c += 32)
        s_in[r][c] = row[refl(2*tx0 + c - 6, 256)];
    }
    __syncthreads();
    for (int r = ty; r < rows; r += 8) {
      if (tx < ow) {
        float acc = 0.f;
#pragma unroll
        for (int t = 0; t < 8; t++) acc += s_in[r][2*tx + t] * DLO[7 - t];
        s_lo[r][tx] = acc;
      }
    }
  }
  __syncthreads();

  float* dst = out + bc * 17161;
  const int gx = tx0 + tx;
#pragma unroll
  for (int k = 0; k < 4; k++) {
    int oyl = ty + 8*k;
    int oy = ty0 + oyl;
    if (oy < 131 && gx < 131) {
      float acc = 0.f;
#pragma unroll
      for (int t = 0; t < 8; t++) acc += s_lo[2*oyl + t][tx] * DLO[7 - t];
      dst[oy * 131 + gx] = acc;
    }
  }
}

// ---------------------------------------------------------------------------
// Generic LL-only analysis (level 2: 131 -> 69). Block (32,8).
// ---------------------------------------------------------------------------
template<int TOY, int TOX>
__global__ __launch_bounds__(256)
void afb_ll_kernel(const float* __restrict__ in, int inPS,
                   float* __restrict__ out,
                   int H, int W, int OH, int OW) {
  constexpr int RI = 2*TOY + 6;
  constexpr int CI = 2*TOX + 6;
  __shared__ float s_in[RI][CI];
  __shared__ float s_lo[RI][TOX];

  const int bc  = blockIdx.z;
  const int ty0 = blockIdx.y * TOY;
  const int tx0 = blockIdx.x * TOX;
  const int tx = threadIdx.x, ty = threadIdx.y;
  const float* src = in + bc * inPS;

  for (int r = ty; r < RI; r += 8) {
    int sr = refl(2*ty0 + r - 6, H);
    const float* row = src + sr * W;
    for (int c = tx; c < CI; c += 32)
      s_in[r][c] = row[refl(2*tx0 + c - 6, W)];
  }
  __syncthreads();

#pragma unroll
  for (int r = ty; r < RI; r += 8) {
    float acc = 0.f;
#pragma unroll
    for (int t = 0; t < 8; t++) acc += s_in[r][2*tx + t] * DLO[7 - t];
    s_lo[r][tx] = acc;
  }
  __syncthreads();

  float* dst = out + bc * OH * OW;
  const int gx = tx0 + tx;
#pragma unroll
  for (int oyl = ty; oyl < TOY; oyl += 8) {
    int oy = ty0 + oyl;
    if (oy < OH && gx < OW) {
      float acc = 0.f;
#pragma unroll
      for (int t = 0; t < 8; t++) acc += s_lo[2*oyl + t][tx] * DLO[7 - t];
      dst[oy * OW + gx] = acc;
    }
  }
}

// ---------------------------------------------------------------------------
// Fused forward levels 3+4: ll2 (BC,69,69) -> l4 (BC,4,22,22). Block/plane.
// ---------------------------------------------------------------------------
__global__ __launch_bounds__(256)
void afb_fused34_kernel(const float* __restrict__ in, float* __restrict__ out) {
  __shared__ float A[69*82];
  __shared__ float Bf[82*39];
  const int bc = blockIdx.x;
  const int tx = threadIdx.x, ty = threadIdx.y;
  const float* src = in + bc * 4761;

  for (int r = ty; r < 69; r += 8)
    for (int c = tx; c < 82; c += 32)
      A[r*82 + c] = src[r*69 + refl(c - 6, 69)];
  __syncthreads();

  for (int pr = ty; pr < 82; pr += 8) {
    int sr = refl(pr - 6, 69);
    const float* arow = &A[sr*82];
    for (int ox = tx; ox < 38; ox += 32) {
      float acc = 0.f;
#pragma unroll
      for (int t = 0; t < 8; t++) acc += arow[2*ox + t] * DLO[7 - t];
      Bf[pr*39 + ox] = acc;
    }
  }
  __syncthreads();

  for (int oy = ty; oy < 38; oy += 8)
    for (int ox = tx; ox < 38; ox += 32) {
      float acc = 0.f;
#pragma unroll
      for (int t = 0; t < 8; t++) acc += Bf[(2*oy + t)*39 + ox] * DLO[7 - t];
      A[oy*50 + 6 + ox] = acc;
    }
  __syncthreads();

  {
    int idx = ty*32 + tx;
    for (int f = idx; f < 38*12; f += 256) {
      int oy = f / 12, k = f - oy*12;
      int c = (k < 6) ? k : (k + 38);
      A[oy*50 + c] = A[oy*50 + 6 + refl(c - 6, 38)];
    }
  }
  __syncthreads();

  for (int pr = ty; pr < 50; pr += 8) {
    int sr = refl(pr - 6, 38);
    const float* arow = &A[sr*50];
    if (tx < 22) {
      float lo = 0.f, hi = 0.f;
#pragma unroll
      for (int t = 0; t < 8; t++) {
        float v = arow[2*tx + t];
        lo += v * DLO[7 - t];
        hi += v * DHI[7 - t];
      }
      Bf[pr*23 + tx] = lo;
      Bf[1150 + pr*23 + tx] = hi;
    }
  }
  __syncthreads();

  float* dst = out + bc * 1936;
  if (tx < 22) {
#pragma unroll
    for (int oy = ty; oy < 22; oy += 8) {
      float ll=0.f, lh=0.f, hl=0.f, hh=0.f;
#pragma unroll
      for (int t = 0; t < 8; t++) {
        float a = Bf[(2*oy + t)*23 + tx];
        float b = Bf[1150 + (2*oy + t)*23 + tx];
        float kl = DLO[7 - t], kh = DHI[7 - t];
        ll += a*kl;  lh += a*kh;  hl += b*kl;  hh += b*kh;
      }
      int o = oy*22 + tx;
      dst[o] = ll;  dst[484 + o] = lh;  dst[968 + o] = hl;  dst[1452 + o] = hh;
    }
  }
}

// ---------------------------------------------------------------------------
// Fused inverse levels 4+3: d4 (BC,4,22,22) -> r3 (BC,69,69). Block/plane.
// ---------------------------------------------------------------------------
__global__ __launch_bounds__(256)
void sfb_fused43_kernel(const float* __restrict__ d4, float* __restrict__ r3) {
  __shared__ float sd[4*484];
  __shared__ float slo[38*23];
  __shared__ float shi[38*23];
  __shared__ float sr4[38*39];
  __shared__ float slo2[69*39];
  const int bc = blockIdx.x;
  const int tx = threadIdx.x, ty = threadIdx.y;
  const int t = ty*32 + tx;
  const float* src = d4 + bc * 1936;

  for (int f = t; f < 1936; f += 256) sd[f] = src[f];
  __syncthreads();

  if (tx < 22) {
#pragma unroll
    for (int jy = ty; jy < 38; jy += 8) {
      int base = jy >> 1, u0 = 1 - (jy & 1);
      float lo = 0.f, hi = 0.f;
#pragma unroll
      for (int m = 0; m < 4; m++) {
        int off = (base + m)*22 + tx;
        float fl = DLO[u0 + 2*m], fh = DHI[u0 + 2*m];
        lo += fl*sd[off]       + fh*sd[484 + off];
        hi += fl*sd[968 + off] + fh*sd[1452 + off];
      }
      slo[jy*23 + tx] = lo;
      shi[jy*23 + tx] = hi;
    }
  }
  __syncthreads();

#pragma unroll
  for (int jy = ty; jy < 38; jy += 8)
    for (int jx = tx; jx < 38; jx += 32) {
      int t0 = 1 - (jx & 1), ib = jx >> 1;
      float acc = 0.f;
#pragma unroll
      for (int m = 0; m < 4; m++)
        acc += DLO[t0 + 2*m]*slo[jy*23 + ib + m] + DHI[t0 + 2*m]*shi[jy*23 + ib + m];
      sr4[jy*39 + jx] = acc;
    }
  __syncthreads();

  for (int jy2 = ty; jy2 < 69; jy2 += 8) {
    int base = jy2 >> 1, u0 = 1 - (jy2 & 1);
    float f0 = DLO[u0], f1 = DLO[u0+2], f2 = DLO[u0+4], f3 = DLO[u0+6];
    for (int i = tx; i < 38; i += 32)
      slo2[jy2*39 + i] = f0*sr4[base*39 + i]     + f1*sr4[(base+1)*39 + i]
                       + f2*sr4[(base+2)*39 + i] + f3*sr4[(base+3)*39 + i];
  }
  __syncthreads();

  float* dst = r3 + bc * 4761;
  for (int jy2 = ty; jy2 < 69; jy2 += 8)
    for (int jx = tx; jx < 69; jx += 32) {
      int t0 = 1 - (jx & 1), ib = jx >> 1;
      float acc = DLO[t0  ]*slo2[jy2*39 + ib    ]
                + DLO[t0+2]*slo2[jy2*39 + ib + 1]
                + DLO[t0+4]*slo2[jy2*39 + ib + 2]
                + DLO[t0+6]*slo2[jy2*39 + ib + 3];
      dst[jy2*69 + jx] = acc;
    }
}

// ---------------------------------------------------------------------------
// Fused inverse levels 2+1: r3 (BC,69,69) -> out = x + synth (BC,256,256).
// Full-width tiles: grid (16, BCv), block (32,8); each block emits 16x256.
// ---------------------------------------------------------------------------
__global__ __launch_bounds__(256)
void sfb_final2_kernel(const float* __restrict__ r3,
                       const float* __restrict__ x,
                       float* __restrict__ out) {
  __shared__ float s_r3[9][69];
  __shared__ float s_t [11][69];
  __shared__ __align__(16) float s_ll[11][136];
  __shared__ __align__(16) float s_lo[16][136];

  const int bc  = blockIdx.y;
  const int jy0 = blockIdx.x * 16;     // 0..240
  const int q0  = jy0 >> 2;            // r3 row origin: 0..60
  const int tx = threadIdx.x, ty = threadIdx.y;
  const int t = ty*32 + tx;

  // stage A: r3 tile [9][69]
  const float* pr3 = r3 + bc * 4761 + q0 * 69;
  for (int f = t; f < 9*69; f += 256) {
    int r = f / 69, c = f - r*69;
    s_r3[r][c] = pr3[r*69 + c];
  }
  __syncthreads();

  // stage B: vertical L2-synthesis -> s_t[11][69] (r2 rows bl0..bl0+10)
  for (int f = t; f < 11*69; f += 256) {
    int rr = f / 69, c = f - rr*69;
    int rb = rr >> 1, u0 = 1 - (rr & 1);
    s_t[rr][c] = DLO[u0  ]*s_r3[rb  ][c] + DLO[u0+2]*s_r3[rb+1][c]
               + DLO[u0+4]*s_r3[rb+2][c] + DLO[u0+6]*s_r3[rb+3][c];
  }
  __syncthreads();

  // stage C: horizontal L2-synthesis -> s_ll[11][131] (full r2 width)
  for (int f = t; f < 11*131; f += 256) {
    int rr = f / 131, cc = f - rr*131;
    int ib = cc >> 1, t0 = 1 - (cc & 1);
    s_ll[rr][cc] = DLO[t0  ]*s_t[rr][ib  ] + DLO[t0+2]*s_t[rr][ib+1]
                 + DLO[t0+4]*s_t[rr][ib+2] + DLO[t0+6]*s_t[rr][ib+3];
  }
  __syncthreads();

  // stage 1: vertical L1-synthesis -> s_lo[16][131]
#pragma unroll
  for (int jyl = ty; jyl < 16; jyl += 8) {
    int rb = jyl >> 1;
    int u0 = 1 - (jyl & 1);
    float f0 = DLO[u0], f1 = DLO[u0+2], f2 = DLO[u0+4], f3 = DLO[u0+6];
    for (int c = tx; c < 131; c += 32)
      s_lo[jyl][c] = f0*s_ll[rb][c] + f1*s_ll[rb+1][c]
                   + f2*s_ll[rb+2][c] + f3*s_ll[rb+3][c];
  }
  __syncthreads();

  // stage 2: horizontal L1-synthesis, float4 out with +x; 2 chunks of 128 cols
  float* po = out + bc * 65536;
  const float* px = x + bc * 65536;
  const float k0 = DLO[0], k1 = DLO[1], k2 = DLO[2], k3 = DLO[3];
  const float k4 = DLO[4], k5 = DLO[5], k6 = DLO[6], k7 = DLO[7];
#pragma unroll
  for (int jyl = ty; jyl < 16; jyl += 8) {
    int jy = jy0 + jyl;
    const float2* sp = reinterpret_cast<const float2*>(&s_lo[jyl][0]);
#pragma unroll
    for (int k = 0; k < 2; k++) {
      float2 a = sp[32*k + tx], b = sp[32*k + tx + 1], c2 = sp[32*k + tx + 2];
      float4 v;
      v.x = k1*a.x + k3*a.y + k5*b.x + k7*b.y;
      v.y = k0*a.x + k2*a.y + k4*b.x + k6*b.y;
      v.z = k1*a.y + k3*b.x + k5*b.y + k7*c2.x;
      v.w = k0*a.y + k2*b.x + k4*b.y + k6*c2.x;
      int o = jy * 256 + 128*k + 4*tx;
      float4 xv = *reinterpret_cast<const float4*>(px + o);
      v.x += xv.x; v.y += xv.y; v.z += xv.z; v.w += xv.w;
      *reinterpret_cast<float4*>(po + o) = v;
    }
  }
}

// ---------------------------------------------------------------------------
// Level-4 channel mixing -> delta, register-tiled.
// Block 256 = 8 xy-lanes x 32 groups; group = (bq: 4 b's) x (og: 8 o's).
// grid (61, 4): bx = xy tile of 8, by = s.
// ---------------------------------------------------------------------------
__global__ __launch_bounds__(256)
void mul2d_delta_kernel(const float* __restrict__ in,
                        const float* __restrict__ w1,
                        const float* __restrict__ w2,
                        const float* __restrict__ w3,
                        const float* __restrict__ w4,
                        float* __restrict__ outb) {
  const int s   = blockIdx.y;
  const int xy0 = blockIdx.x * 8;
  const float* W = (s == 0) ? w1 : (s == 1) ? w2 : (s == 2) ? w3 : w4;
  const int t = threadIdx.x;
  const int lane = t & 7;            // xy
  const int g    = t >> 3;           // 0..31
  const int bq   = g >> 3;           // 0..3 -> b = bq*4 + j
  const int og   = g & 7;            // 0..7 -> o = og*8 + k
  const int xy   = xy0 + lane;

  __shared__ float Ws[16][64][9];    // [i-chunk][o][xy-lane(pad)]
  __shared__ float As[16][16][9];    // [i-chunk][b][xy-lane(pad)]

  float acc[4][8];
#pragma unroll
  for (int j = 0; j < 4; j++)
#pragma unroll
    for (int k = 0; k < 8; k++) acc[j][k] = 0.f;

  for (int i0 = 0; i0 < 64; i0 += 16) {
    __syncthreads();
#pragma unroll
    for (int k = 0; k < 32; k++) {          // W chunk: 16i x 64o x 8xy
      int f = t + 256*k;
      int ii = f >> 9, o = (f >> 3) & 63, lx = f & 7;
      int xyl = xy0 + lx; xyl = xyl < 484 ? xyl : 483;
      Ws[ii][o][lx] = W[((i0 + ii)*64 + o)*484 + xyl];
    }
#pragma unroll
    for (int k = 0; k < 8; k++) {           // a chunk: 16i x 16b x 8xy
      int f = t + 256*k;
      int ii = f >> 7, b = (f >> 3) & 15, lx = f & 7;
      int xyl = xy0 + lx; xyl = xyl < 484 ? xyl : 483;
      As[ii][b][lx] = in[((b*64 + (i0 + ii))*4 + s)*484 + xyl];
    }
    __syncthreads();
#pragma unroll
    for (int ii = 0; ii < 16; ii++) {
      float wv[8], av[4];
#pragma unroll
      for (int k = 0; k < 8; k++) wv[k] = Ws[ii][og*8 + k][lane];
#pragma unroll
      for (int j = 0; j < 4; j++) av[j] = As[ii][bq*4 + j][lane];
#pragma unroll
      for (int j = 0; j < 4; j++)
#pragma unroll
        for (int k = 0; k < 8; k++)
          acc[j][k] += av[j] * wv[k];
    }
  }

  if (xy < 484) {
#pragma unroll
    for (int j = 0; j < 4; j++) {
      int b = bq*4 + j;
#pragma unroll
      for (int k = 0; k < 8; k++) {
        int o = og*8 + k;
        int idx = ((b*64 + o)*4 + s)*484 + xy;
        outb[idx] = acc[j][k] - in[idx];    // delta = mixed - original
      }
    }
  }
}

// ---------------------------------------------------------------------------
extern "C" void kernel_launch(void* const* d_in, const int* in_sizes, int n_in,
                              void* d_out, int out_size) {
  const float* x  = (const float*)d_in[0];
  const float* w1 = (const float*)d_in[1];
  const float* w2 = (const float*)d_in[2];
  const float* w3 = (const float*)d_in[3];
  const float* w4 = (const float*)d_in[4];
  float* out = (float*)d_out;

  float *ll1, *ll2, *l4, *d4, *r3;
  cudaGetSymbolAddress((void**)&ll1, g_ll1);
  cudaGetSymbolAddress((void**)&ll2, g_ll2);
  cudaGetSymbolAddress((void**)&l4,  g_l4);
  cudaGetSymbolAddress((void**)&d4,  g_d4);
  cudaGetSymbolAddress((void**)&r3,  g_r3);

  const dim3 blk(32, 8);

  // forward
  afb_ll1_kernel<<<dim3(5, 5, BCv), blk>>>(x, ll1);
  afb_ll_kernel<16,32><<<dim3(3, 5, BCv), blk>>>(ll1, 131*131, ll2, 131, 131, 69, 69);
  afb_fused34_kernel<<<BCv, blk>>>(ll2, l4);

  // level-4 mixing -> delta
  mul2d_delta_kernel<<<dim3(61, 4), 256>>>(l4, w1, w2, w3, w4, d4);

  // inverse
  sfb_fused43_kernel<<<BCv, blk>>>(d4, r3);
  sfb_final2_kernel<<<dim3(16, BCv), blk>>>(r3, x, out);
}

// round 7
// speedup vs baseline: 3.0267x; 1.0078x over previous
#include <cuda_runtime.h>

// ---------------------------------------------------------------------------
// WaveConv2d via perfect-reconstruction shortcut:
//   out = x + IDWT(delta), delta nonzero only at level 4.
// R7: mul2d o-split x4 (occupancy), 32-row final sfb tiles.
// ---------------------------------------------------------------------------

#define BCv 1024   // B*C

__constant__ float DLO[8] = {
  -0.010597401784997278f,  0.032883011666982945f,  0.030841381835986965f,
  -0.18703481171888114f,  -0.02798376941698385f,   0.6308807679295904f,
   0.7148465705525415f,    0.23037781330885523f };
__constant__ float DHI[8] = {
  -0.23037781330885523f,   0.7148465705525415f,   -0.6308807679295904f,
  -0.02798376941698385f,   0.18703481171888114f,   0.030841381835986965f,
  -0.032883011666982945f, -0.010597401784997278f };

// ---- scratch ----
__device__ float g_ll1[(size_t)BCv*131*131];
__device__ float g_ll2[(size_t)BCv*69*69];
__device__ float g_l4 [(size_t)BCv*4*22*22];
__device__ float g_d4 [(size_t)BCv*4*22*22];
__device__ float g_r3 [(size_t)BCv*69*69];

__device__ __forceinline__ int refl(int j, int N) {
  if (j < 0)  j = -1 - j;
  if (j >= N) j = 2*N - 1 - j;
  return j;
}

// ---------------------------------------------------------------------------
// Level-1 analysis (256x256 -> 131x131, LL only). 32x32 output tile.
// Block (32,8), grid (5,5,BCv).
// ---------------------------------------------------------------------------
__global__ __launch_bounds__(256)
void afb_ll1_kernel(const float* __restrict__ in, float* __restrict__ out) {
  constexpr int TOY = 32, TOX = 32;
  constexpr int RI = 2*TOY + 6;           // 70
  __shared__ float s_lo[RI][TOX];
  __shared__ float s_in[RI][2*TOX + 6];   // boundary path only

  const int bc  = blockIdx.z;
  const int ty0 = blockIdx.y * TOY;
  const int tx0 = blockIdx.x * TOX;
  const int tx = threadIdx.x, ty = threadIdx.y;
  const float* src = in + bc * 65536;

  const bool interior = (ty0 >= 3) && (2*ty0 + 2*TOY <= 256) &&
                        (tx0 >= 3) && (2*tx0 + 2*TOX <= 256);
  const int oh = min(TOY, 131 - ty0);
  const int rows = 2*oh + 6;

  if (interior) {
    const float2* base = reinterpret_cast<const float2*>(src + (2*ty0 - 6)*256 + (2*tx0 - 6));
    for (int r = ty; r < RI; r += 8) {
      const float2* p = base + r*128 + tx;
      float2 v0 = p[0], v1 = p[1], v2 = p[2], v3 = p[3];
      s_lo[r][tx] = v0.x*DLO[7] + v0.y*DLO[6] + v1.x*DLO[5] + v1.y*DLO[4]
                  + v2.x*DLO[3] + v2.y*DLO[2] + v3.x*DLO[1] + v3.y*DLO[0];
    }
  } else {
    const int ow = min(TOX, 131 - tx0);
    const int cols = 2*ow + 6;
    for (int r = ty; r < rows; r += 8) {
      int sr = refl(2*ty0 + r - 6, 256);
      const float* row = src + sr * 256;
      for (int c = tx; c < cols; c += 32)
        s_in[r][c] = row[refl(2*tx0 + c - 6, 256)];
    }
    __syncthreads();
    for (int r = ty; r < rows; r += 8) {
      if (tx < ow) {
        float acc = 0.f;
#pragma unroll
        for (int t = 0; t < 8; t++) acc += s_in[r][2*tx + t] * DLO[7 - t];
        s_lo[r][tx] = acc;
      }
    }
  }
  __syncthreads();

  float* dst = out + bc * 17161;
  const int gx = tx0 + tx;
#pragma unroll
  for (int k = 0; k < 4; k++) {
    int oyl = ty + 8*k;
    int oy = ty0 + oyl;
    if (oy < 131 && gx < 131) {
      float acc = 0.f;
#pragma unroll
      for (int t = 0; t < 8; t++) acc += s_lo[2*oyl + t][tx] * DLO[7 - t];
      dst[oy * 131 + gx] = acc;
    }
  }
}

// ---------------------------------------------------------------------------
// Generic LL-only analysis (level 2: 131 -> 69). Block (32,8).
// ---------------------------------------------------------------------------
template<int TOY, int TOX>
__global__ __launch_bounds__(256)
void afb_ll_kernel(const float* __restrict__ in, int inPS,
                   float* __restrict__ out,
                   int H, int W, int OH, int OW) {
  constexpr int RI = 2*TOY + 6;
  constexpr int CI = 2*TOX + 6;
  __shared__ float s_in[RI][CI];
  __shared__ float s_lo[RI][TOX];

  const int bc  = blockIdx.z;
  const int ty0 = blockIdx.y * TOY;
  const int tx0 = blockIdx.x * TOX;
  const int tx = threadIdx.x, ty = threadIdx.y;
  const float* src = in + bc * inPS;

  for (int r = ty; r < RI; r += 8) {
    int sr = refl(2*ty0 + r - 6, H);
    const float* row = src + sr * W;
    for (int c = tx; c < CI; c += 32)
      s_in[r][c] = row[refl(2*tx0 + c - 6, W)];
  }
  __syncthreads();

#pragma unroll
  for (int r = ty; r < RI; r += 8) {
    float acc = 0.f;
#pragma unroll
    for (int t = 0; t < 8; t++) acc += s_in[r][2*tx + t] * DLO[7 - t];
    s_lo[r][tx] = acc;
  }
  __syncthreads();

  float* dst = out + bc * OH * OW;
  const int gx = tx0 + tx;
#pragma unroll
  for (int oyl = ty; oyl < TOY; oyl += 8) {
    int oy = ty0 + oyl;
    if (oy < OH && gx < OW) {
      float acc = 0.f;
#pragma unroll
      for (int t = 0; t < 8; t++) acc += s_lo[2*oyl + t][tx] * DLO[7 - t];
      dst[oy * OW + gx] = acc;
    }
  }
}

// ---------------------------------------------------------------------------
// Fused forward levels 3+4: ll2 (BC,69,69) -> l4 (BC,4,22,22). Block/plane.
// ---------------------------------------------------------------------------
__global__ __launch_bounds__(256)
void afb_fused34_kernel(const float* __restrict__ in, float* __restrict__ out) {
  __shared__ float A[69*82];
  __shared__ float Bf[82*39];
  const int bc = blockIdx.x;
  const int tx = threadIdx.x, ty = threadIdx.y;
  const float* src = in + bc * 4761;

  for (int r = ty; r < 69; r += 8)
    for (int c = tx; c < 82; c += 32)
      A[r*82 + c] = src[r*69 + refl(c - 6, 69)];
  __syncthreads();

  for (int pr = ty; pr < 82; pr += 8) {
    int sr = refl(pr - 6, 69);
    const float* arow = &A[sr*82];
    for (int ox = tx; ox < 38; ox += 32) {
      float acc = 0.f;
#pragma unroll
      for (int t = 0; t < 8; t++) acc += arow[2*ox + t] * DLO[7 - t];
      Bf[pr*39 + ox] = acc;
    }
  }
  __syncthreads();

  for (int oy = ty; oy < 38; oy += 8)
    for (int ox = tx; ox < 38; ox += 32) {
      float acc = 0.f;
#pragma unroll
      for (int t = 0; t < 8; t++) acc += Bf[(2*oy + t)*39 + ox] * DLO[7 - t];
      A[oy*50 + 6 + ox] = acc;
    }
  __syncthreads();

  {
    int idx = ty*32 + tx;
    for (int f = idx; f < 38*12; f += 256) {
      int oy = f / 12, k = f - oy*12;
      int c = (k < 6) ? k : (k + 38);
      A[oy*50 + c] = A[oy*50 + 6 + refl(c - 6, 38)];
    }
  }
  __syncthreads();

  for (int pr = ty; pr < 50; pr += 8) {
    int sr = refl(pr - 6, 38);
    const float* arow = &A[sr*50];
    if (tx < 22) {
      float lo = 0.f, hi = 0.f;
#pragma unroll
      for (int t = 0; t < 8; t++) {
        float v = arow[2*tx + t];
        lo += v * DLO[7 - t];
        hi += v * DHI[7 - t];
      }
      Bf[pr*23 + tx] = lo;
      Bf[1150 + pr*23 + tx] = hi;
    }
  }
  __syncthreads();

  float* dst = out + bc * 1936;
  if (tx < 22) {
#pragma unroll
    for (int oy = ty; oy < 22; oy += 8) {
      float ll=0.f, lh=0.f, hl=0.f, hh=0.f;
#pragma unroll
      for (int t = 0; t < 8; t++) {
        float a = Bf[(2*oy + t)*23 + tx];
        float b = Bf[1150 + (2*oy + t)*23 + tx];
        float kl = DLO[7 - t], kh = DHI[7 - t];
        ll += a*kl;  lh += a*kh;  hl += b*kl;  hh += b*kh;
      }
      int o = oy*22 + tx;
      dst[o] = ll;  dst[484 + o] = lh;  dst[968 + o] = hl;  dst[1452 + o] = hh;
    }
  }
}

// ---------------------------------------------------------------------------
// Fused inverse levels 4+3: d4 (BC,4,22,22) -> r3 (BC,69,69). Block/plane.
// ---------------------------------------------------------------------------
__global__ __launch_bounds__(256)
void sfb_fused43_kernel(const float* __restrict__ d4, float* __restrict__ r3) {
  __shared__ float sd[4*484];
  __shared__ float slo[38*23];
  __shared__ float shi[38*23];
  __shared__ float sr4[38*39];
  __shared__ float slo2[69*39];
  const int bc = blockIdx.x;
  const int tx = threadIdx.x, ty = threadIdx.y;
  const int t = ty*32 + tx;
  const float* src = d4 + bc * 1936;

  for (int f = t; f < 1936; f += 256) sd[f] = src[f];
  __syncthreads();

  if (tx < 22) {
#pragma unroll
    for (int jy = ty; jy < 38; jy += 8) {
      int base = jy >> 1, u0 = 1 - (jy & 1);
      float lo = 0.f, hi = 0.f;
#pragma unroll
      for (int m = 0; m < 4; m++) {
        int off = (base + m)*22 + tx;
        float fl = DLO[u0 + 2*m], fh = DHI[u0 + 2*m];
        lo += fl*sd[off]       + fh*sd[484 + off];
        hi += fl*sd[968 + off] + fh*sd[1452 + off];
      }
      slo[jy*23 + tx] = lo;
      shi[jy*23 + tx] = hi;
    }
  }
  __syncthreads();

#pragma unroll
  for (int jy = ty; jy < 38; jy += 8)
    for (int jx = tx; jx < 38; jx += 32) {
      int t0 = 1 - (jx & 1), ib = jx >> 1;
      float acc = 0.f;
#pragma unroll
      for (int m = 0; m < 4; m++)
        acc += DLO[t0 + 2*m]*slo[jy*23 + ib + m] + DHI[t0 + 2*m]*shi[jy*23 + ib + m];
      sr4[jy*39 + jx] = acc;
    }
  __syncthreads();

  for (int jy2 = ty; jy2 < 69; jy2 += 8) {
    int base = jy2 >> 1, u0 = 1 - (jy2 & 1);
    float f0 = DLO[u0], f1 = DLO[u0+2], f2 = DLO[u0+4], f3 = DLO[u0+6];
    for (int i = tx; i < 38; i += 32)
      slo2[jy2*39 + i] = f0*sr4[base*39 + i]     + f1*sr4[(base+1)*39 + i]
                       + f2*sr4[(base+2)*39 + i] + f3*sr4[(base+3)*39 + i];
  }
  __syncthreads();

  float* dst = r3 + bc * 4761;
  for (int jy2 = ty; jy2 < 69; jy2 += 8)
    for (int jx = tx; jx < 69; jx += 32) {
      int t0 = 1 - (jx & 1), ib = jx >> 1;
      float acc = DLO[t0  ]*slo2[jy2*39 + ib    ]
                + DLO[t0+2]*slo2[jy2*39 + ib + 1]
                + DLO[t0+4]*slo2[jy2*39 + ib + 2]
                + DLO[t0+6]*slo2[jy2*39 + ib + 3];
      dst[jy2*69 + jx] = acc;
    }
}

// ---------------------------------------------------------------------------
// Fused inverse levels 2+1: r3 (BC,69,69) -> out = x + synth (BC,256,256).
// 32-row tiles: grid (8, BCv), block (32,8); each block emits 32x256.
// ---------------------------------------------------------------------------
__global__ __launch_bounds__(256)
void sfb_final2_kernel(const float* __restrict__ r3,
                       const float* __restrict__ x,
                       float* __restrict__ out) {
  __shared__ float s_r3[13][69];
  __shared__ float s_t [19][69];
  __shared__ __align__(16) float s_ll[19][136];
  __shared__ __align__(16) float s_lo[32][136];

  const int bc  = blockIdx.y;
  const int jy0 = blockIdx.x * 32;     // 0..224
  const int q0  = jy0 >> 2;            // r3 row origin: 0..56
  const int tx = threadIdx.x, ty = threadIdx.y;
  const int t = ty*32 + tx;

  // stage A: r3 tile [13][69] (rows q0..q0+12, max 68)
  const float* pr3 = r3 + bc * 4761 + q0 * 69;
  for (int f = t; f < 13*69; f += 256) {
    int r = f / 69, c = f - r*69;
    s_r3[r][c] = pr3[r*69 + c];
  }
  __syncthreads();

  // stage B: vertical L2-synthesis -> s_t[19][69] (r2 rows jy0/2 .. +18)
  for (int f = t; f < 19*69; f += 256) {
    int rr = f / 69, c = f - rr*69;
    int rb = rr >> 1, u0 = 1 - (rr & 1);
    s_t[rr][c] = DLO[u0  ]*s_r3[rb  ][c] + DLO[u0+2]*s_r3[rb+1][c]
               + DLO[u0+4]*s_r3[rb+2][c] + DLO[u0+6]*s_r3[rb+3][c];
  }
  __syncthreads();

  // stage C: horizontal L2-synthesis -> s_ll[19][131] (full r2 width)
  for (int f = t; f < 19*131; f += 256) {
    int rr = f / 131, cc = f - rr*131;
    int ib = cc >> 1, t0 = 1 - (cc & 1);
    s_ll[rr][cc] = DLO[t0  ]*s_t[rr][ib  ] + DLO[t0+2]*s_t[rr][ib+1]
                 + DLO[t0+4]*s_t[rr][ib+2] + DLO[t0+6]*s_t[rr][ib+3];
  }
  __syncthreads();

  // stage 1: vertical L1-synthesis -> s_lo[32][131]
#pragma unroll
  for (int jyl = ty; jyl < 32; jyl += 8) {
    int rb = jyl >> 1;
    int u0 = 1 - (jyl & 1);
    float f0 = DLO[u0], f1 = DLO[u0+2], f2 = DLO[u0+4], f3 = DLO[u0+6];
    for (int c = tx; c < 131; c += 32)
      s_lo[jyl][c] = f0*s_ll[rb][c] + f1*s_ll[rb+1][c]
                   + f2*s_ll[rb+2][c] + f3*s_ll[rb+3][c];
  }
  __syncthreads();

  // stage 2: horizontal L1-synthesis, float4 out with +x
  float* po = out + bc * 65536;
  const float* px = x + bc * 65536;
  const float k0 = DLO[0], k1 = DLO[1], k2 = DLO[2], k3 = DLO[3];
  const float k4 = DLO[4], k5 = DLO[5], k6 = DLO[6], k7 = DLO[7];
#pragma unroll
  for (int jyl = ty; jyl < 32; jyl += 8) {
    int jy = jy0 + jyl;
    const float2* sp = reinterpret_cast<const float2*>(&s_lo[jyl][0]);
#pragma unroll
    for (int k = 0; k < 2; k++) {
      float2 a = sp[32*k + tx], b = sp[32*k + tx + 1], c2 = sp[32*k + tx + 2];
      float4 v;
      v.x = k1*a.x + k3*a.y + k5*b.x + k7*b.y;
      v.y = k0*a.x + k2*a.y + k4*b.x + k6*b.y;
      v.z = k1*a.y + k3*b.x + k5*b.y + k7*c2.x;
      v.w = k0*a.y + k2*b.x + k4*b.y + k6*c2.x;
      int o = jy * 256 + 128*k + 4*tx;
      float4 xv = *reinterpret_cast<const float4*>(px + o);
      v.x += xv.x; v.y += xv.y; v.z += xv.z; v.w += xv.w;
      *reinterpret_cast<float4*>(po + o) = v;
    }
  }
}

// ---------------------------------------------------------------------------
// Level-4 channel mixing -> delta. o split x4 for occupancy.
// grid (61, 4, 4): bx = xy tile of 8, by = s, bz = o tile of 16. Block 256.
// Thread: lane = xy (8), group g = t>>3: b = (g>>3)*4 + j, o = o0 + (g&7)*2 + k.
// ---------------------------------------------------------------------------
__global__ __launch_bounds__(256)
void mul2d_delta_kernel(const float* __restrict__ in,
                        const float* __restrict__ w1,
                        const float* __restrict__ w2,
                        const float* __restrict__ w3,
                        const float* __restrict__ w4,
                        float* __restrict__ outb) {
  const int s   = blockIdx.y;
  const int xy0 = blockIdx.x * 8;
  const int o0  = blockIdx.z * 16;
  const float* W = (s == 0) ? w1 : (s == 1) ? w2 : (s == 2) ? w3 : w4;
  const int t = threadIdx.x;
  const int lane = t & 7;            // xy
  const int g    = t >> 3;           // 0..31
  const int bq   = g >> 3;           // 0..3 -> b = bq*4 + j
  const int og   = g & 7;            // 0..7 -> o = o0 + og*2 + k
  const int xy   = xy0 + lane;

  __shared__ float Ws[16][16][9];    // [i-chunk][o-local][xy(pad)]
  __shared__ float As[16][16][9];    // [i-chunk][b][xy(pad)]

  float acc[4][2];
#pragma unroll
  for (int j = 0; j < 4; j++) { acc[j][0] = 0.f; acc[j][1] = 0.f; }

  for (int i0 = 0; i0 < 64; i0 += 16) {
    __syncthreads();
#pragma unroll
    for (int k = 0; k < 8; k++) {           // W chunk: 16i x 16o x 8xy
      int f = t + 256*k;
      int ii = f >> 7, o = (f >> 3) & 15, lx = f & 7;
      int xyl = xy0 + lx; xyl = xyl < 484 ? xyl : 483;
      Ws[ii][o][lx] = W[((i0 + ii)*64 + o0 + o)*484 + xyl];
    }
#pragma unroll
    for (int k = 0; k < 8; k++) {           // a chunk: 16i x 16b x 8xy
      int f = t + 256*k;
      int ii = f >> 7, b = (f >> 3) & 15, lx = f & 7;
      int xyl = xy0 + lx; xyl = xyl < 484 ? xyl : 483;
      As[ii][b][lx] = in[((b*64 + (i0 + ii))*4 + s)*484 + xyl];
    }
    __syncthreads();
#pragma unroll
    for (int ii = 0; ii < 16; ii++) {
      float wv0 = Ws[ii][og*2    ][lane];
      float wv1 = Ws[ii][og*2 + 1][lane];
      float av[4];
#pragma unroll
      for (int j = 0; j < 4; j++) av[j] = As[ii][bq*4 + j][lane];
#pragma unroll
      for (int j = 0; j < 4; j++) {
        acc[j][0] += av[j] * wv0;
        acc[j][1] += av[j] * wv1;
      }
    }
  }

  if (xy < 484) {
#pragma unroll
    for (int j = 0; j < 4; j++) {
      int b = bq*4 + j;
#pragma unroll
      for (int k = 0; k < 2; k++) {
        int o = o0 + og*2 + k;
        int idx = ((b*64 + o)*4 + s)*484 + xy;
        outb[idx] = acc[j][k] - in[idx];    // delta = mixed - original
      }
    }
  }
}

// ---------------------------------------------------------------------------
extern "C" void kernel_launch(void* const* d_in, const int* in_sizes, int n_in,
                              void* d_out, int out_size) {
  const float* x  = (const float*)d_in[0];
  const float* w1 = (const float*)d_in[1];
  const float* w2 = (const float*)d_in[2];
  const float* w3 = (const float*)d_in[3];
  const float* w4 = (const float*)d_in[4];
  float* out = (float*)d_out;

  float *ll1, *ll2, *l4, *d4, *r3;
  cudaGetSymbolAddress((void**)&ll1, g_ll1);
  cudaGetSymbolAddress((void**)&ll2, g_ll2);
  cudaGetSymbolAddress((void**)&l4,  g_l4);
  cudaGetSymbolAddress((void**)&d4,  g_d4);
  cudaGetSymbolAddress((void**)&r3,  g_r3);

  const dim3 blk(32, 8);

  // forward
  afb_ll1_kernel<<<dim3(5, 5, BCv), blk>>>(x, ll1);
  afb_ll_kernel<16,32><<<dim3(3, 5, BCv), blk>>>(ll1, 131*131, ll2, 131, 131, 69, 69);
  afb_fused34_kernel<<<BCv, blk>>>(ll2, l4);

  // level-4 mixing -> delta
  mul2d_delta_kernel<<<dim3(61, 4, 4), 256>>>(l4, w1, w2, w3, w4, d4);

  // inverse
  sfb_fused43_kernel<<<BCv, blk>>>(d4, r3);
  sfb_final2_kernel<<<dim3(8, BCv), blk>>>(r3, x, out);
}

// round 8
// speedup vs baseline: 3.0750x; 1.0159x over previous
#include <cuda_runtime.h>

// ---------------------------------------------------------------------------
// WaveConv2d via perfect-reconstruction shortcut:
//   out = x + IDWT(delta), delta nonzero only at level 4.
// R8: mul2d with 32-wide xy tiles (full-line coalescing), float4 stage-1 in
// the final synthesis kernel.
// ---------------------------------------------------------------------------

#define BCv 1024   // B*C

__constant__ float DLO[8] = {
  -0.010597401784997278f,  0.032883011666982945f,  0.030841381835986965f,
  -0.18703481171888114f,  -0.02798376941698385f,   0.6308807679295904f,
   0.7148465705525415f,    0.23037781330885523f };
__constant__ float DHI[8] = {
  -0.23037781330885523f,   0.7148465705525415f,   -0.6308807679295904f,
  -0.02798376941698385f,   0.18703481171888114f,   0.030841381835986965f,
  -0.032883011666982945f, -0.010597401784997278f };

// ---- scratch ----
__device__ float g_ll1[(size_t)BCv*131*131];
__device__ float g_ll2[(size_t)BCv*69*69];
__device__ float g_l4 [(size_t)BCv*4*22*22];
__device__ float g_d4 [(size_t)BCv*4*22*22];
__device__ float g_r3 [(size_t)BCv*69*69];

__device__ __forceinline__ int refl(int j, int N) {
  if (j < 0)  j = -1 - j;
  if (j >= N) j = 2*N - 1 - j;
  return j;
}

// ---------------------------------------------------------------------------
// Level-1 analysis (256x256 -> 131x131, LL only). 32x32 output tile.
// ---------------------------------------------------------------------------
__global__ __launch_bounds__(256)
void afb_ll1_kernel(const float* __restrict__ in, float* __restrict__ out) {
  constexpr int TOY = 32, TOX = 32;
  constexpr int RI = 2*TOY + 6;           // 70
  __shared__ float s_lo[RI][TOX];
  __shared__ float s_in[RI][2*TOX + 6];   // boundary path only

  const int bc  = blockIdx.z;
  const int ty0 = blockIdx.y * TOY;
  const int tx0 = blockIdx.x * TOX;
  const int tx = threadIdx.x, ty = threadIdx.y;
  const float* src = in + bc * 65536;

  const bool interior = (ty0 >= 3) && (2*ty0 + 2*TOY <= 256) &&
                        (tx0 >= 3) && (2*tx0 + 2*TOX <= 256);
  const int oh = min(TOY, 131 - ty0);
  const int rows = 2*oh + 6;

  if (interior) {
    const float2* base = reinterpret_cast<const float2*>(src + (2*ty0 - 6)*256 + (2*tx0 - 6));
    for (int r = ty; r < RI; r += 8) {
      const float2* p = base + r*128 + tx;
      float2 v0 = p[0], v1 = p[1], v2 = p[2], v3 = p[3];
      s_lo[r][tx] = v0.x*DLO[7] + v0.y*DLO[6] + v1.x*DLO[5] + v1.y*DLO[4]
                  + v2.x*DLO[3] + v2.y*DLO[2] + v3.x*DLO[1] + v3.y*DLO[0];
    }
  } else {
    const int ow = min(TOX, 131 - tx0);
    const int cols = 2*ow + 6;
    for (int r = ty; r < rows; r += 8) {
      int sr = refl(2*ty0 + r - 6, 256);
      const float* row = src + sr * 256;
      for (int c = tx; c < cols; c += 32)
        s_in[r][c] = row[refl(2*tx0 + c - 6, 256)];
    }
    __syncthreads();
    for (int r = ty; r < rows; r += 8) {
      if (tx < ow) {
        float acc = 0.f;
#pragma unroll
        for (int t = 0; t < 8; t++) acc += s_in[r][2*tx + t] * DLO[7 - t];
        s_lo[r][tx] = acc;
      }
    }
  }
  __syncthreads();

  float* dst = out + bc * 17161;
  const int gx = tx0 + tx;
#pragma unroll
  for (int k = 0; k < 4; k++) {
    int oyl = ty + 8*k;
    int oy = ty0 + oyl;
    if (oy < 131 && gx < 131) {
      float acc = 0.f;
#pragma unroll
      for (int t = 0; t < 8; t++) acc += s_lo[2*oyl + t][tx] * DLO[7 - t];
      dst[oy * 131 + gx] = acc;
    }
  }
}

// ---------------------------------------------------------------------------
// Generic LL-only analysis (level 2: 131 -> 69). Block (32,8).
// ---------------------------------------------------------------------------
template<int TOY, int TOX>
__global__ __launch_bounds__(256)
void afb_ll_kernel(const float* __restrict__ in, int inPS,
                   float* __restrict__ out,
                   int H, int W, int OH, int OW) {
  constexpr int RI = 2*TOY + 6;
  constexpr int CI = 2*TOX + 6;
  __shared__ float s_in[RI][CI];
  __shared__ float s_lo[RI][TOX];

  const int bc  = blockIdx.z;
  const int ty0 = blockIdx.y * TOY;
  const int tx0 = blockIdx.x * TOX;
  const int tx = threadIdx.x, ty = threadIdx.y;
  const float* src = in + bc * inPS;

  for (int r = ty; r < RI; r += 8) {
    int sr = refl(2*ty0 + r - 6, H);
    const float* row = src + sr * W;
    for (int c = tx; c < CI; c += 32)
      s_in[r][c] = row[refl(2*tx0 + c - 6, W)];
  }
  __syncthreads();

#pragma unroll
  for (int r = ty; r < RI; r += 8) {
    float acc = 0.f;
#pragma unroll
    for (int t = 0; t < 8; t++) acc += s_in[r][2*tx + t] * DLO[7 - t];
    s_lo[r][tx] = acc;
  }
  __syncthreads();

  float* dst = out + bc * OH * OW;
  const int gx = tx0 + tx;
#pragma unroll
  for (int oyl = ty; oyl < TOY; oyl += 8) {
    int oy = ty0 + oyl;
    if (oy < OH && gx < OW) {
      float acc = 0.f;
#pragma unroll
      for (int t = 0; t < 8; t++) acc += s_lo[2*oyl + t][tx] * DLO[7 - t];
      dst[oy * OW + gx] = acc;
    }
  }
}

// ---------------------------------------------------------------------------
// Fused forward levels 3+4: ll2 (BC,69,69) -> l4 (BC,4,22,22). Block/plane.
// ---------------------------------------------------------------------------
__global__ __launch_bounds__(256)
void afb_fused34_kernel(const float* __restrict__ in, float* __restrict__ out) {
  __shared__ float A[69*82];
  __shared__ float Bf[82*39];
  const int bc = blockIdx.x;
  const int tx = threadIdx.x, ty = threadIdx.y;
  const float* src = in + bc * 4761;

  for (int r = ty; r < 69; r += 8)
    for (int c = tx; c < 82; c += 32)
      A[r*82 + c] = src[r*69 + refl(c - 6, 69)];
  __syncthreads();

  for (int pr = ty; pr < 82; pr += 8) {
    int sr = refl(pr - 6, 69);
    const float* arow = &A[sr*82];
    for (int ox = tx; ox < 38; ox += 32) {
      float acc = 0.f;
#pragma unroll
      for (int t = 0; t < 8; t++) acc += arow[2*ox + t] * DLO[7 - t];
      Bf[pr*39 + ox] = acc;
    }
  }
  __syncthreads();

  for (int oy = ty; oy < 38; oy += 8)
    for (int ox = tx; ox < 38; ox += 32) {
      float acc = 0.f;
#pragma unroll
      for (int t = 0; t < 8; t++) acc += Bf[(2*oy + t)*39 + ox] * DLO[7 - t];
      A[oy*50 + 6 + ox] = acc;
    }
  __syncthreads();

  {
    int idx = ty*32 + tx;
    for (int f = idx; f < 38*12; f += 256) {
      int oy = f / 12, k = f - oy*12;
      int c = (k < 6) ? k : (k + 38);
      A[oy*50 + c] = A[oy*50 + 6 + refl(c - 6, 38)];
    }
  }
  __syncthreads();

  for (int pr = ty; pr < 50; pr += 8) {
    int sr = refl(pr - 6, 38);
    const float* arow = &A[sr*50];
    if (tx < 22) {
      float lo = 0.f, hi = 0.f;
#pragma unroll
      for (int t = 0; t < 8; t++) {
        float v = arow[2*tx + t];
        lo += v * DLO[7 - t];
        hi += v * DHI[7 - t];
      }
      Bf[pr*23 + tx] = lo;
      Bf[1150 + pr*23 + tx] = hi;
    }
  }
  __syncthreads();

  float* dst = out + bc * 1936;
  if (tx < 22) {
#pragma unroll
    for (int oy = ty; oy < 22; oy += 8) {
      float ll=0.f, lh=0.f, hl=0.f, hh=0.f;
#pragma unroll
      for (int t = 0; t < 8; t++) {
        float a = Bf[(2*oy + t)*23 + tx];
        float b = Bf[1150 + (2*oy + t)*23 + tx];
        float kl = DLO[7 - t], kh = DHI[7 - t];
        ll += a*kl;  lh += a*kh;  hl += b*kl;  hh += b*kh;
      }
      int o = oy*22 + tx;
      dst[o] = ll;  dst[484 + o] = lh;  dst[968 + o] = hl;  dst[1452 + o] = hh;
    }
  }
}

// ---------------------------------------------------------------------------
// Fused inverse levels 4+3: d4 (BC,4,22,22) -> r3 (BC,69,69). Block/plane.
// ---------------------------------------------------------------------------
__global__ __launch_bounds__(256)
void sfb_fused43_kernel(const float* __restrict__ d4, float* __restrict__ r3) {
  __shared__ float sd[4*484];
  __shared__ float slo[38*23];
  __shared__ float shi[38*23];
  __shared__ float sr4[38*39];
  __shared__ float slo2[69*39];
  const int bc = blockIdx.x;
  const int tx = threadIdx.x, ty = threadIdx.y;
  const int t = ty*32 + tx;
  const float* src = d4 + bc * 1936;

  for (int f = t; f < 1936; f += 256) sd[f] = src[f];
  __syncthreads();

  if (tx < 22) {
#pragma unroll
    for (int jy = ty; jy < 38; jy += 8) {
      int base = jy >> 1, u0 = 1 - (jy & 1);
      float lo = 0.f, hi = 0.f;
#pragma unroll
      for (int m = 0; m < 4; m++) {
        int off = (base + m)*22 + tx;
        float fl = DLO[u0 + 2*m], fh = DHI[u0 + 2*m];
        lo += fl*sd[off]       + fh*sd[484 + off];
        hi += fl*sd[968 + off] + fh*sd[1452 + off];
      }
      slo[jy*23 + tx] = lo;
      shi[jy*23 + tx] = hi;
    }
  }
  __syncthreads();

#pragma unroll
  for (int jy = ty; jy < 38; jy += 8)
    for (int jx = tx; jx < 38; jx += 32) {
      int t0 = 1 - (jx & 1), ib = jx >> 1;
      float acc = 0.f;
#pragma unroll
      for (int m = 0; m < 4; m++)
        acc += DLO[t0 + 2*m]*slo[jy*23 + ib + m] + DHI[t0 + 2*m]*shi[jy*23 + ib + m];
      sr4[jy*39 + jx] = acc;
    }
  __syncthreads();

  for (int jy2 = ty; jy2 < 69; jy2 += 8) {
    int base = jy2 >> 1, u0 = 1 - (jy2 & 1);
    float f0 = DLO[u0], f1 = DLO[u0+2], f2 = DLO[u0+4], f3 = DLO[u0+6];
    for (int i = tx; i < 38; i += 32)
      slo2[jy2*39 + i] = f0*sr4[base*39 + i]     + f1*sr4[(base+1)*39 + i]
                       + f2*sr4[(base+2)*39 + i] + f3*sr4[(base+3)*39 + i];
  }
  __syncthreads();

  float* dst = r3 + bc * 4761;
  for (int jy2 = ty; jy2 < 69; jy2 += 8)
    for (int jx = tx; jx < 69; jx += 32) {
      int t0 = 1 - (jx & 1), ib = jx >> 1;
      float acc = DLO[t0  ]*slo2[jy2*39 + ib    ]
                + DLO[t0+2]*slo2[jy2*39 + ib + 1]
                + DLO[t0+4]*slo2[jy2*39 + ib + 2]
                + DLO[t0+6]*slo2[jy2*39 + ib + 3];
      dst[jy2*69 + jx] = acc;
    }
}

// ---------------------------------------------------------------------------
// Fused inverse levels 2+1: r3 (BC,69,69) -> out = x + synth (BC,256,256).
// 32-row tiles: grid (8, BCv), block (32,8). Stage-1 uses float4 LDS/STS.
// ---------------------------------------------------------------------------
__global__ __launch_bounds__(256)
void sfb_final2_kernel(const float* __restrict__ r3,
                       const float* __restrict__ x,
                       float* __restrict__ out) {
  __shared__ float s_r3[13][69];
  __shared__ float s_t [19][69];
  __shared__ __align__(16) float s_ll[19][132];
  __shared__ __align__(16) float s_lo[32][132];

  const int bc  = blockIdx.y;
  const int jy0 = blockIdx.x * 32;     // 0..224
  const int q0  = jy0 >> 2;            // r3 row origin: 0..56
  const int tx = threadIdx.x, ty = threadIdx.y;
  const int t = ty*32 + tx;

  // stage A: r3 tile [13][69]
  const float* pr3 = r3 + bc * 4761 + q0 * 69;
  for (int f = t; f < 13*69; f += 256) {
    int r = f / 69, c = f - r*69;
    s_r3[r][c] = pr3[r*69 + c];
  }
  __syncthreads();

  // stage B: vertical L2-synthesis -> s_t[19][69]
  for (int f = t; f < 19*69; f += 256) {
    int rr = f / 69, c = f - rr*69;
    int rb = rr >> 1, u0 = 1 - (rr & 1);
    s_t[rr][c] = DLO[u0  ]*s_r3[rb  ][c] + DLO[u0+2]*s_r3[rb+1][c]
               + DLO[u0+4]*s_r3[rb+2][c] + DLO[u0+6]*s_r3[rb+3][c];
  }
  __syncthreads();

  // stage C: horizontal L2-synthesis -> s_ll[19][131]
  for (int f = t; f < 19*131; f += 256) {
    int rr = f / 131, cc = f - rr*131;
    int ib = cc >> 1, t0 = 1 - (cc & 1);
    s_ll[rr][cc] = DLO[t0  ]*s_t[rr][ib  ] + DLO[t0+2]*s_t[rr][ib+1]
                 + DLO[t0+4]*s_t[rr][ib+2] + DLO[t0+6]*s_t[rr][ib+3];
  }
  __syncthreads();

  // stage 1: vertical L1-synthesis, float4 (33 col-groups cover 132 cols;
  // col 131 is never consumed by stage 2 arithmetic).
#pragma unroll
  for (int jyl = ty; jyl < 32; jyl += 8) {
    int rb = jyl >> 1;
    int u0 = 1 - (jyl & 1);
    float f0 = DLO[u0], f1 = DLO[u0+2], f2 = DLO[u0+4], f3 = DLO[u0+6];
    const float4* r0 = reinterpret_cast<const float4*>(&s_ll[rb  ][0]);
    const float4* r1 = reinterpret_cast<const float4*>(&s_ll[rb+1][0]);
    const float4* r2 = reinterpret_cast<const float4*>(&s_ll[rb+2][0]);
    const float4* r3p = reinterpret_cast<const float4*>(&s_ll[rb+3][0]);
    float4* dst4 = reinterpret_cast<float4*>(&s_lo[jyl][0]);
#pragma unroll
    for (int c4 = tx; c4 < 33; c4 += 32) {
      float4 a = r0[c4], b = r1[c4], c = r2[c4], d = r3p[c4];
      float4 v;
      v.x = f0*a.x + f1*b.x + f2*c.x + f3*d.x;
      v.y = f0*a.y + f1*b.y + f2*c.y + f3*d.y;
      v.z = f0*a.z + f1*b.z + f2*c.z + f3*d.z;
      v.w = f0*a.w + f1*b.w + f2*c.w + f3*d.w;
      dst4[c4] = v;
    }
  }
  __syncthreads();

  // stage 2: horizontal L1-synthesis, float4 out with +x
  float* po = out + bc * 65536;
  const float* px = x + bc * 65536;
  const float k0 = DLO[0], k1 = DLO[1], k2 = DLO[2], k3 = DLO[3];
  const float k4 = DLO[4], k5 = DLO[5], k6 = DLO[6], k7 = DLO[7];
#pragma unroll
  for (int jyl = ty; jyl < 32; jyl += 8) {
    int jy = jy0 + jyl;
    const float2* sp = reinterpret_cast<const float2*>(&s_lo[jyl][0]);
#pragma unroll
    for (int k = 0; k < 2; k++) {
      float2 a = sp[32*k + tx], b = sp[32*k + tx + 1], c2 = sp[32*k + tx + 2];
      float4 v;
      v.x = k1*a.x + k3*a.y + k5*b.x + k7*b.y;
      v.y = k0*a.x + k2*a.y + k4*b.x + k6*b.y;
      v.z = k1*a.y + k3*b.x + k5*b.y + k7*c2.x;
      v.w = k0*a.y + k2*b.x + k4*b.y + k6*c2.x;
      int o = jy * 256 + 128*k + 4*tx;
      float4 xv = *reinterpret_cast<const float4*>(px + o);
      v.x += xv.x; v.y += xv.y; v.z += xv.z; v.w += xv.w;
      *reinterpret_cast<float4*>(po + o) = v;
    }
  }
}

// ---------------------------------------------------------------------------
// Level-4 channel mixing -> delta. 32-wide xy tiles, o-split 8.
// grid (16, 4, 8): bx = xy tile of 32, by = s, bz = o tile of 8. Block 256.
// Thread: lane = xy (32), g = t>>5 (0..7) -> b pair {2g, 2g+1}; all 8 o's.
// ---------------------------------------------------------------------------
__global__ __launch_bounds__(256)
void mul2d_delta_kernel(const float* __restrict__ in,
                        const float* __restrict__ w1,
                        const float* __restrict__ w2,
                        const float* __restrict__ w3,
                        const float* __restrict__ w4,
                        float* __restrict__ outb) {
  const int s   = blockIdx.y;
  const int xy0 = blockIdx.x * 32;
  const int o0  = blockIdx.z * 8;
  const float* W = (s == 0) ? w1 : (s == 1) ? w2 : (s == 2) ? w3 : w4;
  const int t = threadIdx.x;
  const int lane = t & 31;           // xy
  const int g    = t >> 5;           // 0..7 -> b = 2g, 2g+1
  const int xy   = xy0 + lane;
  const bool ok  = xy < 484;

  __shared__ float Ws[8][8][32];     // [i-chunk][o-local][xy]
  __shared__ float As[8][16][32];    // [i-chunk][b][xy]

  float acc[2][8];
#pragma unroll
  for (int j = 0; j < 2; j++)
#pragma unroll
    for (int k = 0; k < 8; k++) acc[j][k] = 0.f;

  const int xyl = ok ? xy : 483;

  for (int i0 = 0; i0 < 64; i0 += 8) {
    __syncthreads();
    // W chunk: 8i x 8o x 32xy = 2048 -> 8 per thread
#pragma unroll
    for (int k = 0; k < 2; k++) {
      int f = t + 256*k;            // f = ii*64 + oo*... layout: [ii][o][lane]
      int ii = f >> 8, rem = f & 255;
      int o = rem >> 5, lx = rem & 31;
      // need 8 ii values: loop k covers 512 of 2048... fix: iterate 8 times
      (void)ii; (void)o; (void)lx;
    }
    // simple strided fill (8 iters)
#pragma unroll
    for (int f = t; f < 8*8*32; f += 256) {
      int ii = f >> 8;
      int o  = (f >> 5) & 7;
      int lx = f & 31;
      int xg = xy0 + lx; xg = xg < 484 ? xg : 483;
      Ws[ii][o][lx] = W[((i0 + ii)*64 + o0 + o)*484 + xg];
    }
    // a chunk: 8i x 16b x 32xy = 4096 -> 16 per thread
#pragma unroll
    for (int f = t; f < 8*16*32; f += 256) {
      int ii = f >> 9;
      int b  = (f >> 5) & 15;
      int lx = f & 31;
      int xg = xy0 + lx; xg = xg < 484 ? xg : 483;
      As[ii][b][lx] = in[((b*64 + (i0 + ii))*4 + s)*484 + xg];
    }
    __syncthreads();
#pragma unroll
    for (int ii = 0; ii < 8; ii++) {
      float av0 = As[ii][2*g    ][lane];
      float av1 = As[ii][2*g + 1][lane];
#pragma unroll
      for (int k = 0; k < 8; k++) {
        float wv = Ws[ii][k][lane];
        acc[0][k] += av0 * wv;
        acc[1][k] += av1 * wv;
      }
    }
  }

  if (ok) {
#pragma unroll
    for (int j = 0; j < 2; j++) {
      int b = 2*g + j;
#pragma unroll
      for (int k = 0; k < 8; k++) {
        int o = o0 + k;
        int idx = ((b*64 + o)*4 + s)*484 + xy;
        outb[idx] = acc[j][k] - in[idx];    // delta = mixed - original
      }
    }
  }
  (void)xyl;
}

// ---------------------------------------------------------------------------
extern "C" void kernel_launch(void* const* d_in, const int* in_sizes, int n_in,
                              void* d_out, int out_size) {
  const float* x  = (const float*)d_in[0];
  const float* w1 = (const float*)d_in[1];
  const float* w2 = (const float*)d_in[2];
  const float* w3 = (const float*)d_in[3];
  const float* w4 = (const float*)d_in[4];
  float* out = (float*)d_out;

  float *ll1, *ll2, *l4, *d4, *r3;
  cudaGetSymbolAddress((void**)&ll1, g_ll1);
  cudaGetSymbolAddress((void**)&ll2, g_ll2);
  cudaGetSymbolAddress((void**)&l4,  g_l4);
  cudaGetSymbolAddress((void**)&d4,  g_d4);
  cudaGetSymbolAddress((void**)&r3,  g_r3);

  const dim3 blk(32, 8);

  // forward
  afb_ll1_kernel<<<dim3(5, 5, BCv), blk>>>(x, ll1);
  afb_ll_kernel<16,32><<<dim3(3, 5, BCv), blk>>>(ll1, 131*131, ll2, 131, 131, 69, 69);
  afb_fused34_kernel<<<BCv, blk>>>(ll2, l4);

  // level-4 mixing -> delta
  mul2d_delta_kernel<<<dim3(16, 4, 8), 256>>>(l4, w1, w2, w3, w4, d4);

  // inverse
  sfb_fused43_kernel<<<BCv, blk>>>(d4, r3);
  sfb_final2_kernel<<<dim3(8, BCv), blk>>>(r3, x, out);
}

// round 9
// speedup vs baseline: 3.2334x; 1.0515x over previous
#include <cuda_runtime.h>

// ---------------------------------------------------------------------------
// WaveConv2d via perfect-reconstruction shortcut:
//   out = x + IDWT(delta), delta nonzero only at level 4.
// R9: vectorized-smem mul2d, paired row-pass in afb_ll1, vector stages in
// sfb_final2 (r3 padded to row stride 72).
// ---------------------------------------------------------------------------

#define BCv 1024   // B*C

__constant__ float DLO[8] = {
  -0.010597401784997278f,  0.032883011666982945f,  0.030841381835986965f,
  -0.18703481171888114f,  -0.02798376941698385f,   0.6308807679295904f,
   0.7148465705525415f,    0.23037781330885523f };
__constant__ float DHI[8] = {
  -0.23037781330885523f,   0.7148465705525415f,   -0.6308807679295904f,
  -0.02798376941698385f,   0.18703481171888114f,   0.030841381835986965f,
  -0.032883011666982945f, -0.010597401784997278f };

// ---- scratch ----
__device__ float g_ll1[(size_t)BCv*131*131];
__device__ float g_ll2[(size_t)BCv*69*69];
__device__ float g_l4 [(size_t)BCv*4*22*22];
__device__ float g_d4 [(size_t)BCv*4*22*22];
__device__ float g_r3 [(size_t)BCv*69*72];   // rows padded to 72

__device__ __forceinline__ int refl(int j, int N) {
  if (j < 0)  j = -1 - j;
  if (j >= N) j = 2*N - 1 - j;
  return j;
}

// ---------------------------------------------------------------------------
// Level-1 analysis (256x256 -> 131x131, LL only). 32x32 output tile.
// Interior row pass: 2 outputs per task from 5 float2 loads.
// ---------------------------------------------------------------------------
__global__ __launch_bounds__(256)
void afb_ll1_kernel(const float* __restrict__ in, float* __restrict__ out) {
  constexpr int TOY = 32, TOX = 32;
  constexpr int RI = 2*TOY + 6;           // 70
  __shared__ __align__(16) float s_lo[RI][TOX];
  __shared__ float s_in[RI][2*TOX + 6];   // boundary path only

  const int bc  = blockIdx.z;
  const int ty0 = blockIdx.y * TOY;
  const int tx0 = blockIdx.x * TOX;
  const int tx = threadIdx.x, ty = threadIdx.y;
  const int t  = ty*32 + tx;
  const float* src = in + bc * 65536;

  const bool interior = (ty0 >= 3) && (2*ty0 + 2*TOY <= 256) &&
                        (tx0 >= 3) && (2*tx0 + 2*TOX <= 256);
  const int oh = min(TOY, 131 - ty0);
  const int rows = 2*oh + 6;

  if (interior) {
    const float2* base2 = reinterpret_cast<const float2*>(src + (2*ty0 - 6)*256 + (2*tx0 - 6));
#pragma unroll
    for (int f = t; f < 70*16; f += 256) {
      int r = f >> 4, pr = f & 15;
      const float2* p = base2 + r*128 + 2*pr;
      float2 v0 = p[0], v1 = p[1], v2 = p[2], v3 = p[3], v4 = p[4];
      float lo0 = v0.x*DLO[7] + v0.y*DLO[6] + v1.x*DLO[5] + v1.y*DLO[4]
                + v2.x*DLO[3] + v2.y*DLO[2] + v3.x*DLO[1] + v3.y*DLO[0];
      float lo1 = v1.x*DLO[7] + v1.y*DLO[6] + v2.x*DLO[5] + v2.y*DLO[4]
                + v3.x*DLO[3] + v3.y*DLO[2] + v4.x*DLO[1] + v4.y*DLO[0];
      float2 o2; o2.x = lo0; o2.y = lo1;
      *reinterpret_cast<float2*>(&s_lo[r][2*pr]) = o2;
    }
  } else {
    const int ow = min(TOX, 131 - tx0);
    const int cols = 2*ow + 6;
    for (int r = ty; r < rows; r += 8) {
      int sr = refl(2*ty0 + r - 6, 256);
      const float* row = src + sr * 256;
      for (int c = tx; c < cols; c += 32)
        s_in[r][c] = row[refl(2*tx0 + c - 6, 256)];
    }
    __syncthreads();
    for (int r = ty; r < rows; r += 8) {
      if (tx < ow) {
        float acc = 0.f;
#pragma unroll
        for (int tt = 0; tt < 8; tt++) acc += s_in[r][2*tx + tt] * DLO[7 - tt];
        s_lo[r][tx] = acc;
      }
    }
  }
  __syncthreads();

  float* dst = out + bc * 17161;
  const int gx = tx0 + tx;
#pragma unroll
  for (int k = 0; k < 4; k++) {
    int oyl = ty + 8*k;
    int oy = ty0 + oyl;
    if (oy < 131 && gx < 131) {
      float acc = 0.f;
#pragma unroll
      for (int tt = 0; tt < 8; tt++) acc += s_lo[2*oyl + tt][tx] * DLO[7 - tt];
      dst[oy * 131 + gx] = acc;
    }
  }
}

// ---------------------------------------------------------------------------
// Generic LL-only analysis (level 2: 131 -> 69). Block (32,8).
// ---------------------------------------------------------------------------
template<int TOY, int TOX>
__global__ __launch_bounds__(256)
void afb_ll_kernel(const float* __restrict__ in, int inPS,
                   float* __restrict__ out,
                   int H, int W, int OH, int OW) {
  constexpr int RI = 2*TOY + 6;
  constexpr int CI = 2*TOX + 6;
  __shared__ float s_in[RI][CI];
  __shared__ float s_lo[RI][TOX];

  const int bc  = blockIdx.z;
  const int ty0 = blockIdx.y * TOY;
  const int tx0 = blockIdx.x * TOX;
  const int tx = threadIdx.x, ty = threadIdx.y;
  const float* src = in + bc * inPS;

  for (int r = ty; r < RI; r += 8) {
    int sr = refl(2*ty0 + r - 6, H);
    const float* row = src + sr * W;
    for (int c = tx; c < CI; c += 32)
      s_in[r][c] = row[refl(2*tx0 + c - 6, W)];
  }
  __syncthreads();

#pragma unroll
  for (int r = ty; r < RI; r += 8) {
    float acc = 0.f;
#pragma unroll
    for (int t = 0; t < 8; t++) acc += s_in[r][2*tx + t] * DLO[7 - t];
    s_lo[r][tx] = acc;
  }
  __syncthreads();

  float* dst = out + bc * OH * OW;
  const int gx = tx0 + tx;
#pragma unroll
  for (int oyl = ty; oyl < TOY; oyl += 8) {
    int oy = ty0 + oyl;
    if (oy < OH && gx < OW) {
      float acc = 0.f;
#pragma unroll
      for (int t = 0; t < 8; t++) acc += s_lo[2*oyl + t][tx] * DLO[7 - t];
      dst[oy * OW + gx] = acc;
    }
  }
}

// ---------------------------------------------------------------------------
// Fused forward levels 3+4: ll2 (BC,69,69) -> l4 (BC,4,22,22). Block/plane.
// ---------------------------------------------------------------------------
__global__ __launch_bounds__(256)
void afb_fused34_kernel(const float* __restrict__ in, float* __restrict__ out) {
  __shared__ float A[69*82];
  __shared__ float Bf[82*39];
  const int bc = blockIdx.x;
  const int tx = threadIdx.x, ty = threadIdx.y;
  const float* src = in + bc * 4761;

  for (int r = ty; r < 69; r += 8)
    for (int c = tx; c < 82; c += 32)
      A[r*82 + c] = src[r*69 + refl(c - 6, 69)];
  __syncthreads();

  for (int pr = ty; pr < 82; pr += 8) {
    int sr = refl(pr - 6, 69);
    const float* arow = &A[sr*82];
    for (int ox = tx; ox < 38; ox += 32) {
      float acc = 0.f;
#pragma unroll
      for (int t = 0; t < 8; t++) acc += arow[2*ox + t] * DLO[7 - t];
      Bf[pr*39 + ox] = acc;
    }
  }
  __syncthreads();

  for (int oy = ty; oy < 38; oy += 8)
    for (int ox = tx; ox < 38; ox += 32) {
      float acc = 0.f;
#pragma unroll
      for (int t = 0; t < 8; t++) acc += Bf[(2*oy + t)*39 + ox] * DLO[7 - t];
      A[oy*50 + 6 + ox] = acc;
    }
  __syncthreads();

  {
    int idx = ty*32 + tx;
    for (int f = idx; f < 38*12; f += 256) {
      int oy = f / 12, k = f - oy*12;
      int c = (k < 6) ? k : (k + 38);
      A[oy*50 + c] = A[oy*50 + 6 + refl(c - 6, 38)];
    }
  }
  __syncthreads();

  for (int pr = ty; pr < 50; pr += 8) {
    int sr = refl(pr - 6, 38);
    const float* arow = &A[sr*50];
    if (tx < 22) {
      float lo = 0.f, hi = 0.f;
#pragma unroll
      for (int t = 0; t < 8; t++) {
        float v = arow[2*tx + t];
        lo += v * DLO[7 - t];
        hi += v * DHI[7 - t];
      }
      Bf[pr*23 + tx] = lo;
      Bf[1150 + pr*23 + tx] = hi;
    }
  }
  __syncthreads();

  float* dst = out + bc * 1936;
  if (tx < 22) {
#pragma unroll
    for (int oy = ty; oy < 22; oy += 8) {
      float ll=0.f, lh=0.f, hl=0.f, hh=0.f;
#pragma unroll
      for (int t = 0; t < 8; t++) {
        float a = Bf[(2*oy + t)*23 + tx];
        float b = Bf[1150 + (2*oy + t)*23 + tx];
        float kl = DLO[7 - t], kh = DHI[7 - t];
        ll += a*kl;  lh += a*kh;  hl += b*kl;  hh += b*kh;
      }
      int o = oy*22 + tx;
      dst[o] = ll;  dst[484 + o] = lh;  dst[968 + o] = hl;  dst[1452 + o] = hh;
    }
  }
}

// ---------------------------------------------------------------------------
// Fused inverse levels 4+3: d4 (BC,4,22,22) -> r3 (BC,69,72 padded).
// ---------------------------------------------------------------------------
__global__ __launch_bounds__(256)
void sfb_fused43_kernel(const float* __restrict__ d4, float* __restrict__ r3) {
  __shared__ float sd[4*484];
  __shared__ float slo[38*23];
  __shared__ float shi[38*23];
  __shared__ float sr4[38*39];
  __shared__ float slo2[69*39];
  const int bc = blockIdx.x;
  const int tx = threadIdx.x, ty = threadIdx.y;
  const int t = ty*32 + tx;
  const float* src = d4 + bc * 1936;

  for (int f = t; f < 1936; f += 256) sd[f] = src[f];
  __syncthreads();

  if (tx < 22) {
#pragma unroll
    for (int jy = ty; jy < 38; jy += 8) {
      int base = jy >> 1, u0 = 1 - (jy & 1);
      float lo = 0.f, hi = 0.f;
#pragma unroll
      for (int m = 0; m < 4; m++) {
        int off = (base + m)*22 + tx;
        float fl = DLO[u0 + 2*m], fh = DHI[u0 + 2*m];
        lo += fl*sd[off]       + fh*sd[484 + off];
        hi += fl*sd[968 + off] + fh*sd[1452 + off];
      }
      slo[jy*23 + tx] = lo;
      shi[jy*23 + tx] = hi;
    }
  }
  __syncthreads();

#pragma unroll
  for (int jy = ty; jy < 38; jy += 8)
    for (int jx = tx; jx < 38; jx += 32) {
      int t0 = 1 - (jx & 1), ib = jx >> 1;
      float acc = 0.f;
#pragma unroll
      for (int m = 0; m < 4; m++)
        acc += DLO[t0 + 2*m]*slo[jy*23 + ib + m] + DHI[t0 + 2*m]*shi[jy*23 + ib + m];
      sr4[jy*39 + jx] = acc;
    }
  __syncthreads();

  for (int jy2 = ty; jy2 < 69; jy2 += 8) {
    int base = jy2 >> 1, u0 = 1 - (jy2 & 1);
    float f0 = DLO[u0], f1 = DLO[u0+2], f2 = DLO[u0+4], f3 = DLO[u0+6];
    for (int i = tx; i < 38; i += 32)
      slo2[jy2*39 + i] = f0*sr4[base*39 + i]     + f1*sr4[(base+1)*39 + i]
                       + f2*sr4[(base+2)*39 + i] + f3*sr4[(base+3)*39 + i];
  }
  __syncthreads();

  float* dst = r3 + bc * 4968;           // padded plane 69*72
  for (int jy2 = ty; jy2 < 69; jy2 += 8)
    for (int jx = tx; jx < 69; jx += 32) {
      int t0 = 1 - (jx & 1), ib = jx >> 1;
      float acc = DLO[t0  ]*slo2[jy2*39 + ib    ]
                + DLO[t0+2]*slo2[jy2*39 + ib + 1]
                + DLO[t0+4]*slo2[jy2*39 + ib + 2]
                + DLO[t0+6]*slo2[jy2*39 + ib + 3];
      dst[jy2*72 + jx] = acc;
    }
}

// ---------------------------------------------------------------------------
// Fused inverse levels 2+1: r3 (BC,69,72) -> out = x + synth (BC,256,256).
// 32-row tiles: grid (8, BCv), block (32,8). Vectorized stages.
// ---------------------------------------------------------------------------
__global__ __launch_bounds__(256)
void sfb_final2_kernel(const float* __restrict__ r3,
                       const float* __restrict__ x,
                       float* __restrict__ out) {
  __shared__ __align__(16) float s_r3[13][72];
  __shared__ __align__(16) float s_t [19][72];
  __shared__ __align__(16) float s_ll[19][132];
  __shared__ __align__(16) float s_lo[32][132];

  const int bc  = blockIdx.y;
  const int jy0 = blockIdx.x * 32;     // 0..224
  const int q0  = jy0 >> 2;            // r3 row origin: 0..56
  const int tx = threadIdx.x, ty = threadIdx.y;
  const int t = ty*32 + tx;

  const float k0 = DLO[0], k1 = DLO[1], k2 = DLO[2], k3 = DLO[3];
  const float k4 = DLO[4], k5 = DLO[5], k6 = DLO[6], k7 = DLO[7];

  // stage A: r3 tile [13][72] via float4 (18 groups/row)
  {
    const float4* g4 = reinterpret_cast<const float4*>(r3 + bc * 4968 + q0 * 72);
    for (int f = t; f < 13*18; f += 256) {
      int r = f / 18, c4 = f - r*18;
      reinterpret_cast<float4*>(&s_r3[r][0])[c4] = g4[r*18 + c4];
    }
  }
  __syncthreads();

  // stage B: vertical L2-synthesis (float4) -> s_t[19][72]
  for (int f = t; f < 19*18; f += 256) {
    int rr = f / 18, c4 = f - rr*18;
    int rb = rr >> 1, u0 = 1 - (rr & 1);
    float f0 = DLO[u0], f1 = DLO[u0+2], f2 = DLO[u0+4], f3 = DLO[u0+6];
    float4 a = reinterpret_cast<const float4*>(&s_r3[rb  ][0])[c4];
    float4 b = reinterpret_cast<const float4*>(&s_r3[rb+1][0])[c4];
    float4 c = reinterpret_cast<const float4*>(&s_r3[rb+2][0])[c4];
    float4 d = reinterpret_cast<const float4*>(&s_r3[rb+3][0])[c4];
    float4 v;
    v.x = f0*a.x + f1*b.x + f2*c.x + f3*d.x;
    v.y = f0*a.y + f1*b.y + f2*c.y + f3*d.y;
    v.z = f0*a.z + f1*b.z + f2*c.z + f3*d.z;
    v.w = f0*a.w + f1*b.w + f2*c.w + f3*d.w;
    reinterpret_cast<float4*>(&s_t[rr][0])[c4] = v;
  }
  __syncthreads();

  // stage C: horizontal L2-synthesis, even/odd pairs share the 4-tap window
  for (int f = t; f < 19*66; f += 256) {
    int rr = f / 66, q = f - rr*66;
    float a = s_t[rr][q], b = s_t[rr][q+1], c = s_t[rr][q+2], d = s_t[rr][q+3];
    float2 v;
    v.x = k1*a + k3*b + k5*c + k7*d;   // even col 2q
    v.y = k0*a + k2*b + k4*c + k6*d;   // odd col 2q+1
    *reinterpret_cast<float2*>(&s_ll[rr][2*q]) = v;
  }
  __syncthreads();

  // stage 1: vertical L1-synthesis, float4 (33 groups; col 131 garbage unused)
#pragma unroll
  for (int jyl = ty; jyl < 32; jyl += 8) {
    int rb = jyl >> 1;
    int u0 = 1 - (jyl & 1);
    float f0 = DLO[u0], f1 = DLO[u0+2], f2 = DLO[u0+4], f3 = DLO[u0+6];
    const float4* r0 = reinterpret_cast<const float4*>(&s_ll[rb  ][0]);
    const float4* r1 = reinterpret_cast<const float4*>(&s_ll[rb+1][0]);
    const float4* r2 = reinterpret_cast<const float4*>(&s_ll[rb+2][0]);
    const float4* r3p = reinterpret_cast<const float4*>(&s_ll[rb+3][0]);
    float4* dst4 = reinterpret_cast<float4*>(&s_lo[jyl][0]);
#pragma unroll
    for (int c4 = tx; c4 < 33; c4 += 32) {
      float4 a = r0[c4], b = r1[c4], c = r2[c4], d = r3p[c4];
      float4 v;
      v.x = f0*a.x + f1*b.x + f2*c.x + f3*d.x;
      v.y = f0*a.y + f1*b.y + f2*c.y + f3*d.y;
      v.z = f0*a.z + f1*b.z + f2*c.z + f3*d.z;
      v.w = f0*a.w + f1*b.w + f2*c.w + f3*d.w;
      dst4[c4] = v;
    }
  }
  __syncthreads();

  // stage 2: horizontal L1-synthesis, float4 out with +x
  float* po = out + bc * 65536;
  const float* px = x + bc * 65536;
#pragma unroll
  for (int jyl = ty; jyl < 32; jyl += 8) {
    int jy = jy0 + jyl;
    const float2* sp = reinterpret_cast<const float2*>(&s_lo[jyl][0]);
#pragma unroll
    for (int k = 0; k < 2; k++) {
      float2 a = sp[32*k + tx], b = sp[32*k + tx + 1], c2 = sp[32*k + tx + 2];
      float4 v;
      v.x = k1*a.x + k3*a.y + k5*b.x + k7*b.y;
      v.y = k0*a.x + k2*a.y + k4*b.x + k6*b.y;
      v.z = k1*a.y + k3*b.x + k5*b.y + k7*c2.x;
      v.w = k0*a.y + k2*b.x + k4*b.y + k6*c2.x;
      int o = jy * 256 + 128*k + 4*tx;
      float4 xv = *reinterpret_cast<const float4*>(px + o);
      v.x += xv.x; v.y += xv.y; v.z += xv.z; v.w += xv.w;
      *reinterpret_cast<float4*>(po + o) = v;
    }
  }
}

// ---------------------------------------------------------------------------
// Level-4 channel mixing -> delta. Vectorized smem tiles.
// grid (16, 4, 8): bx = xy tile of 32, by = s, bz = o tile of 8. Block 256.
// Thread: lane = xy (32), g = t>>5 (0..7) -> b pair {2g,2g+1}, 8 o's.
// Inner loop per i: 1 LDS.64 + 2 LDS.128 + 16 FMA.
// ---------------------------------------------------------------------------
__global__ __launch_bounds__(256)
void mul2d_delta_kernel(const float* __restrict__ in,
                        const float* __restrict__ w1,
                        const float* __restrict__ w2,
                        const float* __restrict__ w3,
                        const float* __restrict__ w4,
                        float* __restrict__ outb) {
  const int s   = blockIdx.y;
  const int xy0 = blockIdx.x * 32;
  const int o0  = blockIdx.z * 8;
  const float* W = (s == 0) ? w1 : (s == 1) ? w2 : (s == 2) ? w3 : w4;
  const int t = threadIdx.x;
  const int lane = t & 31;           // xy
  const int g    = t >> 5;           // 0..7
  const int xy   = xy0 + lane;
  const bool ok  = xy < 484;

  __shared__ __align__(16) float Ws[8][32][12];  // [i][lane][o(8)+pad]
  __shared__ __align__(16) float As[8][32][18];  // [i][lane][b(16)+pad]

  float acc[2][8];
#pragma unroll
  for (int j = 0; j < 2; j++)
#pragma unroll
    for (int k = 0; k < 8; k++) acc[j][k] = 0.f;

  for (int i0 = 0; i0 < 64; i0 += 8) {
    __syncthreads();
    // W chunk: 8i x 8o x 32xy, stored transposed [i][lane][o]
#pragma unroll
    for (int f = t; f < 8*8*32; f += 256) {
      int lx = f & 31;
      int k  = (f >> 5) & 7;
      int ii = f >> 8;
      int xg = xy0 + lx; xg = xg < 484 ? xg : 483;
      Ws[ii][lx][k] = W[((i0 + ii)*64 + o0 + k)*484 + xg];
    }
    // a chunk: 8i x 16b x 32xy, stored transposed [i][lane][b]
#pragma unroll
    for (int f = t; f < 8*16*32; f += 256) {
      int lx = f & 31;
      int b  = (f >> 5) & 15;
      int ii = f >> 9;
      int xg = xy0 + lx; xg = xg < 484 ? xg : 483;
      As[ii][lx][b] = in[((b*64 + (i0 + ii))*4 + s)*484 + xg];
    }
    __syncthreads();
#pragma unroll
    for (int ii = 0; ii < 8; ii++) {
      float2 av = *reinterpret_cast<const float2*>(&As[ii][lane][2*g]);
      float4 w0 = *reinterpret_cast<const float4*>(&Ws[ii][lane][0]);
      float4 w1v = *reinterpret_cast<const float4*>(&Ws[ii][lane][4]);
      acc[0][0] += av.x*w0.x;  acc[0][1] += av.x*w0.y;
      acc[0][2] += av.x*w0.z;  acc[0][3] += av.x*w0.w;
      acc[0][4] += av.x*w1v.x; acc[0][5] += av.x*w1v.y;
      acc[0][6] += av.x*w1v.z; acc[0][7] += av.x*w1v.w;
      acc[1][0] += av.y*w0.x;  acc[1][1] += av.y*w0.y;
      acc[1][2] += av.y*w0.z;  acc[1][3] += av.y*w0.w;
      acc[1][4] += av.y*w1v.x; acc[1][5] += av.y*w1v.y;
      acc[1][6] += av.y*w1v.z; acc[1][7] += av.y*w1v.w;
    }
  }

  if (ok) {
#pragma unroll
    for (int j = 0; j < 2; j++) {
      int b = 2*g + j;
#pragma unroll
      for (int k = 0; k < 8; k++) {
        int o = o0 + k;
        int idx = ((b*64 + o)*4 + s)*484 + xy;
        outb[idx] = acc[j][k] - in[idx];    // delta = mixed - original
      }
    }
  }
}

// ---------------------------------------------------------------------------
extern "C" void kernel_launch(void* const* d_in, const int* in_sizes, int n_in,
                              void* d_out, int out_size) {
  const float* x  = (const float*)d_in[0];
  const float* w1 = (const float*)d_in[1];
  const float* w2 = (const float*)d_in[2];
  const float* w3 = (const float*)d_in[3];
  const float* w4 = (const float*)d_in[4];
  float* out = (float*)d_out;

  float *ll1, *ll2, *l4, *d4, *r3;
  cudaGetSymbolAddress((void**)&ll1, g_ll1);
  cudaGetSymbolAddress((void**)&ll2, g_ll2);
  cudaGetSymbolAddress((void**)&l4,  g_l4);
  cudaGetSymbolAddress((void**)&d4,  g_d4);
  cudaGetSymbolAddress((void**)&r3,  g_r3);

  const dim3 blk(32, 8);

  // forward
  afb_ll1_kernel<<<dim3(5, 5, BCv), blk>>>(x, ll1);
  afb_ll_kernel<16,32><<<dim3(3, 5, BCv), blk>>>(ll1, 131*131, ll2, 131, 131, 69, 69);
  afb_fused34_kernel<<<BCv, blk>>>(ll2, l4);

  // level-4 mixing -> delta
  mul2d_delta_kernel<<<dim3(16, 4, 8), 256>>>(l4, w1, w2, w3, w4, d4);

  // inverse
  sfb_fused43_kernel<<<BCv, blk>>>(d4, r3);
  sfb_final2_kernel<<<dim3(8, BCv), blk>>>(r3, x, out);
}

// round 10
// speedup vs baseline: 3.2574x; 1.0074x over previous
#include <cuda_runtime.h>

// ---------------------------------------------------------------------------
// WaveConv2d via perfect-reconstruction shortcut:
//   out = x + IDWT(delta), delta nonzero only at level 4.
// R10: sliding-window column passes (afb_ll1/afb_ll), paired-row vertical
// synthesis in sfb_final2.
// ---------------------------------------------------------------------------

#define BCv 1024   // B*C

__constant__ float DLO[8] = {
  -0.010597401784997278f,  0.032883011666982945f,  0.030841381835986965f,
  -0.18703481171888114f,  -0.02798376941698385f,   0.6308807679295904f,
   0.7148465705525415f,    0.23037781330885523f };
__constant__ float DHI[8] = {
  -0.23037781330885523f,   0.7148465705525415f,   -0.6308807679295904f,
  -0.02798376941698385f,   0.18703481171888114f,   0.030841381835986965f,
  -0.032883011666982945f, -0.010597401784997278f };

// ---- scratch ----
__device__ float g_ll1[(size_t)BCv*131*131];
__device__ float g_ll2[(size_t)BCv*69*69];
__device__ float g_l4 [(size_t)BCv*4*22*22];
__device__ float g_d4 [(size_t)BCv*4*22*22];
__device__ float g_r3 [(size_t)BCv*69*72];   // rows padded to 72

__device__ __forceinline__ int refl(int j, int N) {
  if (j < 0)  j = -1 - j;
  if (j >= N) j = 2*N - 1 - j;
  return j;
}

// ---------------------------------------------------------------------------
// Level-1 analysis (256x256 -> 131x131, LL only). 32x32 output tile.
// ---------------------------------------------------------------------------
__global__ __launch_bounds__(256)
void afb_ll1_kernel(const float* __restrict__ in, float* __restrict__ out) {
  constexpr int TOY = 32, TOX = 32;
  constexpr int RI = 2*TOY + 6;           // 70
  __shared__ __align__(16) float s_lo[RI][TOX];
  __shared__ float s_in[RI][2*TOX + 6];   // boundary path only

  const int bc  = blockIdx.z;
  const int ty0 = blockIdx.y * TOY;
  const int tx0 = blockIdx.x * TOX;
  const int tx = threadIdx.x, ty = threadIdx.y;
  const int t  = ty*32 + tx;
  const float* src = in + bc * 65536;

  const bool interior = (ty0 >= 3) && (2*ty0 + 2*TOY <= 256) &&
                        (tx0 >= 3) && (2*tx0 + 2*TOX <= 256);
  const int oh = min(TOY, 131 - ty0);
  const int rows = 2*oh + 6;

  if (interior) {
    const float2* base2 = reinterpret_cast<const float2*>(src + (2*ty0 - 6)*256 + (2*tx0 - 6));
#pragma unroll
    for (int f = t; f < 70*16; f += 256) {
      int r = f >> 4, pr = f & 15;
      const float2* p = base2 + r*128 + 2*pr;
      float2 v0 = p[0], v1 = p[1], v2 = p[2], v3 = p[3], v4 = p[4];
      float lo0 = v0.x*DLO[7] + v0.y*DLO[6] + v1.x*DLO[5] + v1.y*DLO[4]
                + v2.x*DLO[3] + v2.y*DLO[2] + v3.x*DLO[1] + v3.y*DLO[0];
      float lo1 = v1.x*DLO[7] + v1.y*DLO[6] + v2.x*DLO[5] + v2.y*DLO[4]
                + v3.x*DLO[3] + v3.y*DLO[2] + v4.x*DLO[1] + v4.y*DLO[0];
      float2 o2; o2.x = lo0; o2.y = lo1;
      *reinterpret_cast<float2*>(&s_lo[r][2*pr]) = o2;
    }
  } else {
    const int ow = min(TOX, 131 - tx0);
    const int cols = 2*ow + 6;
    for (int r = ty; r < rows; r += 8) {
      int sr = refl(2*ty0 + r - 6, 256);
      const float* row = src + sr * 256;
      for (int c = tx; c < cols; c += 32)
        s_in[r][c] = row[refl(2*tx0 + c - 6, 256)];
    }
    __syncthreads();
    for (int r = ty; r < rows; r += 8) {
      if (tx < ow) {
        float acc = 0.f;
#pragma unroll
        for (int tt = 0; tt < 8; tt++) acc += s_in[r][2*tx + tt] * DLO[7 - tt];
        s_lo[r][tx] = acc;
      }
    }
  }
  __syncthreads();

  // stage 2: sliding window, 4 consecutive output rows per thread.
  float* dst = out + bc * 17161;
  const int gx = tx0 + tx;
  float v[14];
#pragma unroll
  for (int tt = 0; tt < 14; tt++) v[tt] = s_lo[8*ty + tt][tx];
  if (gx < 131) {
#pragma unroll
    for (int j = 0; j < 4; j++) {
      int oy = ty0 + 4*ty + j;
      if (oy < 131) {
        float acc = 0.f;
#pragma unroll
        for (int tt = 0; tt < 8; tt++) acc += v[2*j + tt] * DLO[7 - tt];
        dst[oy * 131 + gx] = acc;
      }
    }
  }
}

// ---------------------------------------------------------------------------
// Generic LL-only analysis (level 2: 131 -> 69). Block (32,8).
// ---------------------------------------------------------------------------
template<int TOY, int TOX>
__global__ __launch_bounds__(256)
void afb_ll_kernel(const float* __restrict__ in, int inPS,
                   float* __restrict__ out,
                   int H, int W, int OH, int OW) {
  constexpr int RI = 2*TOY + 6;
  constexpr int CI = 2*TOX + 6;
  __shared__ float s_in[RI][CI];
  __shared__ float s_lo[RI][TOX];

  const int bc  = blockIdx.z;
  const int ty0 = blockIdx.y * TOY;
  const int tx0 = blockIdx.x * TOX;
  const int tx = threadIdx.x, ty = threadIdx.y;
  const float* src = in + bc * inPS;

  for (int r = ty; r < RI; r += 8) {
    int sr = refl(2*ty0 + r - 6, H);
    const float* row = src + sr * W;
    for (int c = tx; c < CI; c += 32)
      s_in[r][c] = row[refl(2*tx0 + c - 6, W)];
  }
  __syncthreads();

#pragma unroll
  for (int r = ty; r < RI; r += 8) {
    float acc = 0.f;
#pragma unroll
    for (int t = 0; t < 8; t++) acc += s_in[r][2*tx + t] * DLO[7 - t];
    s_lo[r][tx] = acc;
  }
  __syncthreads();

  // stage 2: sliding window, 2 consecutive output rows per thread.
  float* dst = out + bc * OH * OW;
  const int gx = tx0 + tx;
  float v[10];
#pragma unroll
  for (int tt = 0; tt < 10; tt++) v[tt] = s_lo[4*ty + tt][tx];
  if (gx < OW) {
#pragma unroll
    for (int j = 0; j < 2; j++) {
      int oy = ty0 + 2*ty + j;
      if (oy < OH) {
        float acc = 0.f;
#pragma unroll
        for (int tt = 0; tt < 8; tt++) acc += v[2*j + tt] * DLO[7 - tt];
        dst[oy * OW + gx] = acc;
      }
    }
  }
}

// ---------------------------------------------------------------------------
// Fused forward levels 3+4: ll2 (BC,69,69) -> l4 (BC,4,22,22). Block/plane.
// ---------------------------------------------------------------------------
__global__ __launch_bounds__(256)
void afb_fused34_kernel(const float* __restrict__ in, float* __restrict__ out) {
  __shared__ float A[69*82];
  __shared__ float Bf[82*39];
  const int bc = blockIdx.x;
  const int tx = threadIdx.x, ty = threadIdx.y;
  const float* src = in + bc * 4761;

  for (int r = ty; r < 69; r += 8)
    for (int c = tx; c < 82; c += 32)
      A[r*82 + c] = src[r*69 + refl(c - 6, 69)];
  __syncthreads();

  for (int pr = ty; pr < 82; pr += 8) {
    int sr = refl(pr - 6, 69);
    const float* arow = &A[sr*82];
    for (int ox = tx; ox < 38; ox += 32) {
      float acc = 0.f;
#pragma unroll
      for (int t = 0; t < 8; t++) acc += arow[2*ox + t] * DLO[7 - t];
      Bf[pr*39 + ox] = acc;
    }
  }
  __syncthreads();

  for (int oy = ty; oy < 38; oy += 8)
    for (int ox = tx; ox < 38; ox += 32) {
      float acc = 0.f;
#pragma unroll
      for (int t = 0; t < 8; t++) acc += Bf[(2*oy + t)*39 + ox] * DLO[7 - t];
      A[oy*50 + 6 + ox] = acc;
    }
  __syncthreads();

  {
    int idx = ty*32 + tx;
    for (int f = idx; f < 38*12; f += 256) {
      int oy = f / 12, k = f - oy*12;
      int c = (k < 6) ? k : (k + 38);
      A[oy*50 + c] = A[oy*50 + 6 + refl(c - 6, 38)];
    }
  }
  __syncthreads();

  for (int pr = ty; pr < 50; pr += 8) {
    int sr = refl(pr - 6, 38);
    const float* arow = &A[sr*50];
    if (tx < 22) {
      float lo = 0.f, hi = 0.f;
#pragma unroll
      for (int t = 0; t < 8; t++) {
        float v = arow[2*tx + t];
        lo += v * DLO[7 - t];
        hi += v * DHI[7 - t];
      }
      Bf[pr*23 + tx] = lo;
      Bf[1150 + pr*23 + tx] = hi;
    }
  }
  __syncthreads();

  float* dst = out + bc * 1936;
  if (tx < 22) {
#pragma unroll
    for (int oy = ty; oy < 22; oy += 8) {
      float ll=0.f, lh=0.f, hl=0.f, hh=0.f;
#pragma unroll
      for (int t = 0; t < 8; t++) {
        float a = Bf[(2*oy + t)*23 + tx];
        float b = Bf[1150 + (2*oy + t)*23 + tx];
        float kl = DLO[7 - t], kh = DHI[7 - t];
        ll += a*kl;  lh += a*kh;  hl += b*kl;  hh += b*kh;
      }
      int o = oy*22 + tx;
      dst[o] = ll;  dst[484 + o] = lh;  dst[968 + o] = hl;  dst[1452 + o] = hh;
    }
  }
}

// ---------------------------------------------------------------------------
// Fused inverse levels 4+3: d4 (BC,4,22,22) -> r3 (BC,69,72 padded).
// ---------------------------------------------------------------------------
__global__ __launch_bounds__(256)
void sfb_fused43_kernel(const float* __restrict__ d4, float* __restrict__ r3) {
  __shared__ float sd[4*484];
  __shared__ float slo[38*23];
  __shared__ float shi[38*23];
  __shared__ float sr4[38*39];
  __shared__ float slo2[69*39];
  const int bc = blockIdx.x;
  const int tx = threadIdx.x, ty = threadIdx.y;
  const int t = ty*32 + tx;
  const float* src = d4 + bc * 1936;

  for (int f = t; f < 1936; f += 256) sd[f] = src[f];
  __syncthreads();

  if (tx < 22) {
#pragma unroll
    for (int jy = ty; jy < 38; jy += 8) {
      int base = jy >> 1, u0 = 1 - (jy & 1);
      float lo = 0.f, hi = 0.f;
#pragma unroll
      for (int m = 0; m < 4; m++) {
        int off = (base + m)*22 + tx;
        float fl = DLO[u0 + 2*m], fh = DHI[u0 + 2*m];
        lo += fl*sd[off]       + fh*sd[484 + off];
        hi += fl*sd[968 + off] + fh*sd[1452 + off];
      }
      slo[jy*23 + tx] = lo;
      shi[jy*23 + tx] = hi;
    }
  }
  __syncthreads();

#pragma unroll
  for (int jy = ty; jy < 38; jy += 8)
    for (int jx = tx; jx < 38; jx += 32) {
      int t0 = 1 - (jx & 1), ib = jx >> 1;
      float acc = 0.f;
#pragma unroll
      for (int m = 0; m < 4; m++)
        acc += DLO[t0 + 2*m]*slo[jy*23 + ib + m] + DHI[t0 + 2*m]*shi[jy*23 + ib + m];
      sr4[jy*39 + jx] = acc;
    }
  __syncthreads();

  for (int jy2 = ty; jy2 < 69; jy2 += 8) {
    int base = jy2 >> 1, u0 = 1 - (jy2 & 1);
    float f0 = DLO[u0], f1 = DLO[u0+2], f2 = DLO[u0+4], f3 = DLO[u0+6];
    for (int i = tx; i < 38; i += 32)
      slo2[jy2*39 + i] = f0*sr4[base*39 + i]     + f1*sr4[(base+1)*39 + i]
                       + f2*sr4[(base+2)*39 + i] + f3*sr4[(base+3)*39 + i];
  }
  __syncthreads();

  float* dst = r3 + bc * 4968;           // padded plane 69*72
  for (int jy2 = ty; jy2 < 69; jy2 += 8)
    for (int jx = tx; jx < 69; jx += 32) {
      int t0 = 1 - (jx & 1), ib = jx >> 1;
      float acc = DLO[t0  ]*slo2[jy2*39 + ib    ]
                + DLO[t0+2]*slo2[jy2*39 + ib + 1]
                + DLO[t0+4]*slo2[jy2*39 + ib + 2]
                + DLO[t0+6]*slo2[jy2*39 + ib + 3];
      dst[jy2*72 + jx] = acc;
    }
}

// ---------------------------------------------------------------------------
// Fused inverse levels 2+1: r3 (BC,69,72) -> out = x + synth (BC,256,256).
// 32-row tiles: grid (8, BCv), block (32,8). Paired-row vertical stages.
// ---------------------------------------------------------------------------
__global__ __launch_bounds__(256)
void sfb_final2_kernel(const float* __restrict__ r3,
                       const float* __restrict__ x,
                       float* __restrict__ out) {
  __shared__ __align__(16) float s_r3[13][72];
  __shared__ __align__(16) float s_t [19][72];
  __shared__ __align__(16) float s_ll[19][132];
  __shared__ __align__(16) float s_lo[32][132];

  const int bc  = blockIdx.y;
  const int jy0 = blockIdx.x * 32;     // 0..224
  const int q0  = jy0 >> 2;            // r3 row origin: 0..56
  const int tx = threadIdx.x, ty = threadIdx.y;
  const int t = ty*32 + tx;

  const float k0 = DLO[0], k1 = DLO[1], k2 = DLO[2], k3 = DLO[3];
  const float k4 = DLO[4], k5 = DLO[5], k6 = DLO[6], k7 = DLO[7];

  // stage A: r3 tile [13][72] via float4 (18 groups/row)
  {
    const float4* g4 = reinterpret_cast<const float4*>(r3 + bc * 4968 + q0 * 72);
    for (int f = t; f < 13*18; f += 256) {
      int r = f / 18, c4 = f - r*18;
      reinterpret_cast<float4*>(&s_r3[r][0])[c4] = g4[r*18 + c4];
    }
  }
  __syncthreads();

  // stage B: vertical L2-synthesis, paired rows (2m, 2m+1 share sources).
  // 10 pairs x 18 col-groups (pair 9: only even row 18).
  for (int f = t; f < 10*18; f += 256) {
    int m = f / 18, c4 = f - m*18;
    const float4 a = reinterpret_cast<const float4*>(&s_r3[m  ][0])[c4];
    const float4 b = reinterpret_cast<const float4*>(&s_r3[m+1][0])[c4];
    const float4 c = reinterpret_cast<const float4*>(&s_r3[m+2][0])[c4];
    const float4 d = reinterpret_cast<const float4*>(&s_r3[m+3][0])[c4];
    float4 ve;   // even row 2m: u0=1
    ve.x = k1*a.x + k3*b.x + k5*c.x + k7*d.x;
    ve.y = k1*a.y + k3*b.y + k5*c.y + k7*d.y;
    ve.z = k1*a.z + k3*b.z + k5*c.z + k7*d.z;
    ve.w = k1*a.w + k3*b.w + k5*c.w + k7*d.w;
    reinterpret_cast<float4*>(&s_t[2*m][0])[c4] = ve;
    if (m < 9) {
      float4 vo;  // odd row 2m+1: u0=0
      vo.x = k0*a.x + k2*b.x + k4*c.x + k6*d.x;
      vo.y = k0*a.y + k2*b.y + k4*c.y + k6*d.y;
      vo.z = k0*a.z + k2*b.z + k4*c.z + k6*d.z;
      vo.w = k0*a.w + k2*b.w + k4*c.w + k6*d.w;
      reinterpret_cast<float4*>(&s_t[2*m+1][0])[c4] = vo;
    }
  }
  __syncthreads();

  // stage C: horizontal L2-synthesis, even/odd pairs share the 4-tap window
  for (int f = t; f < 19*66; f += 256) {
    int rr = f / 66, q = f - rr*66;
    float a = s_t[rr][q], b = s_t[rr][q+1], c = s_t[rr][q+2], d = s_t[rr][q+3];
    float2 v;
    v.x = k1*a + k3*b + k5*c + k7*d;   // even col 2q
    v.y = k0*a + k2*b + k4*c + k6*d;   // odd col 2q+1
    *reinterpret_cast<float2*>(&s_ll[rr][2*q]) = v;
  }
  __syncthreads();

  // stage 1: vertical L1-synthesis, paired rows (2m, 2m+1 share sources),
  // float4 columns. 16 pairs x 33 groups.
#pragma unroll
  for (int m = ty; m < 16; m += 8) {
    const float4* r0 = reinterpret_cast<const float4*>(&s_ll[m  ][0]);
    const float4* r1 = reinterpret_cast<const float4*>(&s_ll[m+1][0]);
    const float4* r2 = reinterpret_cast<const float4*>(&s_ll[m+2][0]);
    const float4* r3p = reinterpret_cast<const float4*>(&s_ll[m+3][0]);
    float4* de = reinterpret_cast<float4*>(&s_lo[2*m  ][0]);
    float4* dp = reinterpret_cast<float4*>(&s_lo[2*m+1][0]);
#pragma unroll
    for (int c4 = tx; c4 < 33; c4 += 32) {
      float4 a = r0[c4], b = r1[c4], c = r2[c4], d = r3p[c4];
      float4 ve, vo;
      ve.x = k1*a.x + k3*b.x + k5*c.x + k7*d.x;
      ve.y = k1*a.y + k3*b.y + k5*c.y + k7*d.y;
      ve.z = k1*a.z + k3*b.z + k5*c.z + k7*d.z;
      ve.w = k1*a.w + k3*b.w + k5*c.w + k7*d.w;
      vo.x = k0*a.x + k2*b.x + k4*c.x + k6*d.x;
      vo.y = k0*a.y + k2*b.y + k4*c.y + k6*d.y;
      vo.z = k0*a.z + k2*b.z + k4*c.z + k6*d.z;
      vo.w = k0*a.w + k2*b.w + k4*c.w + k6*d.w;
      de[c4] = ve;
      dp[c4] = vo;
    }
  }
  __syncthreads();

  // stage 2: horizontal L1-synthesis, float4 out with +x
  float* po = out + bc * 65536;
  const float* px = x + bc * 65536;
#pragma unroll
  for (int jyl = ty; jyl < 32; jyl += 8) {
    int jy = jy0 + jyl;
    const float2* sp = reinterpret_cast<const float2*>(&s_lo[jyl][0]);
#pragma unroll
    for (int k = 0; k < 2; k++) {
      float2 a = sp[32*k + tx], b = sp[32*k + tx + 1], c2 = sp[32*k + tx + 2];
      float4 v;
      v.x = k1*a.x + k3*a.y + k5*b.x + k7*b.y;
      v.y = k0*a.x + k2*a.y + k4*b.x + k6*b.y;
      v.z = k1*a.y + k3*b.x + k5*b.y + k7*c2.x;
      v.w = k0*a.y + k2*b.x + k4*b.y + k6*c2.x;
      int o = jy * 256 + 128*k + 4*tx;
      float4 xv = *reinterpret_cast<const float4*>(px + o);
      v.x += xv.x; v.y += xv.y; v.z += xv.z; v.w += xv.w;
      *reinterpret_cast<float4*>(po + o) = v;
    }
  }
}

// ---------------------------------------------------------------------------
// Level-4 channel mixing -> delta. Vectorized smem tiles (unchanged).
// grid (16, 4, 8). Block 256: lane = xy (32), g = t>>5 -> b pair, 8 o's.
// ---------------------------------------------------------------------------
__global__ __launch_bounds__(256)
void mul2d_delta_kernel(const float* __restrict__ in,
                        const float* __restrict__ w1,
                        const float* __restrict__ w2,
                        const float* __restrict__ w3,
                        const float* __restrict__ w4,
                        float* __restrict__ outb) {
  const int s   = blockIdx.y;
  const int xy0 = blockIdx.x * 32;
  const int o0  = blockIdx.z * 8;
  const float* W = (s == 0) ? w1 : (s == 1) ? w2 : (s == 2) ? w3 : w4;
  const int t = threadIdx.x;
  const int lane = t & 31;
  const int g    = t >> 5;
  const int xy   = xy0 + lane;
  const bool ok  = xy < 484;

  __shared__ __align__(16) float Ws[8][32][12];
  __shared__ __align__(16) float As[8][32][18];

  float acc[2][8];
#pragma unroll
  for (int j = 0; j < 2; j++)
#pragma unroll
    for (int k = 0; k < 8; k++) acc[j][k] = 0.f;

  for (int i0 = 0; i0 < 64; i0 += 8) {
    __syncthreads();
#pragma unroll
    for (int f = t; f < 8*8*32; f += 256) {
      int lx = f & 31;
      int k  = (f >> 5) & 7;
      int ii = f >> 8;
      int xg = xy0 + lx; xg = xg < 484 ? xg : 483;
      Ws[ii][lx][k] = W[((i0 + ii)*64 + o0 + k)*484 + xg];
    }
#pragma unroll
    for (int f = t; f < 8*16*32; f += 256) {
      int lx = f & 31;
      int b  = (f >> 5) & 15;
      int ii = f >> 9;
      int xg = xy0 + lx; xg = xg < 484 ? xg : 483;
      As[ii][lx][b] = in[((b*64 + (i0 + ii))*4 + s)*484 + xg];
    }
    __syncthreads();
#pragma unroll
    for (int ii = 0; ii < 8; ii++) {
      float2 av = *reinterpret_cast<const float2*>(&As[ii][lane][2*g]);
      float4 w0 = *reinterpret_cast<const float4*>(&Ws[ii][lane][0]);
      float4 w1v = *reinterpret_cast<const float4*>(&Ws[ii][lane][4]);
      acc[0][0] += av.x*w0.x;  acc[0][1] += av.x*w0.y;
      acc[0][2] += av.x*w0.z;  acc[0][3] += av.x*w0.w;
      acc[0][4] += av.x*w1v.x; acc[0][5] += av.x*w1v.y;
      acc[0][6] += av.x*w1v.z; acc[0][7] += av.x*w1v.w;
      acc[1][0] += av.y*w0.x;  acc[1][1] += av.y*w0.y;
      acc[1][2] += av.y*w0.z;  acc[1][3] += av.y*w0.w;
      acc[1][4] += av.y*w1v.x; acc[1][5] += av.y*w1v.y;
      acc[1][6] += av.y*w1v.z; acc[1][7] += av.y*w1v.w;
    }
  }

  if (ok) {
#pragma unroll
    for (int j = 0; j < 2; j++) {
      int b = 2*g + j;
#pragma unroll
      for (int k = 0; k < 8; k++) {
        int o = o0 + k;
        int idx = ((b*64 + o)*4 + s)*484 + xy;
        outb[idx] = acc[j][k] - in[idx];
      }
    }
  }
}

// ---------------------------------------------------------------------------
extern "C" void kernel_launch(void* const* d_in, const int* in_sizes, int n_in,
                              void* d_out, int out_size) {
  const float* x  = (const float*)d_in[0];
  const float* w1 = (const float*)d_in[1];
  const float* w2 = (const float*)d_in[2];
  const float* w3 = (const float*)d_in[3];
  const float* w4 = (const float*)d_in[4];
  float* out = (float*)d_out;

  float *ll1, *ll2, *l4, *d4, *r3;
  cudaGetSymbolAddress((void**)&ll1, g_ll1);
  cudaGetSymbolAddress((void**)&ll2, g_ll2);
  cudaGetSymbolAddress((void**)&l4,  g_l4);
  cudaGetSymbolAddress((void**)&d4,  g_d4);
  cudaGetSymbolAddress((void**)&r3,  g_r3);

  const dim3 blk(32, 8);

  // forward
  afb_ll1_kernel<<<dim3(5, 5, BCv), blk>>>(x, ll1);
  afb_ll_kernel<16,32><<<dim3(3, 5, BCv), blk>>>(ll1, 131*131, ll2, 131, 131, 69, 69);
  afb_fused34_kernel<<<BCv, blk>>>(ll2, l4);

  // level-4 mixing -> delta
  mul2d_delta_kernel<<<dim3(16, 4, 8), 256>>>(l4, w1, w2, w3, w4, d4);

  // inverse
  sfb_fused43_kernel<<<BCv, blk>>>(d4, r3);
  sfb_final2_kernel<<<dim3(8, BCv), blk>>>(r3, x, out);
}